// round 3
// baseline (speedup 1.0000x reference)
#include <cuda_runtime.h>
#include <math.h>

// Problem constants
constexpr int cB = 2, cT = 2048, cS = 2048, cD = 1024, cH = 16, cDK = 64;
constexpr int cHD = cH * cDK;      // 1024
constexpr int cMT = cB * cT;       // 4096 rows for the projection GEMMs

using u64 = unsigned long long;

// ---- packed f32x2 helpers (sm_100+; ptxas never emits these from C++) ----
__device__ __forceinline__ u64 ffma2(u64 a, u64 b, u64 c) {
    u64 d; asm("fma.rn.f32x2 %0, %1, %2, %3;" : "=l"(d) : "l"(a), "l"(b), "l"(c));
    return d;
}
__device__ __forceinline__ u64 mul2(u64 a, u64 b) {
    u64 d; asm("mul.rn.f32x2 %0, %1, %2;" : "=l"(d) : "l"(a), "l"(b));
    return d;
}
__device__ __forceinline__ u64 add2(u64 a, u64 b) {
    u64 d; asm("add.rn.f32x2 %0, %1, %2;" : "=l"(d) : "l"(a), "l"(b));
    return d;
}
__device__ __forceinline__ u64 pack2(float x, float y) {
    u64 r; asm("mov.b64 %0, {%1, %2};" : "=l"(r) : "f"(x), "f"(y));
    return r;
}
__device__ __forceinline__ float2 unpack2(u64 v) {
    float2 f; asm("mov.b64 {%0, %1}, %2;" : "=f"(f.x), "=f"(f.y) : "l"(v));
    return f;
}

// Scratch (alloc-free rule: __device__ globals)
__device__ float g_q[(size_t)cMT * cHD];
__device__ float g_k[(size_t)cB * cS * cHD];
__device__ float g_v[(size_t)cB * cS * cHD];
__device__ float g_attn[(size_t)cMT * cHD];

// ---------------------------------------------------------------------------
// GEMM: C[M,N] = (X[M,K] @ W[K,N] + bias[N]) * scale
// Tile 64x128x16, 256 threads, 4 rows x 8 cols (4 f32x2 pairs) per thread.
// A held in smem duplicated as (x,x) pairs -> broadcast operand is one LDS.64.
// ---------------------------------------------------------------------------
constexpr int GBM = 64, GBN = 128, GBK = 16;

__global__ __launch_bounds__(256) void gemm_bias(
    const float* __restrict__ X, const float* __restrict__ W,
    const float* __restrict__ bias, float* __restrict__ C,
    int M, int N, int K, float scale)
{
    __shared__ u64   XsD[GBM * GBK];   // duplicated pairs, 8KB
    __shared__ float Ws[GBK * GBN];    // [k][n], 8KB

    const int tid = threadIdx.x;
    const int tx = tid & 15;           // col group (8 cols)
    const int ty = tid >> 4;           // row group (4 rows)
    const int m0 = blockIdx.y * GBM;
    const int n0 = blockIdx.x * GBN;
    const int col0 = tx << 3;
    const int row0 = ty << 2;

    u64 acc[4][4] = {};

    for (int k0 = 0; k0 < K; k0 += GBK) {
        // X tile 64x16 -> duplicated pairs
        {
            const int r = tid >> 2, c = (tid & 3) << 2;
            const float4 v = *reinterpret_cast<const float4*>(
                X + (size_t)(m0 + r) * K + k0 + c);
            ulonglong2 d0, d1;
            d0.x = pack2(v.x, v.x); d0.y = pack2(v.y, v.y);
            d1.x = pack2(v.z, v.z); d1.y = pack2(v.w, v.w);
            *reinterpret_cast<ulonglong2*>(&XsD[r * GBK + c])     = d0;
            *reinterpret_cast<ulonglong2*>(&XsD[r * GBK + c + 2]) = d1;
        }
        // W tile 16x128
        #pragma unroll
        for (int i = 0; i < 2; i++) {
            const int idx = tid + i * 256;
            const int r = idx >> 5, c = (idx & 31) << 2;
            *reinterpret_cast<float4*>(&Ws[r * GBN + c]) =
                *reinterpret_cast<const float4*>(W + (size_t)(k0 + r) * N + n0 + c);
        }
        __syncthreads();

        #pragma unroll
        for (int kk = 0; kk < GBK; kk++) {
            const u64 a0 = XsD[(row0 + 0) * GBK + kk];
            const u64 a1 = XsD[(row0 + 1) * GBK + kk];
            const u64 a2 = XsD[(row0 + 2) * GBK + kk];
            const u64 a3 = XsD[(row0 + 3) * GBK + kk];
            const ulonglong2 b01 = *reinterpret_cast<const ulonglong2*>(&Ws[kk * GBN + col0]);
            const ulonglong2 b23 = *reinterpret_cast<const ulonglong2*>(&Ws[kk * GBN + col0 + 4]);
            acc[0][0] = ffma2(a0, b01.x, acc[0][0]); acc[0][1] = ffma2(a0, b01.y, acc[0][1]);
            acc[0][2] = ffma2(a0, b23.x, acc[0][2]); acc[0][3] = ffma2(a0, b23.y, acc[0][3]);
            acc[1][0] = ffma2(a1, b01.x, acc[1][0]); acc[1][1] = ffma2(a1, b01.y, acc[1][1]);
            acc[1][2] = ffma2(a1, b23.x, acc[1][2]); acc[1][3] = ffma2(a1, b23.y, acc[1][3]);
            acc[2][0] = ffma2(a2, b01.x, acc[2][0]); acc[2][1] = ffma2(a2, b01.y, acc[2][1]);
            acc[2][2] = ffma2(a2, b23.x, acc[2][2]); acc[2][3] = ffma2(a2, b23.y, acc[2][3]);
            acc[3][0] = ffma2(a3, b01.x, acc[3][0]); acc[3][1] = ffma2(a3, b01.y, acc[3][1]);
            acc[3][2] = ffma2(a3, b23.x, acc[3][2]); acc[3][3] = ffma2(a3, b23.y, acc[3][3]);
        }
        __syncthreads();
    }

    // Epilogue: (acc + bias) * scale, bias pairs are naturally adjacent cols
    const u64* bp = reinterpret_cast<const u64*>(bias + n0 + col0);
    const u64 ss = pack2(scale, scale);
    #pragma unroll
    for (int i = 0; i < 4; i++) {
        float* cp = C + (size_t)(m0 + row0 + i) * N + n0 + col0;
        ulonglong2 s0, s1;
        s0.x = mul2(add2(acc[i][0], bp[0]), ss);
        s0.y = mul2(add2(acc[i][1], bp[1]), ss);
        s1.x = mul2(add2(acc[i][2], bp[2]), ss);
        s1.y = mul2(add2(acc[i][3], bp[3]), ss);
        *reinterpret_cast<ulonglong2*>(cp)     = s0;
        *reinterpret_cast<ulonglong2*>(cp + 4) = s1;
    }
}

// ---------------------------------------------------------------------------
// Flash attention: per block = (t-tile of 64, head, batch). 256 threads,
// 8 warps, thread tile 4x4 (2 f32x2 pairs). Online softmax over s-tiles of 64.
// K tile transposed + 16B-XOR-swizzled; broadcast A operand packed on the fly
// (mov.b64 on the idle ALU pipe).
// ---------------------------------------------------------------------------
constexpr int ATTN_SMEM_BYTES = 4 * 64 * 64 * 4;   // qs + kts + vs + ps = 64KB

__global__ __launch_bounds__(256) void attn_kernel(
    const float* __restrict__ Qg, const float* __restrict__ Kg,
    const float* __restrict__ Vg, float* __restrict__ Og)
{
    extern __shared__ float sm[];
    float* qs  = sm;                 // [t][dk]
    float* kts = sm + 4096;          // swizzled [dk][s]
    float* vs  = sm + 8192;          // [s][dk]
    float* ps  = sm + 12288;         // [t][s] (warp-private rows)

    const int tid = threadIdx.x;
    const int tx = tid & 15;
    const int ty = tid >> 4;
    const int t0 = blockIdx.x * 64;
    const int hi = blockIdx.y;
    const int bi = blockIdx.z;

    // Load Q tile (64 x 64)
    #pragma unroll
    for (int it = 0; it < 4; it++) {
        const int idx = tid + it * 256;
        const int r = idx >> 4;
        const int c = (idx & 15) << 2;
        *reinterpret_cast<float4*>(&qs[r * 64 + c]) =
            *reinterpret_cast<const float4*>(
                Qg + ((size_t)(bi * cT + t0 + r) * cH + hi) * cDK + c);
    }

    u64 acc[4][2] = {};
    float m[4], l[4];
    #pragma unroll
    for (int i = 0; i < 4; i++) { m[i] = -INFINITY; l[i] = 0.0f; }

    for (int s0 = 0; s0 < cS; s0 += 64) {
        __syncthreads();
        // K tile -> transposed + swizzled; V tile -> natural layout
        #pragma unroll
        for (int it = 0; it < 4; it++) {
            const int idx = tid + it * 256;
            const int r = idx >> 4;              // s local
            const int c = (idx & 15) << 2;       // dk base
            const float4 kv = *reinterpret_cast<const float4*>(
                Kg + ((size_t)(bi * cS + s0 + r) * cH + hi) * cDK + c);
            const int col16 = (((r >> 2) ^ (c >> 2)) & 15) << 2;
            const int base = col16 + (r & 3);
            kts[(c + 0) * 64 + base] = kv.x;
            kts[(c + 1) * 64 + base] = kv.y;
            kts[(c + 2) * 64 + base] = kv.z;
            kts[(c + 3) * 64 + base] = kv.w;
            *reinterpret_cast<float4*>(&vs[r * 64 + c]) =
                *reinterpret_cast<const float4*>(
                    Vg + ((size_t)(bi * cS + s0 + r) * cH + hi) * cDK + c);
        }
        __syncthreads();

        // S = Q @ K^T  (64x64x64), packed pairs over the 4 s-columns
        u64 sacc[4][2] = {};
        #pragma unroll 8
        for (int kk = 0; kk < 64; kk++) {
            const float f0 = qs[(ty * 4 + 0) * 64 + kk];
            const float f1 = qs[(ty * 4 + 1) * 64 + kk];
            const float f2 = qs[(ty * 4 + 2) * 64 + kk];
            const float f3 = qs[(ty * 4 + 3) * 64 + kk];
            const u64 a0 = pack2(f0, f0), a1 = pack2(f1, f1);
            const u64 a2 = pack2(f2, f2), a3 = pack2(f3, f3);
            const ulonglong2 bb = *reinterpret_cast<const ulonglong2*>(
                &kts[kk * 64 + (((tx ^ (kk >> 2)) & 15) << 2)]);
            sacc[0][0] = ffma2(a0, bb.x, sacc[0][0]); sacc[0][1] = ffma2(a0, bb.y, sacc[0][1]);
            sacc[1][0] = ffma2(a1, bb.x, sacc[1][0]); sacc[1][1] = ffma2(a1, bb.y, sacc[1][1]);
            sacc[2][0] = ffma2(a2, bb.x, sacc[2][0]); sacc[2][1] = ffma2(a2, bb.y, sacc[2][1]);
            sacc[3][0] = ffma2(a3, bb.x, sacc[3][0]); sacc[3][1] = ffma2(a3, bb.y, sacc[3][1]);
        }

        // Online softmax per row (row owned by a 16-lane half-warp)
        #pragma unroll
        for (int i = 0; i < 4; i++) {
            const float2 u0 = unpack2(sacc[i][0]);
            const float2 u1 = unpack2(sacc[i][1]);
            float mt = fmaxf(fmaxf(u0.x, u0.y), fmaxf(u1.x, u1.y));
            #pragma unroll
            for (int off = 8; off >= 1; off >>= 1)
                mt = fmaxf(mt, __shfl_xor_sync(0xffffffffu, mt, off));
            const float mnew = fmaxf(m[i], mt);
            const float corr = __expf(m[i] - mnew);
            const float p0 = __expf(u0.x - mnew);
            const float p1 = __expf(u0.y - mnew);
            const float p2 = __expf(u1.x - mnew);
            const float p3 = __expf(u1.y - mnew);
            float ls = (p0 + p1) + (p2 + p3);
            #pragma unroll
            for (int off = 8; off >= 1; off >>= 1)
                ls += __shfl_xor_sync(0xffffffffu, ls, off);
            l[i] = l[i] * corr + ls;
            m[i] = mnew;
            const u64 cc = pack2(corr, corr);
            acc[i][0] = mul2(acc[i][0], cc);
            acc[i][1] = mul2(acc[i][1], cc);
            *reinterpret_cast<float4*>(&ps[(ty * 4 + i) * 64 + (tx << 2)]) =
                make_float4(p0, p1, p2, p3);
        }
        __syncwarp();

        // O += P @ V  (64x64x64)
        #pragma unroll 8
        for (int kk = 0; kk < 64; kk++) {
            const float f0 = ps[(ty * 4 + 0) * 64 + kk];
            const float f1 = ps[(ty * 4 + 1) * 64 + kk];
            const float f2 = ps[(ty * 4 + 2) * 64 + kk];
            const float f3 = ps[(ty * 4 + 3) * 64 + kk];
            const u64 a0 = pack2(f0, f0), a1 = pack2(f1, f1);
            const u64 a2 = pack2(f2, f2), a3 = pack2(f3, f3);
            const ulonglong2 bb = *reinterpret_cast<const ulonglong2*>(
                &vs[kk * 64 + (tx << 2)]);
            acc[0][0] = ffma2(a0, bb.x, acc[0][0]); acc[0][1] = ffma2(a0, bb.y, acc[0][1]);
            acc[1][0] = ffma2(a1, bb.x, acc[1][0]); acc[1][1] = ffma2(a1, bb.y, acc[1][1]);
            acc[2][0] = ffma2(a2, bb.x, acc[2][0]); acc[2][1] = ffma2(a2, bb.y, acc[2][1]);
            acc[3][0] = ffma2(a3, bb.x, acc[3][0]); acc[3][1] = ffma2(a3, bb.y, acc[3][1]);
        }
    }

    // Normalize and store attn output [B,T,H,DK]
    #pragma unroll
    for (int i = 0; i < 4; i++) {
        const float inv = 1.0f / l[i];
        const u64 ii = pack2(inv, inv);
        ulonglong2 o;
        o.x = mul2(acc[i][0], ii);
        o.y = mul2(acc[i][1], ii);
        *reinterpret_cast<ulonglong2*>(
            Og + ((size_t)(bi * cT + t0 + ty * 4 + i) * cH + hi) * cDK + (tx << 2)) = o;
    }
}

// ---------------------------------------------------------------------------
extern "C" void kernel_launch(void* const* d_in, const int* in_sizes, int n_in,
                              void* d_out, int out_size)
{
    const float* query = (const float*)d_in[0];
    const float* value = (const float*)d_in[1];
    const float* key   = (const float*)d_in[2];
    const float* Wq    = (const float*)d_in[3];
    const float* bq    = (const float*)d_in[4];
    const float* Wk    = (const float*)d_in[5];
    const float* bk    = (const float*)d_in[6];
    const float* Wv    = (const float*)d_in[7];
    const float* bv    = (const float*)d_in[8];
    const float* Wo    = (const float*)d_in[9];
    const float* bo    = (const float*)d_in[10];
    float* out = (float*)d_out;

    float *pq, *pk, *pv, *pa;
    cudaGetSymbolAddress((void**)&pq, g_q);
    cudaGetSymbolAddress((void**)&pk, g_k);
    cudaGetSymbolAddress((void**)&pv, g_v);
    cudaGetSymbolAddress((void**)&pa, g_attn);

    cudaFuncSetAttribute(attn_kernel,
                         cudaFuncAttributeMaxDynamicSharedMemorySize,
                         ATTN_SMEM_BYTES);

    const dim3 gg(cHD / GBN, cMT / GBM);   // (8, 64)
    const float qscale = 0.125f;           // 1/sqrt(DK), exact in fp32

    gemm_bias<<<gg, 256>>>(query, Wq, bq, pq, cMT, cHD, cD, qscale);
    gemm_bias<<<gg, 256>>>(key,   Wk, bk, pk, cMT, cHD, cD, 1.0f);
    gemm_bias<<<gg, 256>>>(value, Wv, bv, pv, cMT, cHD, cD, 1.0f);

    attn_kernel<<<dim3(cT / 64, cH, cB), 256, ATTN_SMEM_BYTES>>>(pq, pk, pv, pa);

    gemm_bias<<<gg, 256>>>(pa, Wo, bo, out, cMT, cD, cHD, 1.0f);
}

// round 5
// speedup vs baseline: 1.9225x; 1.9225x over previous
#include <cuda_runtime.h>
#include <cuda_bf16.h>
#include <math.h>
#include <cstdint>

// Problem constants
constexpr int cB = 2, cT = 2048, cS = 2048, cD = 1024, cH = 16, cDK = 64;
constexpr int cHD = cH * cDK;      // 1024
constexpr int cMT = cB * cT;       // 4096
constexpr size_t XSZ = (size_t)cMT * cD;    // per input slot
constexpr size_t WSZ = (size_t)cD * cHD;    // per weight

using u64 = unsigned long long;

// ---- packed f32x2 helpers (attn kernel) ----
__device__ __forceinline__ u64 ffma2(u64 a, u64 b, u64 c) {
    u64 d; asm("fma.rn.f32x2 %0, %1, %2, %3;" : "=l"(d) : "l"(a), "l"(b), "l"(c));
    return d;
}
__device__ __forceinline__ u64 mul2(u64 a, u64 b) {
    u64 d; asm("mul.rn.f32x2 %0, %1, %2;" : "=l"(d) : "l"(a), "l"(b));
    return d;
}
__device__ __forceinline__ u64 pack2(float x, float y) {
    u64 r; asm("mov.b64 %0, {%1, %2};" : "=l"(r) : "f"(x), "f"(y));
    return r;
}
__device__ __forceinline__ float2 unpack2(u64 v) {
    float2 f; asm("mov.b64 {%0, %1}, %2;" : "=f"(f.x), "=f"(f.y) : "l"(v));
    return f;
}

// ---- warp MMA helpers (compute_103-safe: sm_80-era PTX) ----
__device__ __forceinline__ uint32_t smem_u32(const void* p) {
    uint32_t a;
    asm("{ .reg .u64 t; cvta.to.shared.u64 t, %1; cvt.u32.u64 %0, t; }"
        : "=r"(a) : "l"(p));
    return a;
}
__device__ __forceinline__ void ldsm4(uint32_t& r0, uint32_t& r1,
                                      uint32_t& r2, uint32_t& r3, uint32_t a) {
    asm volatile("ldmatrix.sync.aligned.m8n8.x4.shared.b16 {%0,%1,%2,%3}, [%4];"
                 : "=r"(r0), "=r"(r1), "=r"(r2), "=r"(r3) : "r"(a));
}
__device__ __forceinline__ void mma_bf16(float c[4],
    uint32_t a0, uint32_t a1, uint32_t a2, uint32_t a3,
    uint32_t b0, uint32_t b1) {
    asm volatile("mma.sync.aligned.m16n8k16.row.col.f32.bf16.bf16.f32 "
                 "{%0,%1,%2,%3}, {%4,%5,%6,%7}, {%8,%9}, {%0,%1,%2,%3};"
                 : "+f"(c[0]), "+f"(c[1]), "+f"(c[2]), "+f"(c[3])
                 : "r"(a0), "r"(a1), "r"(a2), "r"(a3), "r"(b0), "r"(b1));
}
__device__ __forceinline__ void cp16(uint32_t dst, const void* src) {
    asm volatile("cp.async.cg.shared.global [%0], [%1], 16;"
                 :: "r"(dst), "l"(src));
}
#define CP_COMMIT() asm volatile("cp.async.commit_group;")
#define CP_WAIT(n)  asm volatile("cp.async.wait_group %0;" :: "n"(n))

// ---- Scratch (__device__ globals; alloc-free rule) ----
__device__ float g_q[(size_t)cMT * cHD];
__device__ float g_k[(size_t)cB * cS * cHD];
__device__ float g_v[(size_t)cB * cS * cHD];
__device__ float g_attn[(size_t)cMT * cHD];
__device__ __nv_bfloat16 g_xh[3 * XSZ];
__device__ __nv_bfloat16 g_xl[3 * XSZ];
__device__ __nv_bfloat16 g_wth[4 * WSZ];   // W^T: [N][K] K-major
__device__ __nv_bfloat16 g_wtl[4 * WSZ];

// ---------------------------------------------------------------------------
// Elementwise fp32 -> bf16 hi/lo split
// ---------------------------------------------------------------------------
__global__ __launch_bounds__(256) void xconv(
    const float* __restrict__ X, __nv_bfloat16* __restrict__ xh,
    __nv_bfloat16* __restrict__ xl)
{
    const size_t i4 = ((size_t)blockIdx.x * 256 + threadIdx.x) * 4;
    const float4 v = *reinterpret_cast<const float4*>(X + i4);
    __nv_bfloat16 h0 = __float2bfloat16(v.x), h1 = __float2bfloat16(v.y);
    __nv_bfloat16 h2 = __float2bfloat16(v.z), h3 = __float2bfloat16(v.w);
    __nv_bfloat16 l0 = __float2bfloat16(v.x - __bfloat162float(h0));
    __nv_bfloat16 l1 = __float2bfloat16(v.y - __bfloat162float(h1));
    __nv_bfloat16 l2 = __float2bfloat16(v.z - __bfloat162float(h2));
    __nv_bfloat16 l3 = __float2bfloat16(v.w - __bfloat162float(h3));
    __nv_bfloat162* ph = reinterpret_cast<__nv_bfloat162*>(xh + i4);
    __nv_bfloat162* pl = reinterpret_cast<__nv_bfloat162*>(xl + i4);
    ph[0] = __nv_bfloat162(h0, h1); ph[1] = __nv_bfloat162(h2, h3);
    pl[0] = __nv_bfloat162(l0, l1); pl[1] = __nv_bfloat162(l2, l3);
}

// ---------------------------------------------------------------------------
// W[K,N] fp32 -> W^T[N,K] bf16 hi/lo (tiled transpose)
// ---------------------------------------------------------------------------
__global__ __launch_bounds__(256) void wconv(
    const float* __restrict__ W0, const float* __restrict__ W1,
    const float* __restrict__ W2, const float* __restrict__ W3,
    __nv_bfloat16* __restrict__ wh, __nv_bfloat16* __restrict__ wl)
{
    __shared__ float t[32][33];
    const int z = blockIdx.z;
    const float* W = (z == 0) ? W0 : (z == 1) ? W1 : (z == 2) ? W2 : W3;
    const int n0 = blockIdx.x * 32, k0 = blockIdx.y * 32;
    const int tx = threadIdx.x, ty = threadIdx.y;
    #pragma unroll
    for (int i = 0; i < 4; i++)
        t[ty + 8 * i][tx] = W[(size_t)(k0 + ty + 8 * i) * cHD + n0 + tx];
    __syncthreads();
    const size_t zb = (size_t)z * WSZ;
    #pragma unroll
    for (int i = 0; i < 4; i++) {
        const float v = t[tx][ty + 8 * i];
        const __nv_bfloat16 h = __float2bfloat16(v);
        const __nv_bfloat16 l = __float2bfloat16(v - __bfloat162float(h));
        const size_t o = zb + (size_t)(n0 + ty + 8 * i) * cD + k0 + tx;
        wh[o] = h; wl[o] = l;
    }
}

// ---------------------------------------------------------------------------
// mma.sync split-bf16 GEMM: C[M,1024] = (X @ W + bias) * scale
// X hi/lo bf16 [M,K] K-major; W^T hi/lo bf16 [N,K] K-major.
// CTA tile 128x128, K-chunk 32, 8 warps (warp tile 64x32), 2-stage cp.async.
// D = Xh*Wh + Xl*Wh + Xh*Wl (fp32 accum in HMMA).
// ---------------------------------------------------------------------------
constexpr int ROWB = 80;                 // bytes per smem row (40 halves): 5x16B
constexpr int TILE_B = 128 * ROWB;       // 10240
constexpr int STAGE_B = 4 * TILE_B;      // Ah, Al, Bh, Bl
constexpr int GEMM_SMEM = 2 * STAGE_B;   // 81920

__global__ __launch_bounds__(256, 2) void gemm_mma(
    const __nv_bfloat16* __restrict__ Xh, const __nv_bfloat16* __restrict__ Xl,
    const __nv_bfloat16* __restrict__ Wh, const __nv_bfloat16* __restrict__ Wl,
    const float* b0, const float* b1, const float* b2,
    float* o0, float* o1, float* o2, float scale0)
{
    extern __shared__ char dynsm[];
    const uint32_t sb = smem_u32(dynsm);
    const int tid = threadIdx.x;
    const int wid = tid >> 5;
    const int lane = tid & 31;
    const int z = blockIdx.z;
    const int m0 = blockIdx.y * 128;
    const int n0 = blockIdx.x * 128;
    const int wm = wid & 1;       // 2 M-slices of 64
    const int wn = wid >> 1;      // 4 N-slices of 32

    const __nv_bfloat16* Ah = Xh + (size_t)z * XSZ;
    const __nv_bfloat16* Al = Xl + (size_t)z * XSZ;
    const __nv_bfloat16* Bh = Wh + (size_t)z * WSZ;
    const __nv_bfloat16* Bl = Wl + (size_t)z * WSZ;
    const float* bias = (z == 0) ? b0 : (z == 1) ? b1 : b2;
    float* C = (z == 0) ? o0 : (z == 1) ? o1 : o2;
    const float scale = (z == 0) ? scale0 : 1.0f;

    float acc[4][4][4] = {};     // [mi][ni][c0..c3]

    // per-thread load slots: idx = tid + i*256; row = idx>>2, col16 = idx&3
    const int lr0 = tid >> 2, lc = (tid & 3);
    const uint32_t so0 = (uint32_t)(lr0 * ROWB + lc * 16);
    const uint32_t so1 = (uint32_t)((lr0 + 64) * ROWB + lc * 16);

    auto load_stage = [&](int chunk, int stage) {
        const uint32_t s0 = sb + stage * STAGE_B;
        const int k0 = chunk * 32;
        const size_t ga0 = (size_t)(m0 + lr0) * cD + k0 + lc * 8;
        const size_t ga1 = (size_t)(m0 + lr0 + 64) * cD + k0 + lc * 8;
        const size_t gb0 = (size_t)(n0 + lr0) * cD + k0 + lc * 8;
        const size_t gb1 = (size_t)(n0 + lr0 + 64) * cD + k0 + lc * 8;
        cp16(s0 + so0,              Ah + ga0);
        cp16(s0 + so1,              Ah + ga1);
        cp16(s0 + TILE_B + so0,     Al + ga0);
        cp16(s0 + TILE_B + so1,     Al + ga1);
        cp16(s0 + 2 * TILE_B + so0, Bh + gb0);
        cp16(s0 + 2 * TILE_B + so1, Bh + gb1);
        cp16(s0 + 3 * TILE_B + so0, Bl + gb0);
        cp16(s0 + 3 * TILE_B + so1, Bl + gb1);
        CP_COMMIT();
    };

    load_stage(0, 0);
    const int NCH = cD / 32;
    for (int ch = 0; ch < NCH; ch++) {
        if (ch + 1 < NCH) { load_stage(ch + 1, (ch + 1) & 1); CP_WAIT(1); }
        else              { CP_WAIT(0); }
        __syncthreads();
        const uint32_t s0 = sb + (ch & 1) * STAGE_B;

        #pragma unroll
        for (int sp = 0; sp < 3; sp++) {
            const uint32_t ab = s0 + ((sp == 1) ? TILE_B : 0);
            const uint32_t bb = s0 + ((sp == 2) ? 3 * TILE_B : 2 * TILE_B);
            #pragma unroll
            for (int ks = 0; ks < 2; ks++) {
                uint32_t af[4][4];
                #pragma unroll
                for (int mi = 0; mi < 4; mi++) {
                    const int row = wm * 64 + mi * 16 + (lane & 15);
                    const int col = ks * 16 + ((lane >> 4) << 3);
                    ldsm4(af[mi][0], af[mi][1], af[mi][2], af[mi][3],
                          ab + (uint32_t)(row * ROWB + col * 2));
                }
                uint32_t bf[4][2];
                #pragma unroll
                for (int np = 0; np < 2; np++) {
                    const int nrow = wn * 32 + np * 16 + (lane & 7) + ((lane >> 4) << 3);
                    const int col = ks * 16 + (((lane >> 3) & 1) << 3);
                    uint32_t r0, r1, r2, r3;
                    ldsm4(r0, r1, r2, r3, bb + (uint32_t)(nrow * ROWB + col * 2));
                    bf[2 * np][0] = r0;     bf[2 * np][1] = r1;
                    bf[2 * np + 1][0] = r2; bf[2 * np + 1][1] = r3;
                }
                #pragma unroll
                for (int mi = 0; mi < 4; mi++)
                    #pragma unroll
                    for (int ni = 0; ni < 4; ni++)
                        mma_bf16(acc[mi][ni], af[mi][0], af[mi][1],
                                 af[mi][2], af[mi][3], bf[ni][0], bf[ni][1]);
            }
        }
        __syncthreads();
    }

    // Epilogue: (acc + bias) * scale
    #pragma unroll
    for (int mi = 0; mi < 4; mi++) {
        #pragma unroll
        for (int h = 0; h < 2; h++) {
            const int row = m0 + wm * 64 + mi * 16 + h * 8 + (lane >> 2);
            #pragma unroll
            for (int ni = 0; ni < 4; ni++) {
                const int col = n0 + wn * 32 + ni * 8 + (lane & 3) * 2;
                const float2 bb = *reinterpret_cast<const float2*>(bias + col);
                float2 o;
                o.x = (acc[mi][ni][h * 2 + 0] + bb.x) * scale;
                o.y = (acc[mi][ni][h * 2 + 1] + bb.y) * scale;
                *reinterpret_cast<float2*>(C + (size_t)row * 1024 + col) = o;
            }
        }
    }
}

// ---------------------------------------------------------------------------
// Flash attention (round-3 f32x2 version, measured 890us)
// ---------------------------------------------------------------------------
constexpr int ATTN_SMEM_BYTES = 4 * 64 * 64 * 4;   // 64KB

__global__ __launch_bounds__(256) void attn_kernel(
    const float* __restrict__ Qg, const float* __restrict__ Kg,
    const float* __restrict__ Vg, float* __restrict__ Og)
{
    extern __shared__ char dynsm[];
    float* sm = reinterpret_cast<float*>(dynsm);
    float* qs  = sm;
    float* kts = sm + 4096;
    float* vs  = sm + 8192;
    float* ps  = sm + 12288;

    const int tid = threadIdx.x;
    const int tx = tid & 15;
    const int ty = tid >> 4;
    const int t0 = blockIdx.x * 64;
    const int hi = blockIdx.y;
    const int bi = blockIdx.z;

    #pragma unroll
    for (int it = 0; it < 4; it++) {
        const int idx = tid + it * 256;
        const int r = idx >> 4;
        const int c = (idx & 15) << 2;
        *reinterpret_cast<float4*>(&qs[r * 64 + c]) =
            *reinterpret_cast<const float4*>(
                Qg + ((size_t)(bi * cT + t0 + r) * cH + hi) * cDK + c);
    }

    u64 acc[4][2] = {};
    float m[4], l[4];
    #pragma unroll
    for (int i = 0; i < 4; i++) { m[i] = -INFINITY; l[i] = 0.0f; }

    for (int s0 = 0; s0 < cS; s0 += 64) {
        __syncthreads();
        #pragma unroll
        for (int it = 0; it < 4; it++) {
            const int idx = tid + it * 256;
            const int r = idx >> 4;
            const int c = (idx & 15) << 2;
            const float4 kv = *reinterpret_cast<const float4*>(
                Kg + ((size_t)(bi * cS + s0 + r) * cH + hi) * cDK + c);
            const int col16 = (((r >> 2) ^ (c >> 2)) & 15) << 2;
            const int base = col16 + (r & 3);
            kts[(c + 0) * 64 + base] = kv.x;
            kts[(c + 1) * 64 + base] = kv.y;
            kts[(c + 2) * 64 + base] = kv.z;
            kts[(c + 3) * 64 + base] = kv.w;
            *reinterpret_cast<float4*>(&vs[r * 64 + c]) =
                *reinterpret_cast<const float4*>(
                    Vg + ((size_t)(bi * cS + s0 + r) * cH + hi) * cDK + c);
        }
        __syncthreads();

        u64 sacc[4][2] = {};
        #pragma unroll 8
        for (int kk = 0; kk < 64; kk++) {
            const float f0 = qs[(ty * 4 + 0) * 64 + kk];
            const float f1 = qs[(ty * 4 + 1) * 64 + kk];
            const float f2 = qs[(ty * 4 + 2) * 64 + kk];
            const float f3 = qs[(ty * 4 + 3) * 64 + kk];
            const u64 a0 = pack2(f0, f0), a1 = pack2(f1, f1);
            const u64 a2 = pack2(f2, f2), a3 = pack2(f3, f3);
            const ulonglong2 bb = *reinterpret_cast<const ulonglong2*>(
                &kts[kk * 64 + (((tx ^ (kk >> 2)) & 15) << 2)]);
            sacc[0][0] = ffma2(a0, bb.x, sacc[0][0]); sacc[0][1] = ffma2(a0, bb.y, sacc[0][1]);
            sacc[1][0] = ffma2(a1, bb.x, sacc[1][0]); sacc[1][1] = ffma2(a1, bb.y, sacc[1][1]);
            sacc[2][0] = ffma2(a2, bb.x, sacc[2][0]); sacc[2][1] = ffma2(a2, bb.y, sacc[2][1]);
            sacc[3][0] = ffma2(a3, bb.x, sacc[3][0]); sacc[3][1] = ffma2(a3, bb.y, sacc[3][1]);
        }

        #pragma unroll
        for (int i = 0; i < 4; i++) {
            const float2 u0 = unpack2(sacc[i][0]);
            const float2 u1 = unpack2(sacc[i][1]);
            float mt = fmaxf(fmaxf(u0.x, u0.y), fmaxf(u1.x, u1.y));
            #pragma unroll
            for (int off = 8; off >= 1; off >>= 1)
                mt = fmaxf(mt, __shfl_xor_sync(0xffffffffu, mt, off));
            const float mnew = fmaxf(m[i], mt);
            const float corr = __expf(m[i] - mnew);
            const float p0 = __expf(u0.x - mnew);
            const float p1 = __expf(u0.y - mnew);
            const float p2 = __expf(u1.x - mnew);
            const float p3 = __expf(u1.y - mnew);
            float ls = (p0 + p1) + (p2 + p3);
            #pragma unroll
            for (int off = 8; off >= 1; off >>= 1)
                ls += __shfl_xor_sync(0xffffffffu, ls, off);
            l[i] = l[i] * corr + ls;
            m[i] = mnew;
            const u64 cc = pack2(corr, corr);
            acc[i][0] = mul2(acc[i][0], cc);
            acc[i][1] = mul2(acc[i][1], cc);
            *reinterpret_cast<float4*>(&ps[(ty * 4 + i) * 64 + (tx << 2)]) =
                make_float4(p0, p1, p2, p3);
        }
        __syncwarp();

        #pragma unroll 8
        for (int kk = 0; kk < 64; kk++) {
            const float f0 = ps[(ty * 4 + 0) * 64 + kk];
            const float f1 = ps[(ty * 4 + 1) * 64 + kk];
            const float f2 = ps[(ty * 4 + 2) * 64 + kk];
            const float f3 = ps[(ty * 4 + 3) * 64 + kk];
            const u64 a0 = pack2(f0, f0), a1 = pack2(f1, f1);
            const u64 a2 = pack2(f2, f2), a3 = pack2(f3, f3);
            const ulonglong2 bb = *reinterpret_cast<const ulonglong2*>(
                &vs[kk * 64 + (tx << 2)]);
            acc[0][0] = ffma2(a0, bb.x, acc[0][0]); acc[0][1] = ffma2(a0, bb.y, acc[0][1]);
            acc[1][0] = ffma2(a1, bb.x, acc[1][0]); acc[1][1] = ffma2(a1, bb.y, acc[1][1]);
            acc[2][0] = ffma2(a2, bb.x, acc[2][0]); acc[2][1] = ffma2(a2, bb.y, acc[2][1]);
            acc[3][0] = ffma2(a3, bb.x, acc[3][0]); acc[3][1] = ffma2(a3, bb.y, acc[3][1]);
        }
    }

    #pragma unroll
    for (int i = 0; i < 4; i++) {
        const float inv = 1.0f / l[i];
        const u64 ii = pack2(inv, inv);
        ulonglong2 o;
        o.x = mul2(acc[i][0], ii);
        o.y = mul2(acc[i][1], ii);
        *reinterpret_cast<ulonglong2*>(
            Og + ((size_t)(bi * cT + t0 + ty * 4 + i) * cH + hi) * cDK + (tx << 2)) = o;
    }
}

// ---------------------------------------------------------------------------
extern "C" void kernel_launch(void* const* d_in, const int* in_sizes, int n_in,
                              void* d_out, int out_size)
{
    const float* query = (const float*)d_in[0];
    const float* value = (const float*)d_in[1];
    const float* key   = (const float*)d_in[2];
    const float* Wq    = (const float*)d_in[3];
    const float* bq    = (const float*)d_in[4];
    const float* Wk    = (const float*)d_in[5];
    const float* bk    = (const float*)d_in[6];
    const float* Wv    = (const float*)d_in[7];
    const float* bv    = (const float*)d_in[8];
    const float* Wo    = (const float*)d_in[9];
    const float* bo    = (const float*)d_in[10];
    float* out = (float*)d_out;

    float *pq, *pk, *pv, *pa;
    __nv_bfloat16 *xh, *xl, *wh, *wl;
    cudaGetSymbolAddress((void**)&pq, g_q);
    cudaGetSymbolAddress((void**)&pk, g_k);
    cudaGetSymbolAddress((void**)&pv, g_v);
    cudaGetSymbolAddress((void**)&pa, g_attn);
    cudaGetSymbolAddress((void**)&xh, g_xh);
    cudaGetSymbolAddress((void**)&xl, g_xl);
    cudaGetSymbolAddress((void**)&wh, g_wth);
    cudaGetSymbolAddress((void**)&wl, g_wtl);

    cudaFuncSetAttribute(attn_kernel,
                         cudaFuncAttributeMaxDynamicSharedMemorySize,
                         ATTN_SMEM_BYTES);
    cudaFuncSetAttribute(gemm_mma,
                         cudaFuncAttributeMaxDynamicSharedMemorySize,
                         GEMM_SMEM);

    const int XB = (int)(XSZ / 4 / 256);

    xconv<<<XB, 256>>>(query, xh, xl);
    xconv<<<XB, 256>>>(key,   xh + XSZ, xl + XSZ);
    xconv<<<XB, 256>>>(value, xh + 2 * XSZ, xl + 2 * XSZ);
    wconv<<<dim3(32, 32, 4), dim3(32, 8)>>>(Wq, Wk, Wv, Wo, wh, wl);

    // Fused Q/K/V projections on tensor cores (z selects input/weight/out)
    gemm_mma<<<dim3(cHD / 128, cMT / 128, 3), 256, GEMM_SMEM>>>(
        xh, xl, wh, wl, bq, bk, bv, pq, pk, pv, 0.125f);

    attn_kernel<<<dim3(cT / 64, cH, cB), 256, ATTN_SMEM_BYTES>>>(pq, pk, pv, pa);

    xconv<<<XB, 256>>>(pa, xh, xl);
    gemm_mma<<<dim3(cD / 128, cMT / 128, 1), 256, GEMM_SMEM>>>(
        xh, xl, wh + 3 * WSZ, wl + 3 * WSZ, bo, bo, bo, out, out, out, 1.0f);
}

// round 6
// speedup vs baseline: 3.0566x; 1.5899x over previous
#include <cuda_runtime.h>
#include <cuda_bf16.h>
#include <math.h>
#include <cstdint>

// Problem constants
constexpr int cB = 2, cT = 2048, cS = 2048, cD = 1024, cH = 16, cDK = 64;
constexpr int cHD = cH * cDK;      // 1024
constexpr int cMT = cB * cT;       // 4096
constexpr size_t XSZ = (size_t)cMT * cD;    // per slot
constexpr size_t WSZ = (size_t)cD * cHD;    // per weight

using bf16 = __nv_bfloat16;
typedef unsigned short ushortx;

// ---- helpers ----
__device__ __forceinline__ uint32_t smem_u32(const void* p) {
    uint32_t a;
    asm("{ .reg .u64 t; cvta.to.shared.u64 t, %1; cvt.u32.u64 %0, t; }"
        : "=r"(a) : "l"(p));
    return a;
}
__device__ __forceinline__ void ldsm4(uint32_t& r0, uint32_t& r1,
                                      uint32_t& r2, uint32_t& r3, uint32_t a) {
    asm volatile("ldmatrix.sync.aligned.m8n8.x4.shared.b16 {%0,%1,%2,%3}, [%4];"
                 : "=r"(r0), "=r"(r1), "=r"(r2), "=r"(r3) : "r"(a));
}
__device__ __forceinline__ void mma_bf16(float c[4],
    uint32_t a0, uint32_t a1, uint32_t a2, uint32_t a3,
    uint32_t b0, uint32_t b1) {
    asm volatile("mma.sync.aligned.m16n8k16.row.col.f32.bf16.bf16.f32 "
                 "{%0,%1,%2,%3}, {%4,%5,%6,%7}, {%8,%9}, {%0,%1,%2,%3};"
                 : "+f"(c[0]), "+f"(c[1]), "+f"(c[2]), "+f"(c[3])
                 : "r"(a0), "r"(a1), "r"(a2), "r"(a3), "r"(b0), "r"(b1));
}
__device__ __forceinline__ void cp16(uint32_t dst, const void* src) {
    asm volatile("cp.async.cg.shared.global [%0], [%1], 16;"
                 :: "r"(dst), "l"(src));
}
#define CP_COMMIT() asm volatile("cp.async.commit_group;")
#define CP_WAIT(n)  asm volatile("cp.async.wait_group %0;" :: "n"(n))

// pack two fp32 -> bf16x2 (lo = first arg); bf16->fp32 is just <<16
__device__ __forceinline__ uint32_t packbf(float lo, float hi) {
    uint32_t r;
    asm("cvt.rn.bf16x2.f32 %0, %1, %2;" : "=r"(r) : "f"(hi), "f"(lo));
    return r;
}
__device__ __forceinline__ void hilo2(float x, float y,
                                      uint32_t& h, uint32_t& l) {
    h = packbf(x, y);
    const float hx = __uint_as_float(h << 16);
    const float hy = __uint_as_float(h & 0xffff0000u);
    l = packbf(x - hx, y - hy);
}

// ---- Scratch (__device__ globals; alloc-free rule) ----
__device__ bf16 g_xh[3 * XSZ];     // GEMM inputs hi (q,k,v / attn-out)
__device__ bf16 g_xl[3 * XSZ];
__device__ bf16 g_yh[3 * XSZ];     // projection outputs hi (q,k,v)
__device__ bf16 g_yl[3 * XSZ];
__device__ bf16 g_wth[4 * WSZ];    // W^T [N][K] hi
__device__ bf16 g_wtl[4 * WSZ];

// ---------------------------------------------------------------------------
// fp32 -> bf16 hi/lo split
// ---------------------------------------------------------------------------
__global__ __launch_bounds__(256) void xconv(
    const float* __restrict__ X, bf16* __restrict__ xh, bf16* __restrict__ xl)
{
    const size_t i4 = ((size_t)blockIdx.x * 256 + threadIdx.x) * 4;
    const float4 v = *reinterpret_cast<const float4*>(X + i4);
    uint32_t h0, l0, h1, l1;
    hilo2(v.x, v.y, h0, l0);
    hilo2(v.z, v.w, h1, l1);
    uint2* ph = reinterpret_cast<uint2*>(xh + i4);
    uint2* pl = reinterpret_cast<uint2*>(xl + i4);
    *ph = make_uint2(h0, h1);
    *pl = make_uint2(l0, l1);
}

// ---------------------------------------------------------------------------
// W[K,N] fp32 -> W^T[N,K] bf16 hi/lo
// ---------------------------------------------------------------------------
__global__ __launch_bounds__(256) void wconv(
    const float* __restrict__ W0, const float* __restrict__ W1,
    const float* __restrict__ W2, const float* __restrict__ W3,
    bf16* __restrict__ wh, bf16* __restrict__ wl)
{
    __shared__ float t[32][33];
    const int z = blockIdx.z;
    const float* W = (z == 0) ? W0 : (z == 1) ? W1 : (z == 2) ? W2 : W3;
    const int n0 = blockIdx.x * 32, k0 = blockIdx.y * 32;
    const int tx = threadIdx.x, ty = threadIdx.y;
    #pragma unroll
    for (int i = 0; i < 4; i++)
        t[ty + 8 * i][tx] = W[(size_t)(k0 + ty + 8 * i) * cHD + n0 + tx];
    __syncthreads();
    const size_t zb = (size_t)z * WSZ;
    #pragma unroll
    for (int i = 0; i < 4; i++) {
        const float v = t[tx][ty + 8 * i];
        const bf16 h = __float2bfloat16(v);
        const bf16 l = __float2bfloat16(v - __bfloat162float(h));
        const size_t o = zb + (size_t)(n0 + ty + 8 * i) * cD + k0 + tx;
        wh[o] = h; wl[o] = l;
    }
}

// ---------------------------------------------------------------------------
// mma.sync split-bf16 GEMM (verified round 5). BF16OUT selects epilogue:
// true -> write (hi,lo) bf16 pair arrays; false -> fp32.
// ---------------------------------------------------------------------------
constexpr int ROWB = 80;
constexpr int TILE_B = 128 * ROWB;
constexpr int STAGE_B = 4 * TILE_B;
constexpr int GEMM_SMEM = 2 * STAGE_B;   // 81920

template <bool BF16OUT>
__global__ __launch_bounds__(256, 2) void gemm_mma(
    const bf16* __restrict__ Xh, const bf16* __restrict__ Xl,
    const bf16* __restrict__ Wh, const bf16* __restrict__ Wl,
    const float* b0, const float* b1, const float* b2,
    float* oF, bf16* oh, bf16* ol, float scale0)
{
    extern __shared__ char dynsm[];
    const uint32_t sb = smem_u32(dynsm);
    const int tid = threadIdx.x;
    const int wid = tid >> 5;
    const int lane = tid & 31;
    const int z = blockIdx.z;
    const int m0 = blockIdx.y * 128;
    const int n0 = blockIdx.x * 128;
    const int wm = wid & 1;
    const int wn = wid >> 1;

    const bf16* Ah = Xh + (size_t)z * XSZ;
    const bf16* Al = Xl + (size_t)z * XSZ;
    const bf16* Bh = Wh + (size_t)z * WSZ;
    const bf16* Bl = Wl + (size_t)z * WSZ;
    const float* bias = (z == 0) ? b0 : (z == 1) ? b1 : b2;
    const float scale = (z == 0) ? scale0 : 1.0f;

    float acc[4][4][4] = {};

    const int lr0 = tid >> 2, lc = (tid & 3);
    const uint32_t so0 = (uint32_t)(lr0 * ROWB + lc * 16);
    const uint32_t so1 = (uint32_t)((lr0 + 64) * ROWB + lc * 16);

    auto load_stage = [&](int chunk, int stage) {
        const uint32_t s0 = sb + stage * STAGE_B;
        const int k0 = chunk * 32;
        const size_t ga0 = (size_t)(m0 + lr0) * cD + k0 + lc * 8;
        const size_t ga1 = (size_t)(m0 + lr0 + 64) * cD + k0 + lc * 8;
        const size_t gb0 = (size_t)(n0 + lr0) * cD + k0 + lc * 8;
        const size_t gb1 = (size_t)(n0 + lr0 + 64) * cD + k0 + lc * 8;
        cp16(s0 + so0,              Ah + ga0);
        cp16(s0 + so1,              Ah + ga1);
        cp16(s0 + TILE_B + so0,     Al + ga0);
        cp16(s0 + TILE_B + so1,     Al + ga1);
        cp16(s0 + 2 * TILE_B + so0, Bh + gb0);
        cp16(s0 + 2 * TILE_B + so1, Bh + gb1);
        cp16(s0 + 3 * TILE_B + so0, Bl + gb0);
        cp16(s0 + 3 * TILE_B + so1, Bl + gb1);
        CP_COMMIT();
    };

    load_stage(0, 0);
    const int NCH = cD / 32;
    for (int ch = 0; ch < NCH; ch++) {
        if (ch + 1 < NCH) { load_stage(ch + 1, (ch + 1) & 1); CP_WAIT(1); }
        else              { CP_WAIT(0); }
        __syncthreads();
        const uint32_t s0 = sb + (ch & 1) * STAGE_B;

        #pragma unroll
        for (int sp = 0; sp < 3; sp++) {
            const uint32_t ab = s0 + ((sp == 1) ? TILE_B : 0);
            const uint32_t bb = s0 + ((sp == 2) ? 3 * TILE_B : 2 * TILE_B);
            #pragma unroll
            for (int ks = 0; ks < 2; ks++) {
                uint32_t af[4][4];
                #pragma unroll
                for (int mi = 0; mi < 4; mi++) {
                    const int row = wm * 64 + mi * 16 + (lane & 15);
                    const int col = ks * 16 + ((lane >> 4) << 3);
                    ldsm4(af[mi][0], af[mi][1], af[mi][2], af[mi][3],
                          ab + (uint32_t)(row * ROWB + col * 2));
                }
                uint32_t bf[4][2];
                #pragma unroll
                for (int np = 0; np < 2; np++) {
                    const int nrow = wn * 32 + np * 16 + (lane & 7) + ((lane >> 4) << 3);
                    const int col = ks * 16 + (((lane >> 3) & 1) << 3);
                    uint32_t r0, r1, r2, r3;
                    ldsm4(r0, r1, r2, r3, bb + (uint32_t)(nrow * ROWB + col * 2));
                    bf[2 * np][0] = r0;     bf[2 * np][1] = r1;
                    bf[2 * np + 1][0] = r2; bf[2 * np + 1][1] = r3;
                }
                #pragma unroll
                for (int mi = 0; mi < 4; mi++)
                    #pragma unroll
                    for (int ni = 0; ni < 4; ni++)
                        mma_bf16(acc[mi][ni], af[mi][0], af[mi][1],
                                 af[mi][2], af[mi][3], bf[ni][0], bf[ni][1]);
            }
        }
        __syncthreads();
    }

    // Epilogue
    #pragma unroll
    for (int mi = 0; mi < 4; mi++) {
        #pragma unroll
        for (int h = 0; h < 2; h++) {
            const int row = m0 + wm * 64 + mi * 16 + h * 8 + (lane >> 2);
            #pragma unroll
            for (int ni = 0; ni < 4; ni++) {
                const int col = n0 + wn * 32 + ni * 8 + (lane & 3) * 2;
                const float2 bb = *reinterpret_cast<const float2*>(bias + col);
                const float v0 = (acc[mi][ni][h * 2 + 0] + bb.x) * scale;
                const float v1 = (acc[mi][ni][h * 2 + 1] + bb.y) * scale;
                if (BF16OUT) {
                    uint32_t hp, lp;
                    hilo2(v0, v1, hp, lp);
                    const size_t o = (size_t)z * XSZ + (size_t)row * 1024 + col;
                    *reinterpret_cast<uint32_t*>(oh + o) = hp;
                    *reinterpret_cast<uint32_t*>(ol + o) = lp;
                } else {
                    *reinterpret_cast<float2*>(oF + (size_t)row * 1024 + col) =
                        make_float2(v0, v1);
                }
            }
        }
    }
}

// ---------------------------------------------------------------------------
// Tensor-core flash attention (split-bf16, 3-MMA per product).
// CTA: 128 q-rows x (head, batch); 8 warps, 16 rows each; s-tiles of 64.
// P lives in registers (S C-fragment == PV A-fragment layout).
// ---------------------------------------------------------------------------
constexpr int ROW2 = 144;                    // padded row pitch (9x16B)
constexpr int A_KH = 0;                      // K hi   (64 x ROW2)
constexpr int A_KL = 64 * ROW2;              // K lo
constexpr int A_VTH = 2 * 64 * ROW2;         // V^T hi (dk-major)
constexpr int A_VTL = 3 * 64 * ROW2;         // V^T lo
constexpr int ATTN_SMEM = 4 * 64 * ROW2;     // 36864 (Q phase reuses it)

__global__ __launch_bounds__(256, 2) void attn_mma(
    const bf16* __restrict__ qh, const bf16* __restrict__ ql,
    const bf16* __restrict__ kh, const bf16* __restrict__ kl,
    const bf16* __restrict__ vh, const bf16* __restrict__ vl,
    bf16* __restrict__ oh, bf16* __restrict__ ol)
{
    __shared__ __align__(16) unsigned char smb[ATTN_SMEM];
    const uint32_t sb = smem_u32(smb);
    const int tid = threadIdx.x;
    const int wid = tid >> 5;
    const int lane = tid & 31;
    const int t0 = blockIdx.x * 128;
    const int hh = blockIdx.y;
    const int bi = blockIdx.z;

    // ---- Phase 1: Q tile (128x64 hi/lo) -> smem (pitch ROW2), then frags
    #pragma unroll
    for (int it = 0; it < 4; it++) {
        const int i = tid + it * 256;
        const int r = i >> 3, c = i & 7;
        const size_t g = ((size_t)(bi * cT + t0 + r) * cH + hh) * cDK + c * 8;
        // hi at rows [0..127] of region 0, lo at region offset 128*ROW2
        *reinterpret_cast<uint4*>(smb + r * ROW2 + c * 16) =
            *reinterpret_cast<const uint4*>(qh + g);
        *reinterpret_cast<uint4*>(smb + 128 * ROW2 + r * ROW2 + c * 16) =
            *reinterpret_cast<const uint4*>(ql + g);
    }
    __syncthreads();

    uint32_t qfh[4][4], qfl[4][4];
    #pragma unroll
    for (int kb = 0; kb < 4; kb++) {
        const int row = wid * 16 + (lane & 15);
        const int col = kb * 16 + ((lane >> 4) << 3);
        ldsm4(qfh[kb][0], qfh[kb][1], qfh[kb][2], qfh[kb][3],
              sb + (uint32_t)(row * ROW2 + col * 2));
        ldsm4(qfl[kb][0], qfl[kb][1], qfl[kb][2], qfl[kb][3],
              sb + (uint32_t)(128 * ROW2 + row * ROW2 + col * 2));
    }
    __syncthreads();   // done with Q smem; region becomes K/V

    float oacc[8][4] = {};
    float mrow0 = -INFINITY, mrow1 = -INFINITY;
    float lrow0 = 0.0f, lrow1 = 0.0f;

    for (int s0 = 0; s0 < cS; s0 += 64) {
        // ---- Load K (natural) and V (transposed) hi/lo tiles
        #pragma unroll
        for (int it = 0; it < 2; it++) {
            const int i = tid + it * 256;
            const int r = i >> 3, c = i & 7;
            const size_t g = ((size_t)(bi * cS + s0 + r) * cH + hh) * cDK + c * 8;
            *reinterpret_cast<uint4*>(smb + A_KH + r * ROW2 + c * 16) =
                *reinterpret_cast<const uint4*>(kh + g);
            *reinterpret_cast<uint4*>(smb + A_KL + r * ROW2 + c * 16) =
                *reinterpret_cast<const uint4*>(kl + g);
            const uint4 v4h = *reinterpret_cast<const uint4*>(vh + g);
            const uint4 v4l = *reinterpret_cast<const uint4*>(vl + g);
            const ushortx* pvh = reinterpret_cast<const ushortx*>(&v4h);
            const ushortx* pvl = reinterpret_cast<const ushortx*>(&v4l);
            #pragma unroll
            for (int j = 0; j < 8; j++) {
                *reinterpret_cast<ushortx*>(smb + A_VTH + (c * 8 + j) * ROW2 + r * 2) = pvh[j];
                *reinterpret_cast<ushortx*>(smb + A_VTL + (c * 8 + j) * ROW2 + r * 2) = pvl[j];
            }
        }
        __syncthreads();

        // ---- S = Q @ K^T (3-split)
        float sacc[8][4] = {};
        #pragma unroll
        for (int kb = 0; kb < 4; kb++) {
            #pragma unroll
            for (int np = 0; np < 4; np++) {
                const int nrow = np * 16 + (lane & 7) + ((lane >> 4) << 3);
                const int col = kb * 16 + (((lane >> 3) & 1) << 3);
                uint32_t h0, h1, h2, h3, l0, l1, l2, l3;
                ldsm4(h0, h1, h2, h3, sb + (uint32_t)(A_KH + nrow * ROW2 + col * 2));
                ldsm4(l0, l1, l2, l3, sb + (uint32_t)(A_KL + nrow * ROW2 + col * 2));
                mma_bf16(sacc[2 * np], qfh[kb][0], qfh[kb][1], qfh[kb][2], qfh[kb][3], h0, h1);
                mma_bf16(sacc[2 * np], qfl[kb][0], qfl[kb][1], qfl[kb][2], qfl[kb][3], h0, h1);
                mma_bf16(sacc[2 * np], qfh[kb][0], qfh[kb][1], qfh[kb][2], qfh[kb][3], l0, l1);
                mma_bf16(sacc[2 * np + 1], qfh[kb][0], qfh[kb][1], qfh[kb][2], qfh[kb][3], h2, h3);
                mma_bf16(sacc[2 * np + 1], qfl[kb][0], qfl[kb][1], qfl[kb][2], qfl[kb][3], h2, h3);
                mma_bf16(sacc[2 * np + 1], qfh[kb][0], qfh[kb][1], qfh[kb][2], qfh[kb][3], l2, l3);
            }
        }

        // ---- Online softmax; thread owns rows (lane>>2) and +8 within warp tile
        float mx0 = -INFINITY, mx1 = -INFINITY;
        #pragma unroll
        for (int n = 0; n < 8; n++) {
            mx0 = fmaxf(mx0, fmaxf(sacc[n][0], sacc[n][1]));
            mx1 = fmaxf(mx1, fmaxf(sacc[n][2], sacc[n][3]));
        }
        mx0 = fmaxf(mx0, __shfl_xor_sync(0xffffffffu, mx0, 1));
        mx0 = fmaxf(mx0, __shfl_xor_sync(0xffffffffu, mx0, 2));
        mx1 = fmaxf(mx1, __shfl_xor_sync(0xffffffffu, mx1, 1));
        mx1 = fmaxf(mx1, __shfl_xor_sync(0xffffffffu, mx1, 2));
        const float mn0 = fmaxf(mrow0, mx0);
        const float mn1 = fmaxf(mrow1, mx1);
        const float corr0 = __expf(mrow0 - mn0);
        const float corr1 = __expf(mrow1 - mn1);
        float sum0 = 0.0f, sum1 = 0.0f;
        #pragma unroll
        for (int n = 0; n < 8; n++) {
            sacc[n][0] = __expf(sacc[n][0] - mn0);
            sacc[n][1] = __expf(sacc[n][1] - mn0);
            sacc[n][2] = __expf(sacc[n][2] - mn1);
            sacc[n][3] = __expf(sacc[n][3] - mn1);
            sum0 += sacc[n][0] + sacc[n][1];
            sum1 += sacc[n][2] + sacc[n][3];
        }
        sum0 += __shfl_xor_sync(0xffffffffu, sum0, 1);
        sum0 += __shfl_xor_sync(0xffffffffu, sum0, 2);
        sum1 += __shfl_xor_sync(0xffffffffu, sum1, 1);
        sum1 += __shfl_xor_sync(0xffffffffu, sum1, 2);
        lrow0 = lrow0 * corr0 + sum0;  mrow0 = mn0;
        lrow1 = lrow1 * corr1 + sum1;  mrow1 = mn1;
        #pragma unroll
        for (int n = 0; n < 8; n++) {
            oacc[n][0] *= corr0; oacc[n][1] *= corr0;
            oacc[n][2] *= corr1; oacc[n][3] *= corr1;
        }

        // ---- O += P @ V (3-split); P frags built from sacc in place
        #pragma unroll
        for (int kb = 0; kb < 4; kb++) {
            uint32_t pah[4], pal[4];
            hilo2(sacc[2 * kb][0],     sacc[2 * kb][1],     pah[0], pal[0]);
            hilo2(sacc[2 * kb][2],     sacc[2 * kb][3],     pah[1], pal[1]);
            hilo2(sacc[2 * kb + 1][0], sacc[2 * kb + 1][1], pah[2], pal[2]);
            hilo2(sacc[2 * kb + 1][2], sacc[2 * kb + 1][3], pah[3], pal[3]);
            #pragma unroll
            for (int np = 0; np < 4; np++) {
                const int nrow = np * 16 + (lane & 7) + ((lane >> 4) << 3);
                const int col = kb * 16 + (((lane >> 3) & 1) << 3);
                uint32_t h0, h1, h2, h3, l0, l1, l2, l3;
                ldsm4(h0, h1, h2, h3, sb + (uint32_t)(A_VTH + nrow * ROW2 + col * 2));
                ldsm4(l0, l1, l2, l3, sb + (uint32_t)(A_VTL + nrow * ROW2 + col * 2));
                mma_bf16(oacc[2 * np], pah[0], pah[1], pah[2], pah[3], h0, h1);
                mma_bf16(oacc[2 * np], pal[0], pal[1], pal[2], pal[3], h0, h1);
                mma_bf16(oacc[2 * np], pah[0], pah[1], pah[2], pah[3], l0, l1);
                mma_bf16(oacc[2 * np + 1], pah[0], pah[1], pah[2], pah[3], h2, h3);
                mma_bf16(oacc[2 * np + 1], pal[0], pal[1], pal[2], pal[3], h2, h3);
                mma_bf16(oacc[2 * np + 1], pah[0], pah[1], pah[2], pah[3], l2, l3);
            }
        }
        __syncthreads();   // protect K/V smem before next tile's load
    }

    // ---- Normalize + write O as bf16 hi/lo pairs
    const float inv0 = 1.0f / lrow0;
    const float inv1 = 1.0f / lrow1;
    const int row0 = t0 + wid * 16 + (lane >> 2);
    #pragma unroll
    for (int n = 0; n < 8; n++) {
        const int dk = n * 8 + (lane & 3) * 2;
        const size_t g0 = ((size_t)(bi * cT + row0) * cH + hh) * cDK + dk;
        const size_t g1 = ((size_t)(bi * cT + row0 + 8) * cH + hh) * cDK + dk;
        uint32_t hp, lp;
        hilo2(oacc[n][0] * inv0, oacc[n][1] * inv0, hp, lp);
        *reinterpret_cast<uint32_t*>(oh + g0) = hp;
        *reinterpret_cast<uint32_t*>(ol + g0) = lp;
        hilo2(oacc[n][2] * inv1, oacc[n][3] * inv1, hp, lp);
        *reinterpret_cast<uint32_t*>(oh + g1) = hp;
        *reinterpret_cast<uint32_t*>(ol + g1) = lp;
    }
}

// ---------------------------------------------------------------------------
extern "C" void kernel_launch(void* const* d_in, const int* in_sizes, int n_in,
                              void* d_out, int out_size)
{
    const float* query = (const float*)d_in[0];
    const float* value = (const float*)d_in[1];
    const float* key   = (const float*)d_in[2];
    const float* Wq    = (const float*)d_in[3];
    const float* bq    = (const float*)d_in[4];
    const float* Wk    = (const float*)d_in[5];
    const float* bk    = (const float*)d_in[6];
    const float* Wv    = (const float*)d_in[7];
    const float* bv    = (const float*)d_in[8];
    const float* Wo    = (const float*)d_in[9];
    const float* bo    = (const float*)d_in[10];
    float* out = (float*)d_out;

    bf16 *xh, *xl, *yh, *yl, *wh, *wl;
    cudaGetSymbolAddress((void**)&xh, g_xh);
    cudaGetSymbolAddress((void**)&xl, g_xl);
    cudaGetSymbolAddress((void**)&yh, g_yh);
    cudaGetSymbolAddress((void**)&yl, g_yl);
    cudaGetSymbolAddress((void**)&wh, g_wth);
    cudaGetSymbolAddress((void**)&wl, g_wtl);

    cudaFuncSetAttribute(gemm_mma<true>,
                         cudaFuncAttributeMaxDynamicSharedMemorySize, GEMM_SMEM);
    cudaFuncSetAttribute(gemm_mma<false>,
                         cudaFuncAttributeMaxDynamicSharedMemorySize, GEMM_SMEM);

    const int XB = (int)(XSZ / 4 / 256);

    // input converts: query->slot0, key->slot1, value->slot2
    xconv<<<XB, 256>>>(query, xh, xl);
    xconv<<<XB, 256>>>(key,   xh + XSZ, xl + XSZ);
    xconv<<<XB, 256>>>(value, xh + 2 * XSZ, xl + 2 * XSZ);
    wconv<<<dim3(32, 32, 4), dim3(32, 8)>>>(Wq, Wk, Wv, Wo, wh, wl);

    // Q/K/V projections -> bf16 hi/lo outputs (z = 0,1,2)
    gemm_mma<true><<<dim3(cHD / 128, cMT / 128, 3), 256, GEMM_SMEM>>>(
        xh, xl, wh, wl, bq, bk, bv, nullptr, yh, yl, 0.125f);

    // tensor-core attention; writes bf16 hi/lo into x slot 0
    attn_mma<<<dim3(cT / 128, cH, cB), 256>>>(
        yh, yl, yh + XSZ, yl + XSZ, yh + 2 * XSZ, yl + 2 * XSZ, xh, xl);

    // O projection (fp32 out)
    gemm_mma<false><<<dim3(cD / 128, cMT / 128, 1), 256, GEMM_SMEM>>>(
        xh, xl, wh + 3 * WSZ, wl + 3 * WSZ, bo, bo, bo, out, nullptr, nullptr, 1.0f);
}

// round 7
// speedup vs baseline: 3.6000x; 1.1778x over previous
#include <cuda_runtime.h>
#include <cuda_bf16.h>
#include <math.h>
#include <cstdint>

// Problem constants
constexpr int cB = 2, cT = 2048, cS = 2048, cD = 1024, cH = 16, cDK = 64;
constexpr int cHD = cH * cDK;      // 1024
constexpr int cMT = cB * cT;       // 4096
constexpr size_t XSZ = (size_t)cMT * cD;    // per slot
constexpr size_t WSZ = (size_t)cD * cHD;    // per weight

using bf16 = __nv_bfloat16;

// ---- helpers ----
__device__ __forceinline__ uint32_t smem_u32(const void* p) {
    uint32_t a;
    asm("{ .reg .u64 t; cvta.to.shared.u64 t, %1; cvt.u32.u64 %0, t; }"
        : "=r"(a) : "l"(p));
    return a;
}
__device__ __forceinline__ void ldsm4(uint32_t& r0, uint32_t& r1,
                                      uint32_t& r2, uint32_t& r3, uint32_t a) {
    asm volatile("ldmatrix.sync.aligned.m8n8.x4.shared.b16 {%0,%1,%2,%3}, [%4];"
                 : "=r"(r0), "=r"(r1), "=r"(r2), "=r"(r3) : "r"(a));
}
__device__ __forceinline__ void ldsm4t(uint32_t& r0, uint32_t& r1,
                                       uint32_t& r2, uint32_t& r3, uint32_t a) {
    asm volatile("ldmatrix.sync.aligned.m8n8.x4.trans.shared.b16 {%0,%1,%2,%3}, [%4];"
                 : "=r"(r0), "=r"(r1), "=r"(r2), "=r"(r3) : "r"(a));
}
__device__ __forceinline__ void mma_bf16(float c[4],
    uint32_t a0, uint32_t a1, uint32_t a2, uint32_t a3,
    uint32_t b0, uint32_t b1) {
    asm volatile("mma.sync.aligned.m16n8k16.row.col.f32.bf16.bf16.f32 "
                 "{%0,%1,%2,%3}, {%4,%5,%6,%7}, {%8,%9}, {%0,%1,%2,%3};"
                 : "+f"(c[0]), "+f"(c[1]), "+f"(c[2]), "+f"(c[3])
                 : "r"(a0), "r"(a1), "r"(a2), "r"(a3), "r"(b0), "r"(b1));
}
__device__ __forceinline__ void cp16(uint32_t dst, const void* src) {
    asm volatile("cp.async.cg.shared.global [%0], [%1], 16;"
                 :: "r"(dst), "l"(src));
}
#define CP_COMMIT() asm volatile("cp.async.commit_group;")
#define CP_WAIT(n)  asm volatile("cp.async.wait_group %0;" :: "n"(n))

// pack two fp32 -> bf16x2 (lo-half = first arg)
__device__ __forceinline__ uint32_t packbf(float lo, float hi) {
    uint32_t r;
    asm("cvt.rn.bf16x2.f32 %0, %1, %2;" : "=r"(r) : "f"(hi), "f"(lo));
    return r;
}
__device__ __forceinline__ void hilo2(float x, float y,
                                      uint32_t& h, uint32_t& l) {
    h = packbf(x, y);
    const float hx = __uint_as_float(h << 16);
    const float hy = __uint_as_float(h & 0xffff0000u);
    l = packbf(x - hx, y - hy);
}

// ---- Scratch ----
__device__ bf16 g_xh[3 * XSZ];
__device__ bf16 g_xl[3 * XSZ];
__device__ bf16 g_yh[3 * XSZ];
__device__ bf16 g_yl[3 * XSZ];
__device__ bf16 g_wth[4 * WSZ];
__device__ bf16 g_wtl[4 * WSZ];

// ---------------------------------------------------------------------------
// fp32 -> bf16 hi/lo split
// ---------------------------------------------------------------------------
__global__ __launch_bounds__(256) void xconv(
    const float* __restrict__ X, bf16* __restrict__ xh, bf16* __restrict__ xl)
{
    const size_t i4 = ((size_t)blockIdx.x * 256 + threadIdx.x) * 4;
    const float4 v = *reinterpret_cast<const float4*>(X + i4);
    uint32_t h0, l0, h1, l1;
    hilo2(v.x, v.y, h0, l0);
    hilo2(v.z, v.w, h1, l1);
    *reinterpret_cast<uint2*>(xh + i4) = make_uint2(h0, h1);
    *reinterpret_cast<uint2*>(xl + i4) = make_uint2(l0, l1);
}

// ---------------------------------------------------------------------------
// W[K,N] fp32 -> W^T[N,K] bf16 hi/lo
// ---------------------------------------------------------------------------
__global__ __launch_bounds__(256) void wconv(
    const float* __restrict__ W0, const float* __restrict__ W1,
    const float* __restrict__ W2, const float* __restrict__ W3,
    bf16* __restrict__ wh, bf16* __restrict__ wl)
{
    __shared__ float t[32][33];
    const int z = blockIdx.z;
    const float* W = (z == 0) ? W0 : (z == 1) ? W1 : (z == 2) ? W2 : W3;
    const int n0 = blockIdx.x * 32, k0 = blockIdx.y * 32;
    const int tx = threadIdx.x, ty = threadIdx.y;
    #pragma unroll
    for (int i = 0; i < 4; i++)
        t[ty + 8 * i][tx] = W[(size_t)(k0 + ty + 8 * i) * cHD + n0 + tx];
    __syncthreads();
    const size_t zb = (size_t)z * WSZ;
    #pragma unroll
    for (int i = 0; i < 4; i++) {
        const float v = t[tx][ty + 8 * i];
        const bf16 h = __float2bfloat16(v);
        const bf16 l = __float2bfloat16(v - __bfloat162float(h));
        const size_t o = zb + (size_t)(n0 + ty + 8 * i) * cD + k0 + tx;
        wh[o] = h; wl[o] = l;
    }
}

// ---------------------------------------------------------------------------
// mma.sync split-bf16 GEMM (verified). BF16OUT selects bf16-hi/lo vs fp32 out.
// ---------------------------------------------------------------------------
constexpr int ROWB = 80;
constexpr int TILE_B = 128 * ROWB;
constexpr int STAGE_B = 4 * TILE_B;
constexpr int GEMM_SMEM = 2 * STAGE_B;   // 81920

template <bool BF16OUT>
__global__ __launch_bounds__(256, 2) void gemm_mma(
    const bf16* __restrict__ Xh, const bf16* __restrict__ Xl,
    const bf16* __restrict__ Wh, const bf16* __restrict__ Wl,
    const float* b0, const float* b1, const float* b2,
    float* oF, bf16* oh, bf16* ol, float scale0)
{
    extern __shared__ char dynsm[];
    const uint32_t sb = smem_u32(dynsm);
    const int tid = threadIdx.x;
    const int wid = tid >> 5;
    const int lane = tid & 31;
    const int z = blockIdx.z;
    const int m0 = blockIdx.y * 128;
    const int n0 = blockIdx.x * 128;
    const int wm = wid & 1;
    const int wn = wid >> 1;

    const bf16* Ah = Xh + (size_t)z * XSZ;
    const bf16* Al = Xl + (size_t)z * XSZ;
    const bf16* Bh = Wh + (size_t)z * WSZ;
    const bf16* Bl = Wl + (size_t)z * WSZ;
    const float* bias = (z == 0) ? b0 : (z == 1) ? b1 : b2;
    const float scale = (z == 0) ? scale0 : 1.0f;

    float acc[4][4][4] = {};

    const int lr0 = tid >> 2, lc = (tid & 3);
    const uint32_t so0 = (uint32_t)(lr0 * ROWB + lc * 16);
    const uint32_t so1 = (uint32_t)((lr0 + 64) * ROWB + lc * 16);

    auto load_stage = [&](int chunk, int stage) {
        const uint32_t s0 = sb + stage * STAGE_B;
        const int k0 = chunk * 32;
        const size_t ga0 = (size_t)(m0 + lr0) * cD + k0 + lc * 8;
        const size_t ga1 = (size_t)(m0 + lr0 + 64) * cD + k0 + lc * 8;
        const size_t gb0 = (size_t)(n0 + lr0) * cD + k0 + lc * 8;
        const size_t gb1 = (size_t)(n0 + lr0 + 64) * cD + k0 + lc * 8;
        cp16(s0 + so0,              Ah + ga0);
        cp16(s0 + so1,              Ah + ga1);
        cp16(s0 + TILE_B + so0,     Al + ga0);
        cp16(s0 + TILE_B + so1,     Al + ga1);
        cp16(s0 + 2 * TILE_B + so0, Bh + gb0);
        cp16(s0 + 2 * TILE_B + so1, Bh + gb1);
        cp16(s0 + 3 * TILE_B + so0, Bl + gb0);
        cp16(s0 + 3 * TILE_B + so1, Bl + gb1);
        CP_COMMIT();
    };

    load_stage(0, 0);
    const int NCH = cD / 32;
    for (int ch = 0; ch < NCH; ch++) {
        if (ch + 1 < NCH) { load_stage(ch + 1, (ch + 1) & 1); CP_WAIT(1); }
        else              { CP_WAIT(0); }
        __syncthreads();
        const uint32_t s0 = sb + (ch & 1) * STAGE_B;

        #pragma unroll
        for (int sp = 0; sp < 3; sp++) {
            const uint32_t ab = s0 + ((sp == 1) ? TILE_B : 0);
            const uint32_t bb = s0 + ((sp == 2) ? 3 * TILE_B : 2 * TILE_B);
            #pragma unroll
            for (int ks = 0; ks < 2; ks++) {
                uint32_t af[4][4];
                #pragma unroll
                for (int mi = 0; mi < 4; mi++) {
                    const int row = wm * 64 + mi * 16 + (lane & 15);
                    const int col = ks * 16 + ((lane >> 4) << 3);
                    ldsm4(af[mi][0], af[mi][1], af[mi][2], af[mi][3],
                          ab + (uint32_t)(row * ROWB + col * 2));
                }
                uint32_t bf[4][2];
                #pragma unroll
                for (int np = 0; np < 2; np++) {
                    const int nrow = wn * 32 + np * 16 + (lane & 7) + ((lane >> 4) << 3);
                    const int col = ks * 16 + (((lane >> 3) & 1) << 3);
                    uint32_t r0, r1, r2, r3;
                    ldsm4(r0, r1, r2, r3, bb + (uint32_t)(nrow * ROWB + col * 2));
                    bf[2 * np][0] = r0;     bf[2 * np][1] = r1;
                    bf[2 * np + 1][0] = r2; bf[2 * np + 1][1] = r3;
                }
                #pragma unroll
                for (int mi = 0; mi < 4; mi++)
                    #pragma unroll
                    for (int ni = 0; ni < 4; ni++)
                        mma_bf16(acc[mi][ni], af[mi][0], af[mi][1],
                                 af[mi][2], af[mi][3], bf[ni][0], bf[ni][1]);
            }
        }
        __syncthreads();
    }

    #pragma unroll
    for (int mi = 0; mi < 4; mi++) {
        #pragma unroll
        for (int h = 0; h < 2; h++) {
            const int row = m0 + wm * 64 + mi * 16 + h * 8 + (lane >> 2);
            #pragma unroll
            for (int ni = 0; ni < 4; ni++) {
                const int col = n0 + wn * 32 + ni * 8 + (lane & 3) * 2;
                const float2 bb = *reinterpret_cast<const float2*>(bias + col);
                const float v0 = (acc[mi][ni][h * 2 + 0] + bb.x) * scale;
                const float v1 = (acc[mi][ni][h * 2 + 1] + bb.y) * scale;
                if (BF16OUT) {
                    uint32_t hp, lp;
                    hilo2(v0, v1, hp, lp);
                    const size_t o = (size_t)z * XSZ + (size_t)row * 1024 + col;
                    *reinterpret_cast<uint32_t*>(oh + o) = hp;
                    *reinterpret_cast<uint32_t*>(ol + o) = lp;
                } else {
                    *reinterpret_cast<float2*>(oF + (size_t)row * 1024 + col) =
                        make_float2(v0, v1);
                }
            }
        }
    }
}

// ---------------------------------------------------------------------------
// Tensor-core flash attention, v2:
//   - V stored NATURALLY, PV B-fragment via ldmatrix.trans (no scalar transpose)
//   - K/V hi/lo tiles double-buffered with cp.async
// CTA: 128 q-rows x (head, batch); 8 warps x 16 rows; s-tiles of 64.
// ---------------------------------------------------------------------------
constexpr int ROW2 = 144;                    // row pitch (9x16B, conflict-free)
constexpr int R_KH = 0;                      // K hi (64 x ROW2)
constexpr int R_KL = 64 * ROW2;
constexpr int R_VH = 2 * 64 * ROW2;          // V hi, natural [s][dk]
constexpr int R_VL = 3 * 64 * ROW2;
constexpr int STG2 = 4 * 64 * ROW2;          // 36864 per stage
constexpr int ATTN_SMEM = 2 * STG2;          // 73728

__global__ __launch_bounds__(256, 2) void attn_mma(
    const bf16* __restrict__ qh, const bf16* __restrict__ ql,
    const bf16* __restrict__ kh, const bf16* __restrict__ kl,
    const bf16* __restrict__ vh, const bf16* __restrict__ vl,
    bf16* __restrict__ oh, bf16* __restrict__ ol)
{
    __shared__ __align__(16) unsigned char smb[ATTN_SMEM];
    const uint32_t sb = smem_u32(smb);
    const int tid = threadIdx.x;
    const int wid = tid >> 5;
    const int lane = tid & 31;
    const int t0 = blockIdx.x * 128;
    const int hh = blockIdx.y;
    const int bi = blockIdx.z;

    // ---- Q tile (128x64 hi/lo) -> smem, then register fragments
    #pragma unroll
    for (int it = 0; it < 4; it++) {
        const int i = tid + it * 256;
        const int r = i >> 3, c = i & 7;
        const size_t g = ((size_t)(bi * cT + t0 + r) * cH + hh) * cDK + c * 8;
        *reinterpret_cast<uint4*>(smb + r * ROW2 + c * 16) =
            *reinterpret_cast<const uint4*>(qh + g);
        *reinterpret_cast<uint4*>(smb + 128 * ROW2 + r * ROW2 + c * 16) =
            *reinterpret_cast<const uint4*>(ql + g);
    }
    __syncthreads();

    uint32_t qfh[4][4], qfl[4][4];
    #pragma unroll
    for (int kb = 0; kb < 4; kb++) {
        const int row = wid * 16 + (lane & 15);
        const int col = kb * 16 + ((lane >> 4) << 3);
        ldsm4(qfh[kb][0], qfh[kb][1], qfh[kb][2], qfh[kb][3],
              sb + (uint32_t)(row * ROW2 + col * 2));
        ldsm4(qfl[kb][0], qfl[kb][1], qfl[kb][2], qfl[kb][3],
              sb + (uint32_t)(128 * ROW2 + row * ROW2 + col * 2));
    }
    __syncthreads();   // Q smem free; becomes K/V stages

    // K/V tile loader (vectorized cp.async for all 4 regions)
    const int lr = tid >> 3, lc8 = (tid & 7);     // lr 0..31, +32 on 2nd pass
    auto load_kv = [&](int s0, int stage) {
        const uint32_t st = sb + stage * STG2;
        #pragma unroll
        for (int it = 0; it < 2; it++) {
            const int r = lr + it * 32;
            const uint32_t so = (uint32_t)(r * ROW2 + lc8 * 16);
            const size_t g = ((size_t)(bi * cS + s0 + r) * cH + hh) * cDK + lc8 * 8;
            cp16(st + R_KH + so, kh + g);
            cp16(st + R_KL + so, kl + g);
            cp16(st + R_VH + so, vh + g);
            cp16(st + R_VL + so, vl + g);
        }
        CP_COMMIT();
    };

    float oacc[8][4] = {};
    float mrow0 = -INFINITY, mrow1 = -INFINITY;
    float lrow0 = 0.0f, lrow1 = 0.0f;

    const int quad = lane >> 3, id8 = lane & 7;
    constexpr int NT = cS / 64;
    load_kv(0, 0);

    for (int ch = 0; ch < NT; ch++) {
        if (ch + 1 < NT) { load_kv((ch + 1) * 64, (ch + 1) & 1); CP_WAIT(1); }
        else             { CP_WAIT(0); }
        __syncthreads();
        const uint32_t st = sb + (ch & 1) * STG2;

        // ---- S = Q @ K^T (3-split); K natural, non-trans B-frag
        float sacc[8][4] = {};
        #pragma unroll
        for (int kb = 0; kb < 4; kb++) {
            #pragma unroll
            for (int np = 0; np < 4; np++) {
                const int nrow = np * 16 + (lane & 7) + ((lane >> 4) << 3);
                const int col = kb * 16 + (((lane >> 3) & 1) << 3);
                uint32_t h0, h1, h2, h3, l0, l1, l2, l3;
                ldsm4(h0, h1, h2, h3, st + (uint32_t)(R_KH + nrow * ROW2 + col * 2));
                ldsm4(l0, l1, l2, l3, st + (uint32_t)(R_KL + nrow * ROW2 + col * 2));
                mma_bf16(sacc[2 * np], qfh[kb][0], qfh[kb][1], qfh[kb][2], qfh[kb][3], h0, h1);
                mma_bf16(sacc[2 * np], qfl[kb][0], qfl[kb][1], qfl[kb][2], qfl[kb][3], h0, h1);
                mma_bf16(sacc[2 * np], qfh[kb][0], qfh[kb][1], qfh[kb][2], qfh[kb][3], l0, l1);
                mma_bf16(sacc[2 * np + 1], qfh[kb][0], qfh[kb][1], qfh[kb][2], qfh[kb][3], h2, h3);
                mma_bf16(sacc[2 * np + 1], qfl[kb][0], qfl[kb][1], qfl[kb][2], qfl[kb][3], h2, h3);
                mma_bf16(sacc[2 * np + 1], qfh[kb][0], qfh[kb][1], qfh[kb][2], qfh[kb][3], l2, l3);
            }
        }

        // ---- Online softmax
        float mx0 = -INFINITY, mx1 = -INFINITY;
        #pragma unroll
        for (int n = 0; n < 8; n++) {
            mx0 = fmaxf(mx0, fmaxf(sacc[n][0], sacc[n][1]));
            mx1 = fmaxf(mx1, fmaxf(sacc[n][2], sacc[n][3]));
        }
        mx0 = fmaxf(mx0, __shfl_xor_sync(0xffffffffu, mx0, 1));
        mx0 = fmaxf(mx0, __shfl_xor_sync(0xffffffffu, mx0, 2));
        mx1 = fmaxf(mx1, __shfl_xor_sync(0xffffffffu, mx1, 1));
        mx1 = fmaxf(mx1, __shfl_xor_sync(0xffffffffu, mx1, 2));
        const float mn0 = fmaxf(mrow0, mx0);
        const float mn1 = fmaxf(mrow1, mx1);
        const float corr0 = __expf(mrow0 - mn0);
        const float corr1 = __expf(mrow1 - mn1);
        float sum0 = 0.0f, sum1 = 0.0f;
        #pragma unroll
        for (int n = 0; n < 8; n++) {
            sacc[n][0] = __expf(sacc[n][0] - mn0);
            sacc[n][1] = __expf(sacc[n][1] - mn0);
            sacc[n][2] = __expf(sacc[n][2] - mn1);
            sacc[n][3] = __expf(sacc[n][3] - mn1);
            sum0 += sacc[n][0] + sacc[n][1];
            sum1 += sacc[n][2] + sacc[n][3];
        }
        sum0 += __shfl_xor_sync(0xffffffffu, sum0, 1);
        sum0 += __shfl_xor_sync(0xffffffffu, sum0, 2);
        sum1 += __shfl_xor_sync(0xffffffffu, sum1, 1);
        sum1 += __shfl_xor_sync(0xffffffffu, sum1, 2);
        lrow0 = lrow0 * corr0 + sum0;  mrow0 = mn0;
        lrow1 = lrow1 * corr1 + sum1;  mrow1 = mn1;
        #pragma unroll
        for (int n = 0; n < 8; n++) {
            oacc[n][0] *= corr0; oacc[n][1] *= corr0;
            oacc[n][2] *= corr1; oacc[n][3] *= corr1;
        }

        // ---- O += P @ V (3-split); V natural, B-frag via ldmatrix.trans
        #pragma unroll
        for (int kb = 0; kb < 4; kb++) {
            uint32_t pah[4], pal[4];
            hilo2(sacc[2 * kb][0],     sacc[2 * kb][1],     pah[0], pal[0]);
            hilo2(sacc[2 * kb][2],     sacc[2 * kb][3],     pah[1], pal[1]);
            hilo2(sacc[2 * kb + 1][0], sacc[2 * kb + 1][1], pah[2], pal[2]);
            hilo2(sacc[2 * kb + 1][2], sacc[2 * kb + 1][3], pah[3], pal[3]);
            #pragma unroll
            for (int np = 0; np < 4; np++) {
                // trans-ldsm: submatrix q -> rows kb*16+(q&1)*8+id8, cols np*16+(q>>1)*8
                const uint32_t av = (uint32_t)(
                    (kb * 16 + (quad & 1) * 8 + id8) * ROW2 +
                    (np * 16 + (quad >> 1) * 8) * 2);
                uint32_t h0, h1, h2, h3, l0, l1, l2, l3;
                ldsm4t(h0, h1, h2, h3, st + R_VH + av);
                ldsm4t(l0, l1, l2, l3, st + R_VL + av);
                mma_bf16(oacc[2 * np], pah[0], pah[1], pah[2], pah[3], h0, h1);
                mma_bf16(oacc[2 * np], pal[0], pal[1], pal[2], pal[3], h0, h1);
                mma_bf16(oacc[2 * np], pah[0], pah[1], pah[2], pah[3], l0, l1);
                mma_bf16(oacc[2 * np + 1], pah[0], pah[1], pah[2], pah[3], h2, h3);
                mma_bf16(oacc[2 * np + 1], pal[0], pal[1], pal[2], pal[3], h2, h3);
                mma_bf16(oacc[2 * np + 1], pah[0], pah[1], pah[2], pah[3], l2, l3);
            }
        }
        __syncthreads();   // all warps done with this stage before its reuse
    }

    // ---- Normalize + write O as bf16 hi/lo
    const float inv0 = 1.0f / lrow0;
    const float inv1 = 1.0f / lrow1;
    const int row0 = t0 + wid * 16 + (lane >> 2);
    #pragma unroll
    for (int n = 0; n < 8; n++) {
        const int dk = n * 8 + (lane & 3) * 2;
        const size_t g0 = ((size_t)(bi * cT + row0) * cH + hh) * cDK + dk;
        const size_t g1 = ((size_t)(bi * cT + row0 + 8) * cH + hh) * cDK + dk;
        uint32_t hp, lp;
        hilo2(oacc[n][0] * inv0, oacc[n][1] * inv0, hp, lp);
        *reinterpret_cast<uint32_t*>(oh + g0) = hp;
        *reinterpret_cast<uint32_t*>(ol + g0) = lp;
        hilo2(oacc[n][2] * inv1, oacc[n][3] * inv1, hp, lp);
        *reinterpret_cast<uint32_t*>(oh + g1) = hp;
        *reinterpret_cast<uint32_t*>(ol + g1) = lp;
    }
}

// ---------------------------------------------------------------------------
extern "C" void kernel_launch(void* const* d_in, const int* in_sizes, int n_in,
                              void* d_out, int out_size)
{
    const float* query = (const float*)d_in[0];
    const float* value = (const float*)d_in[1];
    const float* key   = (const float*)d_in[2];
    const float* Wq    = (const float*)d_in[3];
    const float* bq    = (const float*)d_in[4];
    const float* Wk    = (const float*)d_in[5];
    const float* bk    = (const float*)d_in[6];
    const float* Wv    = (const float*)d_in[7];
    const float* bv    = (const float*)d_in[8];
    const float* Wo    = (const float*)d_in[9];
    const float* bo    = (const float*)d_in[10];
    float* out = (float*)d_out;

    bf16 *xh, *xl, *yh, *yl, *wh, *wl;
    cudaGetSymbolAddress((void**)&xh, g_xh);
    cudaGetSymbolAddress((void**)&xl, g_xl);
    cudaGetSymbolAddress((void**)&yh, g_yh);
    cudaGetSymbolAddress((void**)&yl, g_yl);
    cudaGetSymbolAddress((void**)&wh, g_wth);
    cudaGetSymbolAddress((void**)&wl, g_wtl);

    cudaFuncSetAttribute(gemm_mma<true>,
                         cudaFuncAttributeMaxDynamicSharedMemorySize, GEMM_SMEM);
    cudaFuncSetAttribute(gemm_mma<false>,
                         cudaFuncAttributeMaxDynamicSharedMemorySize, GEMM_SMEM);

    const int XB = (int)(XSZ / 4 / 256);

    xconv<<<XB, 256>>>(query, xh, xl);
    xconv<<<XB, 256>>>(key,   xh + XSZ, xl + XSZ);
    xconv<<<XB, 256>>>(value, xh + 2 * XSZ, xl + 2 * XSZ);
    wconv<<<dim3(32, 32, 4), dim3(32, 8)>>>(Wq, Wk, Wv, Wo, wh, wl);

    gemm_mma<true><<<dim3(cHD / 128, cMT / 128, 3), 256, GEMM_SMEM>>>(
        xh, xl, wh, wl, bq, bk, bv, nullptr, yh, yl, 0.125f);

    attn_mma<<<dim3(cT / 128, cH, cB), 256>>>(
        yh, yl, yh + XSZ, yl + XSZ, yh + 2 * XSZ, yl + 2 * XSZ, xh, xl);

    gemm_mma<false><<<dim3(cD / 128, cMT / 128, 1), 256, GEMM_SMEM>>>(
        xh, xl, wh + 3 * WSZ, wl + 3 * WSZ, bo, bo, bo, out, nullptr, nullptr, 1.0f);
}

// round 9
// speedup vs baseline: 3.7369x; 1.0380x over previous
#include <cuda_runtime.h>
#include <cuda_bf16.h>
#include <math.h>
#include <cstdint>

// Problem constants
constexpr int cB = 2, cT = 2048, cS = 2048, cD = 1024, cH = 16, cDK = 64;
constexpr int cHD = cH * cDK;      // 1024
constexpr int cMT = cB * cT;       // 4096
constexpr size_t XSZ = (size_t)cMT * cD;    // per slot
constexpr size_t WSZ = (size_t)cD * cHD;    // per weight

using bf16 = __nv_bfloat16;

// ---- helpers ----
__device__ __forceinline__ uint32_t smem_u32(const void* p) {
    uint32_t a;
    asm("{ .reg .u64 t; cvta.to.shared.u64 t, %1; cvt.u32.u64 %0, t; }"
        : "=r"(a) : "l"(p));
    return a;
}
__device__ __forceinline__ void ldsm4(uint32_t& r0, uint32_t& r1,
                                      uint32_t& r2, uint32_t& r3, uint32_t a) {
    asm volatile("ldmatrix.sync.aligned.m8n8.x4.shared.b16 {%0,%1,%2,%3}, [%4];"
                 : "=r"(r0), "=r"(r1), "=r"(r2), "=r"(r3) : "r"(a));
}
__device__ __forceinline__ void ldsm4t(uint32_t& r0, uint32_t& r1,
                                       uint32_t& r2, uint32_t& r3, uint32_t a) {
    asm volatile("ldmatrix.sync.aligned.m8n8.x4.trans.shared.b16 {%0,%1,%2,%3}, [%4];"
                 : "=r"(r0), "=r"(r1), "=r"(r2), "=r"(r3) : "r"(a));
}
__device__ __forceinline__ void mma_bf16(float c[4],
    uint32_t a0, uint32_t a1, uint32_t a2, uint32_t a3,
    uint32_t b0, uint32_t b1) {
    asm volatile("mma.sync.aligned.m16n8k16.row.col.f32.bf16.bf16.f32 "
                 "{%0,%1,%2,%3}, {%4,%5,%6,%7}, {%8,%9}, {%0,%1,%2,%3};"
                 : "+f"(c[0]), "+f"(c[1]), "+f"(c[2]), "+f"(c[3])
                 : "r"(a0), "r"(a1), "r"(a2), "r"(a3), "r"(b0), "r"(b1));
}
__device__ __forceinline__ void cp16(uint32_t dst, const void* src) {
    asm volatile("cp.async.cg.shared.global [%0], [%1], 16;"
                 :: "r"(dst), "l"(src));
}
#define CP_COMMIT() asm volatile("cp.async.commit_group;")
#define CP_WAIT(n)  asm volatile("cp.async.wait_group %0;" :: "n"(n))

// fast exp2
__device__ __forceinline__ float ex2(float x) {
    float r; asm("ex2.approx.ftz.f32 %0, %1;" : "=f"(r) : "f"(x));
    return r;
}

// pack two fp32 -> bf16x2 (lo-half = first arg)
__device__ __forceinline__ uint32_t packbf(float lo, float hi) {
    uint32_t r;
    asm("cvt.rn.bf16x2.f32 %0, %1, %2;" : "=r"(r) : "f"(hi), "f"(lo));
    return r;
}
__device__ __forceinline__ void hilo2(float x, float y,
                                      uint32_t& h, uint32_t& l) {
    h = packbf(x, y);
    const float hx = __uint_as_float(h << 16);
    const float hy = __uint_as_float(h & 0xffff0000u);
    l = packbf(x - hx, y - hy);
}

// ---- Scratch ----
__device__ bf16 g_xh[3 * XSZ];
__device__ bf16 g_xl[3 * XSZ];
__device__ bf16 g_yh[3 * XSZ];
__device__ bf16 g_yl[3 * XSZ];
__device__ bf16 g_wth[4 * WSZ];
__device__ bf16 g_wtl[4 * WSZ];

// ---------------------------------------------------------------------------
// fp32 -> bf16 hi/lo split (3 inputs fused via grid.z)
// ---------------------------------------------------------------------------
__global__ __launch_bounds__(256) void xconv3(
    const float* __restrict__ X0, const float* __restrict__ X1,
    const float* __restrict__ X2, bf16* __restrict__ xh, bf16* __restrict__ xl)
{
    const int z = blockIdx.z;
    const float* X = (z == 0) ? X0 : (z == 1) ? X1 : X2;
    const size_t i4 = ((size_t)blockIdx.x * 256 + threadIdx.x) * 4;
    const float4 v = *reinterpret_cast<const float4*>(X + i4);
    uint32_t h0, l0, h1, l1;
    hilo2(v.x, v.y, h0, l0);
    hilo2(v.z, v.w, h1, l1);
    const size_t o = (size_t)z * XSZ + i4;
    *reinterpret_cast<uint2*>(xh + o) = make_uint2(h0, h1);
    *reinterpret_cast<uint2*>(xl + o) = make_uint2(l0, l1);
}

// ---------------------------------------------------------------------------
// W[K,N] fp32 -> W^T[N,K] bf16 hi/lo
// ---------------------------------------------------------------------------
__global__ __launch_bounds__(256) void wconv(
    const float* __restrict__ W0, const float* __restrict__ W1,
    const float* __restrict__ W2, const float* __restrict__ W3,
    bf16* __restrict__ wh, bf16* __restrict__ wl)
{
    __shared__ float t[32][33];
    const int z = blockIdx.z;
    const float* W = (z == 0) ? W0 : (z == 1) ? W1 : (z == 2) ? W2 : W3;
    const int n0 = blockIdx.x * 32, k0 = blockIdx.y * 32;
    const int tx = threadIdx.x, ty = threadIdx.y;
    #pragma unroll
    for (int i = 0; i < 4; i++)
        t[ty + 8 * i][tx] = W[(size_t)(k0 + ty + 8 * i) * cHD + n0 + tx];
    __syncthreads();
    const size_t zb = (size_t)z * WSZ;
    #pragma unroll
    for (int i = 0; i < 4; i++) {
        const float v = t[tx][ty + 8 * i];
        const bf16 h = __float2bfloat16(v);
        const bf16 l = __float2bfloat16(v - __bfloat162float(h));
        const size_t o = zb + (size_t)(n0 + ty + 8 * i) * cD + k0 + tx;
        wh[o] = h; wl[o] = l;
    }
}

// ---------------------------------------------------------------------------
// mma.sync split-bf16 GEMM (verified round 5-7, unchanged).
// ---------------------------------------------------------------------------
constexpr int ROWB = 80;
constexpr int TILE_B = 128 * ROWB;
constexpr int STAGE_B = 4 * TILE_B;
constexpr int GEMM_SMEM = 2 * STAGE_B;   // 81920

template <bool BF16OUT>
__global__ __launch_bounds__(256, 2) void gemm_mma(
    const bf16* __restrict__ Xh, const bf16* __restrict__ Xl,
    const bf16* __restrict__ Wh, const bf16* __restrict__ Wl,
    const float* b0, const float* b1, const float* b2,
    float* oF, bf16* oh, bf16* ol, float scale0)
{
    extern __shared__ char dynsm[];
    const uint32_t sb = smem_u32(dynsm);
    const int tid = threadIdx.x;
    const int wid = tid >> 5;
    const int lane = tid & 31;
    const int z = blockIdx.z;
    const int m0 = blockIdx.y * 128;
    const int n0 = blockIdx.x * 128;
    const int wm = wid & 1;
    const int wn = wid >> 1;

    const bf16* Ah = Xh + (size_t)z * XSZ;
    const bf16* Al = Xl + (size_t)z * XSZ;
    const bf16* Bh = Wh + (size_t)z * WSZ;
    const bf16* Bl = Wl + (size_t)z * WSZ;
    const float* bias = (z == 0) ? b0 : (z == 1) ? b1 : b2;
    const float scale = (z == 0) ? scale0 : 1.0f;

    float acc[4][4][4] = {};

    const int lr0 = tid >> 2, lc = (tid & 3);
    const uint32_t so0 = (uint32_t)(lr0 * ROWB + lc * 16);
    const uint32_t so1 = (uint32_t)((lr0 + 64) * ROWB + lc * 16);

    auto load_stage = [&](int chunk, int stage) {
        const uint32_t s0 = sb + stage * STAGE_B;
        const int k0 = chunk * 32;
        const size_t ga0 = (size_t)(m0 + lr0) * cD + k0 + lc * 8;
        const size_t ga1 = (size_t)(m0 + lr0 + 64) * cD + k0 + lc * 8;
        const size_t gb0 = (size_t)(n0 + lr0) * cD + k0 + lc * 8;
        const size_t gb1 = (size_t)(n0 + lr0 + 64) * cD + k0 + lc * 8;
        cp16(s0 + so0,              Ah + ga0);
        cp16(s0 + so1,              Ah + ga1);
        cp16(s0 + TILE_B + so0,     Al + ga0);
        cp16(s0 + TILE_B + so1,     Al + ga1);
        cp16(s0 + 2 * TILE_B + so0, Bh + gb0);
        cp16(s0 + 2 * TILE_B + so1, Bh + gb1);
        cp16(s0 + 3 * TILE_B + so0, Bl + gb0);
        cp16(s0 + 3 * TILE_B + so1, Bl + gb1);
        CP_COMMIT();
    };

    load_stage(0, 0);
    const int NCH = cD / 32;
    for (int ch = 0; ch < NCH; ch++) {
        if (ch + 1 < NCH) { load_stage(ch + 1, (ch + 1) & 1); CP_WAIT(1); }
        else              { CP_WAIT(0); }
        __syncthreads();
        const uint32_t s0 = sb + (ch & 1) * STAGE_B;

        #pragma unroll
        for (int sp = 0; sp < 3; sp++) {
            const uint32_t ab = s0 + ((sp == 1) ? TILE_B : 0);
            const uint32_t bb = s0 + ((sp == 2) ? 3 * TILE_B : 2 * TILE_B);
            #pragma unroll
            for (int ks = 0; ks < 2; ks++) {
                uint32_t af[4][4];
                #pragma unroll
                for (int mi = 0; mi < 4; mi++) {
                    const int row = wm * 64 + mi * 16 + (lane & 15);
                    const int col = ks * 16 + ((lane >> 4) << 3);
                    ldsm4(af[mi][0], af[mi][1], af[mi][2], af[mi][3],
                          ab + (uint32_t)(row * ROWB + col * 2));
                }
                uint32_t bf[4][2];
                #pragma unroll
                for (int np = 0; np < 2; np++) {
                    const int nrow = wn * 32 + np * 16 + (lane & 7) + ((lane >> 4) << 3);
                    const int col = ks * 16 + (((lane >> 3) & 1) << 3);
                    uint32_t r0, r1, r2, r3;
                    ldsm4(r0, r1, r2, r3, bb + (uint32_t)(nrow * ROWB + col * 2));
                    bf[2 * np][0] = r0;     bf[2 * np][1] = r1;
                    bf[2 * np + 1][0] = r2; bf[2 * np + 1][1] = r3;
                }
                #pragma unroll
                for (int mi = 0; mi < 4; mi++)
                    #pragma unroll
                    for (int ni = 0; ni < 4; ni++)
                        mma_bf16(acc[mi][ni], af[mi][0], af[mi][1],
                                 af[mi][2], af[mi][3], bf[ni][0], bf[ni][1]);
            }
        }
        __syncthreads();
    }

    #pragma unroll
    for (int mi = 0; mi < 4; mi++) {
        #pragma unroll
        for (int h = 0; h < 2; h++) {
            const int row = m0 + wm * 64 + mi * 16 + h * 8 + (lane >> 2);
            #pragma unroll
            for (int ni = 0; ni < 4; ni++) {
                const int col = n0 + wn * 32 + ni * 8 + (lane & 3) * 2;
                const float2 bb = *reinterpret_cast<const float2*>(bias + col);
                const float v0 = (acc[mi][ni][h * 2 + 0] + bb.x) * scale;
                const float v1 = (acc[mi][ni][h * 2 + 1] + bb.y) * scale;
                if (BF16OUT) {
                    uint32_t hp, lp;
                    hilo2(v0, v1, hp, lp);
                    const size_t o = (size_t)z * XSZ + (size_t)row * 1024 + col;
                    *reinterpret_cast<uint32_t*>(oh + o) = hp;
                    *reinterpret_cast<uint32_t*>(ol + o) = lp;
                } else {
                    *reinterpret_cast<float2*>(oF + (size_t)row * 1024 + col) =
                        make_float2(v0, v1);
                }
            }
        }
    }
}

// ---------------------------------------------------------------------------
// Tensor-core flash attention v3:
//   - Q-lo fragments evicted to a persistent smem region (reg-pressure fix)
//   - exp2-domain softmax (log2e folded into Q-projection scale)
//   - K/V double-buffered cp.async; V via ldmatrix.trans (round 7)
// ---------------------------------------------------------------------------
constexpr int ROW2 = 144;
constexpr int R_KH = 0;
constexpr int R_KL = 64 * ROW2;
constexpr int R_VH = 2 * 64 * ROW2;
constexpr int R_VL = 3 * 64 * ROW2;
constexpr int STG2 = 4 * 64 * ROW2;          // 36864 per stage
constexpr int QLO  = 2 * STG2;               // persistent Q-lo (128 x ROW2)
constexpr int ATTN_SMEM = QLO + 128 * ROW2;  // 92160

__global__ __launch_bounds__(256, 2) void attn_mma(
    const bf16* __restrict__ qh, const bf16* __restrict__ ql,
    const bf16* __restrict__ kh, const bf16* __restrict__ kl,
    const bf16* __restrict__ vh, const bf16* __restrict__ vl,
    bf16* __restrict__ oh, bf16* __restrict__ ol)
{
    __shared__ __align__(16) unsigned char smb[ATTN_SMEM];
    const uint32_t sb = smem_u32(smb);
    const int tid = threadIdx.x;
    const int wid = tid >> 5;
    const int lane = tid & 31;
    const int t0 = blockIdx.x * 128;
    const int hh = blockIdx.y;
    const int bi = blockIdx.z;

    // ---- Q: hi staged in stage0 (transient), lo in persistent QLO region
    #pragma unroll
    for (int it = 0; it < 4; it++) {
        const int i = tid + it * 256;
        const int r = i >> 3, c = i & 7;
        const size_t g = ((size_t)(bi * cT + t0 + r) * cH + hh) * cDK + c * 8;
        *reinterpret_cast<uint4*>(smb + r * ROW2 + c * 16) =
            *reinterpret_cast<const uint4*>(qh + g);
        *reinterpret_cast<uint4*>(smb + QLO + r * ROW2 + c * 16) =
            *reinterpret_cast<const uint4*>(ql + g);
    }
    __syncthreads();

    uint32_t qfh[4][4];                       // Q-hi stays in registers
    #pragma unroll
    for (int kb = 0; kb < 4; kb++) {
        const int row = wid * 16 + (lane & 15);
        const int col = kb * 16 + ((lane >> 4) << 3);
        ldsm4(qfh[kb][0], qfh[kb][1], qfh[kb][2], qfh[kb][3],
              sb + (uint32_t)(row * ROW2 + col * 2));
    }
    __syncthreads();   // stage0 free for K/V

    const int lr = tid >> 3, lc8 = (tid & 7);
    auto load_kv = [&](int s0, int stage) {
        const uint32_t st = sb + stage * STG2;
        #pragma unroll
        for (int it = 0; it < 2; it++) {
            const int r = lr + it * 32;
            const uint32_t so = (uint32_t)(r * ROW2 + lc8 * 16);
            const size_t g = ((size_t)(bi * cS + s0 + r) * cH + hh) * cDK + lc8 * 8;
            cp16(st + R_KH + so, kh + g);
            cp16(st + R_KL + so, kl + g);
            cp16(st + R_VH + so, vh + g);
            cp16(st + R_VL + so, vl + g);
        }
        CP_COMMIT();
    };

    float oacc[8][4] = {};
    float mrow0 = -INFINITY, mrow1 = -INFINITY;
    float lrow0 = 0.0f, lrow1 = 0.0f;

    const int quad = lane >> 3, id8 = lane & 7;
    const int qrow = wid * 16 + (lane & 15);
    constexpr int NT = cS / 64;
    load_kv(0, 0);

    for (int ch = 0; ch < NT; ch++) {
        if (ch + 1 < NT) { load_kv((ch + 1) * 64, (ch + 1) & 1); CP_WAIT(1); }
        else             { CP_WAIT(0); }
        __syncthreads();
        const uint32_t st = sb + (ch & 1) * STG2;

        // ---- S = Q @ K^T (3-split); Q-lo frag reloaded from smem per kb
        float sacc[8][4] = {};
        #pragma unroll
        for (int kb = 0; kb < 4; kb++) {
            uint32_t ql0, ql1, ql2, ql3;
            {
                const int col = kb * 16 + ((lane >> 4) << 3);
                ldsm4(ql0, ql1, ql2, ql3,
                      sb + (uint32_t)(QLO + qrow * ROW2 + col * 2));
            }
            #pragma unroll
            for (int np = 0; np < 4; np++) {
                const int nrow = np * 16 + (lane & 7) + ((lane >> 4) << 3);
                const int col = kb * 16 + (((lane >> 3) & 1) << 3);
                uint32_t h0, h1, h2, h3, l0, l1, l2, l3;
                ldsm4(h0, h1, h2, h3, st + (uint32_t)(R_KH + nrow * ROW2 + col * 2));
                ldsm4(l0, l1, l2, l3, st + (uint32_t)(R_KL + nrow * ROW2 + col * 2));
                mma_bf16(sacc[2 * np], qfh[kb][0], qfh[kb][1], qfh[kb][2], qfh[kb][3], h0, h1);
                mma_bf16(sacc[2 * np], ql0, ql1, ql2, ql3, h0, h1);
                mma_bf16(sacc[2 * np], qfh[kb][0], qfh[kb][1], qfh[kb][2], qfh[kb][3], l0, l1);
                mma_bf16(sacc[2 * np + 1], qfh[kb][0], qfh[kb][1], qfh[kb][2], qfh[kb][3], h2, h3);
                mma_bf16(sacc[2 * np + 1], ql0, ql1, ql2, ql3, h2, h3);
                mma_bf16(sacc[2 * np + 1], qfh[kb][0], qfh[kb][1], qfh[kb][2], qfh[kb][3], l2, l3);
            }
        }

        // ---- Online softmax in exp2 domain (log2e pre-folded into Q scale)
        float mx0 = -INFINITY, mx1 = -INFINITY;
        #pragma unroll
        for (int n = 0; n < 8; n++) {
            mx0 = fmaxf(mx0, fmaxf(sacc[n][0], sacc[n][1]));
            mx1 = fmaxf(mx1, fmaxf(sacc[n][2], sacc[n][3]));
        }
        mx0 = fmaxf(mx0, __shfl_xor_sync(0xffffffffu, mx0, 1));
        mx0 = fmaxf(mx0, __shfl_xor_sync(0xffffffffu, mx0, 2));
        mx1 = fmaxf(mx1, __shfl_xor_sync(0xffffffffu, mx1, 1));
        mx1 = fmaxf(mx1, __shfl_xor_sync(0xffffffffu, mx1, 2));
        const float mn0 = fmaxf(mrow0, mx0);
        const float mn1 = fmaxf(mrow1, mx1);
        const float corr0 = ex2(mrow0 - mn0);
        const float corr1 = ex2(mrow1 - mn1);
        float sum0 = 0.0f, sum1 = 0.0f;
        #pragma unroll
        for (int n = 0; n < 8; n++) {
            sacc[n][0] = ex2(sacc[n][0] - mn0);
            sacc[n][1] = ex2(sacc[n][1] - mn0);
            sacc[n][2] = ex2(sacc[n][2] - mn1);
            sacc[n][3] = ex2(sacc[n][3] - mn1);
            sum0 += sacc[n][0] + sacc[n][1];
            sum1 += sacc[n][2] + sacc[n][3];
        }
        sum0 += __shfl_xor_sync(0xffffffffu, sum0, 1);
        sum0 += __shfl_xor_sync(0xffffffffu, sum0, 2);
        sum1 += __shfl_xor_sync(0xffffffffu, sum1, 1);
        sum1 += __shfl_xor_sync(0xffffffffu, sum1, 2);
        lrow0 = lrow0 * corr0 + sum0;  mrow0 = mn0;
        lrow1 = lrow1 * corr1 + sum1;  mrow1 = mn1;
        #pragma unroll
        for (int n = 0; n < 8; n++) {
            oacc[n][0] *= corr0; oacc[n][1] *= corr0;
            oacc[n][2] *= corr1; oacc[n][3] *= corr1;
        }

        // ---- O += P @ V (3-split); V natural, B-frag via ldmatrix.trans
        #pragma unroll
        for (int kb = 0; kb < 4; kb++) {
            uint32_t pah[4], pal[4];
            hilo2(sacc[2 * kb][0],     sacc[2 * kb][1],     pah[0], pal[0]);
            hilo2(sacc[2 * kb][2],     sacc[2 * kb][3],     pah[1], pal[1]);
            hilo2(sacc[2 * kb + 1][0], sacc[2 * kb + 1][1], pah[2], pal[2]);
            hilo2(sacc[2 * kb + 1][2], sacc[2 * kb + 1][3], pah[3], pal[3]);
            #pragma unroll
            for (int np = 0; np < 4; np++) {
                const uint32_t av = (uint32_t)(
                    (kb * 16 + (quad & 1) * 8 + id8) * ROW2 +
                    (np * 16 + (quad >> 1) * 8) * 2);
                uint32_t h0, h1, h2, h3, l0, l1, l2, l3;
                ldsm4t(h0, h1, h2, h3, st + R_VH + av);
                ldsm4t(l0, l1, l2, l3, st + R_VL + av);
                mma_bf16(oacc[2 * np], pah[0], pah[1], pah[2], pah[3], h0, h1);
                mma_bf16(oacc[2 * np], pal[0], pal[1], pal[2], pal[3], h0, h1);
                mma_bf16(oacc[2 * np], pah[0], pah[1], pah[2], pah[3], l0, l1);
                mma_bf16(oacc[2 * np + 1], pah[0], pah[1], pah[2], pah[3], h2, h3);
                mma_bf16(oacc[2 * np + 1], pal[0], pal[1], pal[2], pal[3], h2, h3);
                mma_bf16(oacc[2 * np + 1], pah[0], pah[1], pah[2], pah[3], l2, l3);
            }
        }
        __syncthreads();
    }

    // ---- Normalize + write O as bf16 hi/lo
    const float inv0 = 1.0f / lrow0;
    const float inv1 = 1.0f / lrow1;
    const int row0 = t0 + wid * 16 + (lane >> 2);
    #pragma unroll
    for (int n = 0; n < 8; n++) {
        const int dk = n * 8 + (lane & 3) * 2;
        const size_t g0 = ((size_t)(bi * cT + row0) * cH + hh) * cDK + dk;
        const size_t g1 = ((size_t)(bi * cT + row0 + 8) * cH + hh) * cDK + dk;
        uint32_t hp, lp;
        hilo2(oacc[n][0] * inv0, oacc[n][1] * inv0, hp, lp);
        *reinterpret_cast<uint32_t*>(oh + g0) = hp;
        *reinterpret_cast<uint32_t*>(ol + g0) = lp;
        hilo2(oacc[n][2] * inv1, oacc[n][3] * inv1, hp, lp);
        *reinterpret_cast<uint32_t*>(oh + g1) = hp;
        *reinterpret_cast<uint32_t*>(ol + g1) = lp;
    }
}

// ---------------------------------------------------------------------------
extern "C" void kernel_launch(void* const* d_in, const int* in_sizes, int n_in,
                              void* d_out, int out_size)
{
    const float* query = (const float*)d_in[0];
    const float* value = (const float*)d_in[1];
    const float* key   = (const float*)d_in[2];
    const float* Wq    = (const float*)d_in[3];
    const float* bq    = (const float*)d_in[4];
    const float* Wk    = (const float*)d_in[5];
    const float* bk    = (const float*)d_in[6];
    const float* Wv    = (const float*)d_in[7];
    const float* bv    = (const float*)d_in[8];
    const float* Wo    = (const float*)d_in[9];
    const float* bo    = (const float*)d_in[10];
    float* out = (float*)d_out;

    bf16 *xh, *xl, *yh, *yl, *wh, *wl;
    cudaGetSymbolAddress((void**)&xh, g_xh);
    cudaGetSymbolAddress((void**)&xl, g_xl);
    cudaGetSymbolAddress((void**)&yh, g_yh);
    cudaGetSymbolAddress((void**)&yl, g_yl);
    cudaGetSymbolAddress((void**)&wh, g_wth);
    cudaGetSymbolAddress((void**)&wl, g_wtl);

    cudaFuncSetAttribute(gemm_mma<true>,
                         cudaFuncAttributeMaxDynamicSharedMemorySize, GEMM_SMEM);
    cudaFuncSetAttribute(gemm_mma<false>,
                         cudaFuncAttributeMaxDynamicSharedMemorySize, GEMM_SMEM);

    const int XB = (int)(XSZ / 4 / 256);

    // converts (query->slot0, key->slot1, value->slot2) + weight transposes
    xconv3<<<dim3(XB, 1, 3), 256>>>(query, key, value, xh, xl);
    wconv<<<dim3(32, 32, 4), dim3(32, 8)>>>(Wq, Wk, Wv, Wo, wh, wl);

    // Q/K/V projections; Q additionally scaled by 1/sqrt(DK) * log2(e)
    const float qscale = 0.125f * 1.44269504088896340736f;
    gemm_mma<true><<<dim3(cHD / 128, cMT / 128, 3), 256, GEMM_SMEM>>>(
        xh, xl, wh, wl, bq, bk, bv, nullptr, yh, yl, qscale);

    attn_mma<<<dim3(cT / 128, cH, cB), 256>>>(
        yh, yl, yh + XSZ, yl + XSZ, yh + 2 * XSZ, yl + 2 * XSZ, xh, xl);

    gemm_mma<false><<<dim3(cD / 128, cMT / 128, 1), 256, GEMM_SMEM>>>(
        xh, xl, wh + 3 * WSZ, wl + 3 * WSZ, bo, bo, bo, out, nullptr, nullptr, 1.0f);
}

// round 10
// speedup vs baseline: 4.5981x; 1.2304x over previous
#include <cuda_runtime.h>
#include <cuda_fp16.h>
#include <math.h>
#include <cstdint>

// Problem constants
constexpr int cB = 2, cT = 2048, cS = 2048, cD = 1024, cH = 16, cDK = 64;
constexpr int cHD = cH * cDK;      // 1024
constexpr int cMT = cB * cT;       // 4096
constexpr size_t XSZ = (size_t)cMT * cD;
constexpr size_t WSZ = (size_t)cD * cHD;

using f16 = __half;

// ---- helpers ----
__device__ __forceinline__ uint32_t smem_u32(const void* p) {
    uint32_t a;
    asm("{ .reg .u64 t; cvta.to.shared.u64 t, %1; cvt.u32.u64 %0, t; }"
        : "=r"(a) : "l"(p));
    return a;
}
__device__ __forceinline__ void ldsm4(uint32_t& r0, uint32_t& r1,
                                      uint32_t& r2, uint32_t& r3, uint32_t a) {
    asm volatile("ldmatrix.sync.aligned.m8n8.x4.shared.b16 {%0,%1,%2,%3}, [%4];"
                 : "=r"(r0), "=r"(r1), "=r"(r2), "=r"(r3) : "r"(a));
}
__device__ __forceinline__ void ldsm4t(uint32_t& r0, uint32_t& r1,
                                       uint32_t& r2, uint32_t& r3, uint32_t a) {
    asm volatile("ldmatrix.sync.aligned.m8n8.x4.trans.shared.b16 {%0,%1,%2,%3}, [%4];"
                 : "=r"(r0), "=r"(r1), "=r"(r2), "=r"(r3) : "r"(a));
}
__device__ __forceinline__ void mma_f16(float c[4],
    uint32_t a0, uint32_t a1, uint32_t a2, uint32_t a3,
    uint32_t b0, uint32_t b1) {
    asm volatile("mma.sync.aligned.m16n8k16.row.col.f32.f16.f16.f32 "
                 "{%0,%1,%2,%3}, {%4,%5,%6,%7}, {%8,%9}, {%0,%1,%2,%3};"
                 : "+f"(c[0]), "+f"(c[1]), "+f"(c[2]), "+f"(c[3])
                 : "r"(a0), "r"(a1), "r"(a2), "r"(a3), "r"(b0), "r"(b1));
}
__device__ __forceinline__ void cp16(uint32_t dst, const void* src) {
    asm volatile("cp.async.cg.shared.global [%0], [%1], 16;"
                 :: "r"(dst), "l"(src));
}
#define CP_COMMIT() asm volatile("cp.async.commit_group;")
#define CP_WAIT(n)  asm volatile("cp.async.wait_group %0;" :: "n"(n))

__device__ __forceinline__ float ex2(float x) {
    float r; asm("ex2.approx.ftz.f32 %0, %1;" : "=f"(r) : "f"(x));
    return r;
}

// fp32 pair -> fp16 hi/lo packed pairs
__device__ __forceinline__ void hilo2h(float x, float y,
                                       uint32_t& h, uint32_t& l) {
    __half2 hh = __floats2half2_rn(x, y);
    float2 hf = __half22float2(hh);
    __half2 ll = __floats2half2_rn(x - hf.x, y - hf.y);
    h = *reinterpret_cast<uint32_t*>(&hh);
    l = *reinterpret_cast<uint32_t*>(&ll);
}

// ---- Scratch ----
__device__ f16 g_xh[3 * XSZ];
__device__ f16 g_xl[3 * XSZ];
__device__ f16 g_yh[3 * XSZ];
__device__ f16 g_yl[XSZ];          // only Q needs a lo plane
__device__ f16 g_wth[4 * WSZ];
__device__ f16 g_wtl[4 * WSZ];

// ---------------------------------------------------------------------------
// fp32 -> fp16 hi/lo split (3 inputs fused)
// ---------------------------------------------------------------------------
__global__ __launch_bounds__(256) void xconv3(
    const float* __restrict__ X0, const float* __restrict__ X1,
    const float* __restrict__ X2, f16* __restrict__ xh, f16* __restrict__ xl)
{
    const int z = blockIdx.z;
    const float* X = (z == 0) ? X0 : (z == 1) ? X1 : X2;
    const size_t i4 = ((size_t)blockIdx.x * 256 + threadIdx.x) * 4;
    const float4 v = *reinterpret_cast<const float4*>(X + i4);
    uint32_t h0, l0, h1, l1;
    hilo2h(v.x, v.y, h0, l0);
    hilo2h(v.z, v.w, h1, l1);
    const size_t o = (size_t)z * XSZ + i4;
    *reinterpret_cast<uint2*>(xh + o) = make_uint2(h0, h1);
    *reinterpret_cast<uint2*>(xl + o) = make_uint2(l0, l1);
}

// ---------------------------------------------------------------------------
// W[K,N] fp32 -> W^T[N,K] fp16 hi/lo
// ---------------------------------------------------------------------------
__global__ __launch_bounds__(256) void wconv(
    const float* __restrict__ W0, const float* __restrict__ W1,
    const float* __restrict__ W2, const float* __restrict__ W3,
    f16* __restrict__ wh, f16* __restrict__ wl)
{
    __shared__ float t[32][33];
    const int z = blockIdx.z;
    const float* W = (z == 0) ? W0 : (z == 1) ? W1 : (z == 2) ? W2 : W3;
    const int n0 = blockIdx.x * 32, k0 = blockIdx.y * 32;
    const int tx = threadIdx.x, ty = threadIdx.y;
    #pragma unroll
    for (int i = 0; i < 4; i++)
        t[ty + 8 * i][tx] = W[(size_t)(k0 + ty + 8 * i) * cHD + n0 + tx];
    __syncthreads();
    const size_t zb = (size_t)z * WSZ;
    #pragma unroll
    for (int i = 0; i < 4; i++) {
        const float v = t[tx][ty + 8 * i];
        const f16 h = __float2half_rn(v);
        const f16 l = __float2half_rn(v - __half2float(h));
        const size_t o = zb + (size_t)(n0 + ty + 8 * i) * cD + k0 + tx;
        wh[o] = h; wl[o] = l;
    }
}

// ---------------------------------------------------------------------------
// mma.sync split-fp16 GEMM, 3-term: D = Xh*Wh + Xh*Wl + Xl*Wh.
// Restructured inner loop: 12 ldsm + 48 MMA per k-step (A regs reused hi->lo).
// ---------------------------------------------------------------------------
constexpr int ROWB = 80;
constexpr int TILE_B = 128 * ROWB;
constexpr int STAGE_B = 4 * TILE_B;
constexpr int GEMM_SMEM = 2 * STAGE_B;   // 81920

template <bool F16OUT>
__global__ __launch_bounds__(256, 2) void gemm_mma(
    const f16* __restrict__ Xh, const f16* __restrict__ Xl,
    const f16* __restrict__ Wh, const f16* __restrict__ Wl,
    const float* b0, const float* b1, const float* b2,
    float* oF, f16* oh, f16* ol, float scale0, int lo_mask)
{
    extern __shared__ char dynsm[];
    const uint32_t sb = smem_u32(dynsm);
    const int tid = threadIdx.x;
    const int wid = tid >> 5;
    const int lane = tid & 31;
    const int z = blockIdx.z;
    const int m0 = blockIdx.y * 128;
    const int n0 = blockIdx.x * 128;
    const int wm = wid & 1;
    const int wn = wid >> 1;

    const f16* Ah = Xh + (size_t)z * XSZ;
    const f16* Al = Xl + (size_t)z * XSZ;
    const f16* Bh = Wh + (size_t)z * WSZ;
    const f16* Bl = Wl + (size_t)z * WSZ;
    const float* bias = (z == 0) ? b0 : (z == 1) ? b1 : b2;
    const float scale = (z == 0) ? scale0 : 1.0f;
    const bool write_lo = ((lo_mask >> z) & 1) != 0;

    float acc[4][4][4] = {};

    const int lr0 = tid >> 2, lc = (tid & 3);
    const uint32_t so0 = (uint32_t)(lr0 * ROWB + lc * 16);
    const uint32_t so1 = (uint32_t)((lr0 + 64) * ROWB + lc * 16);

    auto load_stage = [&](int chunk, int stage) {
        const uint32_t s0 = sb + stage * STAGE_B;
        const int k0 = chunk * 32;
        const size_t ga0 = (size_t)(m0 + lr0) * cD + k0 + lc * 8;
        const size_t ga1 = (size_t)(m0 + lr0 + 64) * cD + k0 + lc * 8;
        const size_t gb0 = (size_t)(n0 + lr0) * cD + k0 + lc * 8;
        const size_t gb1 = (size_t)(n0 + lr0 + 64) * cD + k0 + lc * 8;
        cp16(s0 + so0,              Ah + ga0);
        cp16(s0 + so1,              Ah + ga1);
        cp16(s0 + TILE_B + so0,     Al + ga0);
        cp16(s0 + TILE_B + so1,     Al + ga1);
        cp16(s0 + 2 * TILE_B + so0, Bh + gb0);
        cp16(s0 + 2 * TILE_B + so1, Bh + gb1);
        cp16(s0 + 3 * TILE_B + so0, Bl + gb0);
        cp16(s0 + 3 * TILE_B + so1, Bl + gb1);
        CP_COMMIT();
    };

    load_stage(0, 0);
    const int NCH = cD / 32;
    for (int ch = 0; ch < NCH; ch++) {
        if (ch + 1 < NCH) { load_stage(ch + 1, (ch + 1) & 1); CP_WAIT(1); }
        else              { CP_WAIT(0); }
        __syncthreads();
        const uint32_t s0 = sb + (ch & 1) * STAGE_B;

        #pragma unroll
        for (int ks = 0; ks < 2; ks++) {
            const int acol = ks * 16 + ((lane >> 4) << 3);
            const int bcol = ks * 16 + (((lane >> 3) & 1) << 3);
            const int brow0 = wn * 32 + (lane & 7) + ((lane >> 4) << 3);

            // B fragments (hi and lo) once
            uint32_t bh[4][2], bl[4][2];
            #pragma unroll
            for (int np = 0; np < 2; np++) {
                const uint32_t boff = (uint32_t)((brow0 + np * 16) * ROWB + bcol * 2);
                uint32_t r0, r1, r2, r3;
                ldsm4(r0, r1, r2, r3, s0 + 2 * TILE_B + boff);
                bh[2 * np][0] = r0;     bh[2 * np][1] = r1;
                bh[2 * np + 1][0] = r2; bh[2 * np + 1][1] = r3;
                ldsm4(r0, r1, r2, r3, s0 + 3 * TILE_B + boff);
                bl[2 * np][0] = r0;     bl[2 * np][1] = r1;
                bl[2 * np + 1][0] = r2; bl[2 * np + 1][1] = r3;
            }
            // A-hi fragments; use for both Ah*Bh and Ah*Bl
            uint32_t af[4][4];
            #pragma unroll
            for (int mi = 0; mi < 4; mi++) {
                const int row = wm * 64 + mi * 16 + (lane & 15);
                ldsm4(af[mi][0], af[mi][1], af[mi][2], af[mi][3],
                      s0 + (uint32_t)(row * ROWB + acol * 2));
            }
            #pragma unroll
            for (int mi = 0; mi < 4; mi++)
                #pragma unroll
                for (int ni = 0; ni < 4; ni++)
                    mma_f16(acc[mi][ni], af[mi][0], af[mi][1],
                            af[mi][2], af[mi][3], bh[ni][0], bh[ni][1]);
            #pragma unroll
            for (int mi = 0; mi < 4; mi++)
                #pragma unroll
                for (int ni = 0; ni < 4; ni++)
                    mma_f16(acc[mi][ni], af[mi][0], af[mi][1],
                            af[mi][2], af[mi][3], bl[ni][0], bl[ni][1]);
            // A-lo overwrites the same registers
            #pragma unroll
            for (int mi = 0; mi < 4; mi++) {
                const int row = wm * 64 + mi * 16 + (lane & 15);
                ldsm4(af[mi][0], af[mi][1], af[mi][2], af[mi][3],
                      s0 + TILE_B + (uint32_t)(row * ROWB + acol * 2));
            }
            #pragma unroll
            for (int mi = 0; mi < 4; mi++)
                #pragma unroll
                for (int ni = 0; ni < 4; ni++)
                    mma_f16(acc[mi][ni], af[mi][0], af[mi][1],
                            af[mi][2], af[mi][3], bh[ni][0], bh[ni][1]);
        }
        __syncthreads();
    }

    #pragma unroll
    for (int mi = 0; mi < 4; mi++) {
        #pragma unroll
        for (int h = 0; h < 2; h++) {
            const int row = m0 + wm * 64 + mi * 16 + h * 8 + (lane >> 2);
            #pragma unroll
            for (int ni = 0; ni < 4; ni++) {
                const int col = n0 + wn * 32 + ni * 8 + (lane & 3) * 2;
                const float2 bb = *reinterpret_cast<const float2*>(bias + col);
                const float v0 = (acc[mi][ni][h * 2 + 0] + bb.x) * scale;
                const float v1 = (acc[mi][ni][h * 2 + 1] + bb.y) * scale;
                if (F16OUT) {
                    uint32_t hp, lp;
                    hilo2h(v0, v1, hp, lp);
                    const size_t o = (size_t)z * XSZ + (size_t)row * 1024 + col;
                    *reinterpret_cast<uint32_t*>(oh + o) = hp;
                    if (write_lo)
                        *reinterpret_cast<uint32_t*>(ol + (size_t)row * 1024 + col) = lp;
                } else {
                    *reinterpret_cast<float2*>(oF + (size_t)row * 1024 + col) =
                        make_float2(v0, v1);
                }
            }
        }
    }
}

// ---------------------------------------------------------------------------
// fp16 2-term flash attention:
//   S = Qh*Kh + Ql*Kh   (K-lo dropped);  O = Ph*Vh + Pl*Vh  (V-lo dropped)
//   4-stage cp.async K/V pipeline, ONE barrier per tile; Q-lo in smem.
// ---------------------------------------------------------------------------
constexpr int ROW2 = 144;
constexpr int R_KH = 0;                      // K hi (64 x ROW2)
constexpr int R_VH = 64 * ROW2;              // V hi (natural [s][dk])
constexpr int STG2 = 2 * 64 * ROW2;          // 18432 per stage
constexpr int QLO  = 4 * STG2;               // 73728: persistent Q-lo
constexpr int ATTN_SMEM = QLO + 128 * ROW2;  // 92160

__global__ __launch_bounds__(256, 2) void attn_mma(
    const f16* __restrict__ qh, const f16* __restrict__ ql,
    const f16* __restrict__ kh, const f16* __restrict__ vh,
    f16* __restrict__ oh, f16* __restrict__ ol)
{
    __shared__ __align__(16) unsigned char smb[ATTN_SMEM];
    const uint32_t sb = smem_u32(smb);
    const int tid = threadIdx.x;
    const int wid = tid >> 5;
    const int lane = tid & 31;
    const int t0 = blockIdx.x * 128;
    const int hh = blockIdx.y;
    const int bi = blockIdx.z;

    // ---- Q: hi staged transiently in stage area, lo into persistent QLO
    #pragma unroll
    for (int it = 0; it < 4; it++) {
        const int i = tid + it * 256;
        const int r = i >> 3, c = i & 7;
        const size_t g = ((size_t)(bi * cT + t0 + r) * cH + hh) * cDK + c * 8;
        *reinterpret_cast<uint4*>(smb + r * ROW2 + c * 16) =
            *reinterpret_cast<const uint4*>(qh + g);
        *reinterpret_cast<uint4*>(smb + QLO + r * ROW2 + c * 16) =
            *reinterpret_cast<const uint4*>(ql + g);
    }
    __syncthreads();

    uint32_t qfh[4][4];
    #pragma unroll
    for (int kb = 0; kb < 4; kb++) {
        const int row = wid * 16 + (lane & 15);
        const int col = kb * 16 + ((lane >> 4) << 3);
        ldsm4(qfh[kb][0], qfh[kb][1], qfh[kb][2], qfh[kb][3],
              sb + (uint32_t)(row * ROW2 + col * 2));
    }
    __syncthreads();   // stage area free for K/V

    const int lr = tid >> 3, lc8 = (tid & 7);
    auto load_kv = [&](int s0, int stage) {
        const uint32_t st = sb + stage * STG2;
        #pragma unroll
        for (int it = 0; it < 2; it++) {
            const int r = lr + it * 32;
            const uint32_t so = (uint32_t)(r * ROW2 + lc8 * 16);
            const size_t g = ((size_t)(bi * cS + s0 + r) * cH + hh) * cDK + lc8 * 8;
            cp16(st + R_KH + so, kh + g);
            cp16(st + R_VH + so, vh + g);
        }
        CP_COMMIT();
    };

    float oacc[8][4] = {};
    float mrow0 = -INFINITY, mrow1 = -INFINITY;
    float lrow0 = 0.0f, lrow1 = 0.0f;

    const int quad = lane >> 3, id8 = lane & 7;
    const int qrow = wid * 16 + (lane & 15);
    constexpr int NT = cS / 64;

    load_kv(0, 0);
    load_kv(64, 1);
    load_kv(128, 2);

    for (int ch = 0; ch < NT; ch++) {
        CP_WAIT(2);
        __syncthreads();
        const uint32_t st = sb + (ch & 3) * STG2;

        // ---- S = Qh*Kh + Ql*Kh
        float sacc[8][4] = {};
        #pragma unroll
        for (int kb = 0; kb < 4; kb++) {
            uint32_t ql0, ql1, ql2, ql3;
            {
                const int col = kb * 16 + ((lane >> 4) << 3);
                ldsm4(ql0, ql1, ql2, ql3,
                      sb + (uint32_t)(QLO + qrow * ROW2 + col * 2));
            }
            #pragma unroll
            for (int np = 0; np < 4; np++) {
                const int nrow = np * 16 + (lane & 7) + ((lane >> 4) << 3);
                const int col = kb * 16 + (((lane >> 3) & 1) << 3);
                uint32_t h0, h1, h2, h3;
                ldsm4(h0, h1, h2, h3, st + (uint32_t)(R_KH + nrow * ROW2 + col * 2));
                mma_f16(sacc[2 * np], qfh[kb][0], qfh[kb][1], qfh[kb][2], qfh[kb][3], h0, h1);
                mma_f16(sacc[2 * np], ql0, ql1, ql2, ql3, h0, h1);
                mma_f16(sacc[2 * np + 1], qfh[kb][0], qfh[kb][1], qfh[kb][2], qfh[kb][3], h2, h3);
                mma_f16(sacc[2 * np + 1], ql0, ql1, ql2, ql3, h2, h3);
            }
        }

        // ---- Online softmax (exp2 domain; log2e folded into Q scale)
        float mx0 = -INFINITY, mx1 = -INFINITY;
        #pragma unroll
        for (int n = 0; n < 8; n++) {
            mx0 = fmaxf(mx0, fmaxf(sacc[n][0], sacc[n][1]));
            mx1 = fmaxf(mx1, fmaxf(sacc[n][2], sacc[n][3]));
        }
        mx0 = fmaxf(mx0, __shfl_xor_sync(0xffffffffu, mx0, 1));
        mx0 = fmaxf(mx0, __shfl_xor_sync(0xffffffffu, mx0, 2));
        mx1 = fmaxf(mx1, __shfl_xor_sync(0xffffffffu, mx1, 1));
        mx1 = fmaxf(mx1, __shfl_xor_sync(0xffffffffu, mx1, 2));
        const float mn0 = fmaxf(mrow0, mx0);
        const float mn1 = fmaxf(mrow1, mx1);
        const float corr0 = ex2(mrow0 - mn0);
        const float corr1 = ex2(mrow1 - mn1);
        float sum0 = 0.0f, sum1 = 0.0f;
        #pragma unroll
        for (int n = 0; n < 8; n++) {
            sacc[n][0] = ex2(sacc[n][0] - mn0);
            sacc[n][1] = ex2(sacc[n][1] - mn0);
            sacc[n][2] = ex2(sacc[n][2] - mn1);
            sacc[n][3] = ex2(sacc[n][3] - mn1);
            sum0 += sacc[n][0] + sacc[n][1];
            sum1 += sacc[n][2] + sacc[n][3];
        }
        sum0 += __shfl_xor_sync(0xffffffffu, sum0, 1);
        sum0 += __shfl_xor_sync(0xffffffffu, sum0, 2);
        sum1 += __shfl_xor_sync(0xffffffffu, sum1, 1);
        sum1 += __shfl_xor_sync(0xffffffffu, sum1, 2);
        lrow0 = lrow0 * corr0 + sum0;  mrow0 = mn0;
        lrow1 = lrow1 * corr1 + sum1;  mrow1 = mn1;
        #pragma unroll
        for (int n = 0; n < 8; n++) {
            oacc[n][0] *= corr0; oacc[n][1] *= corr0;
            oacc[n][2] *= corr1; oacc[n][3] *= corr1;
        }

        // ---- O += Ph*Vh + Pl*Vh (V natural, trans-ldsm B-fragments)
        #pragma unroll
        for (int kb = 0; kb < 4; kb++) {
            uint32_t pah[4], pal[4];
            hilo2h(sacc[2 * kb][0],     sacc[2 * kb][1],     pah[0], pal[0]);
            hilo2h(sacc[2 * kb][2],     sacc[2 * kb][3],     pah[1], pal[1]);
            hilo2h(sacc[2 * kb + 1][0], sacc[2 * kb + 1][1], pah[2], pal[2]);
            hilo2h(sacc[2 * kb + 1][2], sacc[2 * kb + 1][3], pah[3], pal[3]);
            #pragma unroll
            for (int np = 0; np < 4; np++) {
                const uint32_t av = (uint32_t)(
                    (kb * 16 + (quad & 1) * 8 + id8) * ROW2 +
                    (np * 16 + (quad >> 1) * 8) * 2);
                uint32_t h0, h1, h2, h3;
                ldsm4t(h0, h1, h2, h3, st + R_VH + av);
                mma_f16(oacc[2 * np], pah[0], pah[1], pah[2], pah[3], h0, h1);
                mma_f16(oacc[2 * np], pal[0], pal[1], pal[2], pal[3], h0, h1);
                mma_f16(oacc[2 * np + 1], pah[0], pah[1], pah[2], pah[3], h2, h3);
                mma_f16(oacc[2 * np + 1], pal[0], pal[1], pal[2], pal[3], h2, h3);
            }
        }

        // prefetch tile ch+3 into stage (ch+3)&3 (safe: all readers passed
        // this tile's barrier); empty commit keeps the wait-count invariant
        if (ch + 3 < NT) load_kv((ch + 3) * 64, (ch + 3) & 3);
        else             CP_COMMIT();
    }

    // ---- Normalize + write O as fp16 hi/lo
    const float inv0 = 1.0f / lrow0;
    const float inv1 = 1.0f / lrow1;
    const int row0 = t0 + wid * 16 + (lane >> 2);
    #pragma unroll
    for (int n = 0; n < 8; n++) {
        const int dk = n * 8 + (lane & 3) * 2;
        const size_t g0 = ((size_t)(bi * cT + row0) * cH + hh) * cDK + dk;
        const size_t g1 = ((size_t)(bi * cT + row0 + 8) * cH + hh) * cDK + dk;
        uint32_t hp, lp;
        hilo2h(oacc[n][0] * inv0, oacc[n][1] * inv0, hp, lp);
        *reinterpret_cast<uint32_t*>(oh + g0) = hp;
        *reinterpret_cast<uint32_t*>(ol + g0) = lp;
        hilo2h(oacc[n][2] * inv1, oacc[n][3] * inv1, hp, lp);
        *reinterpret_cast<uint32_t*>(oh + g1) = hp;
        *reinterpret_cast<uint32_t*>(ol + g1) = lp;
    }
}

// ---------------------------------------------------------------------------
extern "C" void kernel_launch(void* const* d_in, const int* in_sizes, int n_in,
                              void* d_out, int out_size)
{
    const float* query = (const float*)d_in[0];
    const float* value = (const float*)d_in[1];
    const float* key   = (const float*)d_in[2];
    const float* Wq    = (const float*)d_in[3];
    const float* bq    = (const float*)d_in[4];
    const float* Wk    = (const float*)d_in[5];
    const float* bk    = (const float*)d_in[6];
    const float* Wv    = (const float*)d_in[7];
    const float* bv    = (const float*)d_in[8];
    const float* Wo    = (const float*)d_in[9];
    const float* bo    = (const float*)d_in[10];
    float* out = (float*)d_out;

    f16 *xh, *xl, *yh, *yl, *wh, *wl;
    cudaGetSymbolAddress((void**)&xh, g_xh);
    cudaGetSymbolAddress((void**)&xl, g_xl);
    cudaGetSymbolAddress((void**)&yh, g_yh);
    cudaGetSymbolAddress((void**)&yl, g_yl);
    cudaGetSymbolAddress((void**)&wh, g_wth);
    cudaGetSymbolAddress((void**)&wl, g_wtl);

    cudaFuncSetAttribute(gemm_mma<true>,
                         cudaFuncAttributeMaxDynamicSharedMemorySize, GEMM_SMEM);
    cudaFuncSetAttribute(gemm_mma<false>,
                         cudaFuncAttributeMaxDynamicSharedMemorySize, GEMM_SMEM);

    const int XB = (int)(XSZ / 4 / 256);

    xconv3<<<dim3(XB, 1, 3), 256>>>(query, key, value, xh, xl);
    wconv<<<dim3(32, 32, 4), dim3(32, 8)>>>(Wq, Wk, Wv, Wo, wh, wl);

    // Q/K/V projections; Q scaled by 1/sqrt(DK)*log2(e); lo plane only for Q
    const float qscale = 0.125f * 1.44269504088896340736f;
    gemm_mma<true><<<dim3(cHD / 128, cMT / 128, 3), 256, GEMM_SMEM>>>(
        xh, xl, wh, wl, bq, bk, bv, nullptr, yh, yl, qscale, 0b001);

    // 2-term fp16 attention (K-lo / V-lo not used); out -> x slot 0 hi/lo
    attn_mma<<<dim3(cT / 128, cH, cB), 256>>>(
        yh, yl, yh + XSZ, yh + 2 * XSZ, xh, xl);

    // O projection (fp32 out, 3-term)
    gemm_mma<false><<<dim3(cD / 128, cMT / 128, 1), 256, GEMM_SMEM>>>(
        xh, xl, wh + 3 * WSZ, wl + 3 * WSZ, bo, bo, bo, out, nullptr, nullptr,
        1.0f, 0);
}

// round 11
// speedup vs baseline: 5.0679x; 1.1022x over previous
#include <cuda_runtime.h>
#include <cuda_fp16.h>
#include <math.h>
#include <cstdint>

// Problem constants
constexpr int cB = 2, cT = 2048, cS = 2048, cD = 1024, cH = 16, cDK = 64;
constexpr int cHD = cH * cDK;      // 1024
constexpr int cMT = cB * cT;       // 4096
constexpr size_t XSZ = (size_t)cMT * cD;
constexpr size_t WSZ = (size_t)cD * cHD;

using f16 = __half;

// ---- helpers ----
__device__ __forceinline__ uint32_t smem_u32(const void* p) {
    uint32_t a;
    asm("{ .reg .u64 t; cvta.to.shared.u64 t, %1; cvt.u32.u64 %0, t; }"
        : "=r"(a) : "l"(p));
    return a;
}
__device__ __forceinline__ void ldsm4(uint32_t& r0, uint32_t& r1,
                                      uint32_t& r2, uint32_t& r3, uint32_t a) {
    asm volatile("ldmatrix.sync.aligned.m8n8.x4.shared.b16 {%0,%1,%2,%3}, [%4];"
                 : "=r"(r0), "=r"(r1), "=r"(r2), "=r"(r3) : "r"(a));
}
__device__ __forceinline__ void ldsm4t(uint32_t& r0, uint32_t& r1,
                                       uint32_t& r2, uint32_t& r3, uint32_t a) {
    asm volatile("ldmatrix.sync.aligned.m8n8.x4.trans.shared.b16 {%0,%1,%2,%3}, [%4];"
                 : "=r"(r0), "=r"(r1), "=r"(r2), "=r"(r3) : "r"(a));
}
__device__ __forceinline__ void mma_f16(float c[4],
    uint32_t a0, uint32_t a1, uint32_t a2, uint32_t a3,
    uint32_t b0, uint32_t b1) {
    asm volatile("mma.sync.aligned.m16n8k16.row.col.f32.f16.f16.f32 "
                 "{%0,%1,%2,%3}, {%4,%5,%6,%7}, {%8,%9}, {%0,%1,%2,%3};"
                 : "+f"(c[0]), "+f"(c[1]), "+f"(c[2]), "+f"(c[3])
                 : "r"(a0), "r"(a1), "r"(a2), "r"(a3), "r"(b0), "r"(b1));
}
__device__ __forceinline__ void cp16(uint32_t dst, const void* src) {
    asm volatile("cp.async.cg.shared.global [%0], [%1], 16;"
                 :: "r"(dst), "l"(src));
}
#define CP_COMMIT() asm volatile("cp.async.commit_group;")
#define CP_WAIT(n)  asm volatile("cp.async.wait_group %0;" :: "n"(n))

__device__ __forceinline__ float ex2(float x) {
    float r; asm("ex2.approx.ftz.f32 %0, %1;" : "=f"(r) : "f"(x));
    return r;
}

// fp32 pair -> fp16 hi/lo packed pairs
__device__ __forceinline__ void hilo2h(float x, float y,
                                       uint32_t& h, uint32_t& l) {
    __half2 hh = __floats2half2_rn(x, y);
    float2 hf = __half22float2(hh);
    __half2 ll = __floats2half2_rn(x - hf.x, y - hf.y);
    h = *reinterpret_cast<uint32_t*>(&hh);
    l = *reinterpret_cast<uint32_t*>(&ll);
}

// ---- Scratch ----
__device__ f16 g_xh[3 * XSZ];
__device__ f16 g_xl[3 * XSZ];
__device__ f16 g_yh[3 * XSZ];
__device__ f16 g_yl[XSZ];          // only Q needs a lo plane
__device__ f16 g_wth[4 * WSZ];
__device__ f16 g_wtl[4 * WSZ];

// ---------------------------------------------------------------------------
// fp32 -> fp16 hi/lo split (3 inputs fused)
// ---------------------------------------------------------------------------
__global__ __launch_bounds__(256) void xconv3(
    const float* __restrict__ X0, const float* __restrict__ X1,
    const float* __restrict__ X2, f16* __restrict__ xh, f16* __restrict__ xl)
{
    const int z = blockIdx.z;
    const float* X = (z == 0) ? X0 : (z == 1) ? X1 : X2;
    const size_t i4 = ((size_t)blockIdx.x * 256 + threadIdx.x) * 4;
    const float4 v = *reinterpret_cast<const float4*>(X + i4);
    uint32_t h0, l0, h1, l1;
    hilo2h(v.x, v.y, h0, l0);
    hilo2h(v.z, v.w, h1, l1);
    const size_t o = (size_t)z * XSZ + i4;
    *reinterpret_cast<uint2*>(xh + o) = make_uint2(h0, h1);
    *reinterpret_cast<uint2*>(xl + o) = make_uint2(l0, l1);
}

// ---------------------------------------------------------------------------
// W[K,N] fp32 -> W^T[N,K] fp16 hi/lo
// ---------------------------------------------------------------------------
__global__ __launch_bounds__(256) void wconv(
    const float* __restrict__ W0, const float* __restrict__ W1,
    const float* __restrict__ W2, const float* __restrict__ W3,
    f16* __restrict__ wh, f16* __restrict__ wl)
{
    __shared__ float t[32][33];
    const int z = blockIdx.z;
    const float* W = (z == 0) ? W0 : (z == 1) ? W1 : (z == 2) ? W2 : W3;
    const int n0 = blockIdx.x * 32, k0 = blockIdx.y * 32;
    const int tx = threadIdx.x, ty = threadIdx.y;
    #pragma unroll
    for (int i = 0; i < 4; i++)
        t[ty + 8 * i][tx] = W[(size_t)(k0 + ty + 8 * i) * cHD + n0 + tx];
    __syncthreads();
    const size_t zb = (size_t)z * WSZ;
    #pragma unroll
    for (int i = 0; i < 4; i++) {
        const float v = t[tx][ty + 8 * i];
        const f16 h = __float2half_rn(v);
        const f16 l = __float2half_rn(v - __half2float(h));
        const size_t o = zb + (size_t)(n0 + ty + 8 * i) * cD + k0 + tx;
        wh[o] = h; wl[o] = l;
    }
}

// ---------------------------------------------------------------------------
// mma.sync split-fp16 GEMM.
// Per-z term count: 3-term D = Xh*Wh + Xh*Wl + Xl*Wh, or (term2_mask bit set)
// 2-term D = Xh*Wh + Xl*Wh (W-lo dropped: used for K/V whose outputs are
// consumed at fp16-hi precision anyway).
// ---------------------------------------------------------------------------
constexpr int ROWB = 80;
constexpr int TILE_B = 128 * ROWB;
constexpr int STAGE_B = 4 * TILE_B;
constexpr int GEMM_SMEM = 2 * STAGE_B;   // 81920

template <bool F16OUT>
__global__ __launch_bounds__(256, 2) void gemm_mma(
    const f16* __restrict__ Xh, const f16* __restrict__ Xl,
    const f16* __restrict__ Wh, const f16* __restrict__ Wl,
    const float* b0, const float* b1, const float* b2,
    float* oF, f16* oh, f16* ol, float scale0, int lo_mask, int term2_mask)
{
    extern __shared__ char dynsm[];
    const uint32_t sb = smem_u32(dynsm);
    const int tid = threadIdx.x;
    const int wid = tid >> 5;
    const int lane = tid & 31;
    const int z = blockIdx.z;
    const int m0 = blockIdx.y * 128;
    const int n0 = blockIdx.x * 128;
    const int wm = wid & 1;
    const int wn = wid >> 1;

    const f16* Ah = Xh + (size_t)z * XSZ;
    const f16* Al = Xl + (size_t)z * XSZ;
    const f16* Bh = Wh + (size_t)z * WSZ;
    const f16* Bl = Wl + (size_t)z * WSZ;
    const float* bias = (z == 0) ? b0 : (z == 1) ? b1 : b2;
    const float scale = (z == 0) ? scale0 : 1.0f;
    const bool write_lo = ((lo_mask >> z) & 1) != 0;
    const bool two_term = ((term2_mask >> z) & 1) != 0;

    float acc[4][4][4] = {};

    const int lr0 = tid >> 2, lc = (tid & 3);
    const uint32_t so0 = (uint32_t)(lr0 * ROWB + lc * 16);
    const uint32_t so1 = (uint32_t)((lr0 + 64) * ROWB + lc * 16);

    auto load_stage = [&](int chunk, int stage) {
        const uint32_t s0 = sb + stage * STAGE_B;
        const int k0 = chunk * 32;
        const size_t ga0 = (size_t)(m0 + lr0) * cD + k0 + lc * 8;
        const size_t ga1 = (size_t)(m0 + lr0 + 64) * cD + k0 + lc * 8;
        const size_t gb0 = (size_t)(n0 + lr0) * cD + k0 + lc * 8;
        const size_t gb1 = (size_t)(n0 + lr0 + 64) * cD + k0 + lc * 8;
        cp16(s0 + so0,              Ah + ga0);
        cp16(s0 + so1,              Ah + ga1);
        cp16(s0 + TILE_B + so0,     Al + ga0);
        cp16(s0 + TILE_B + so1,     Al + ga1);
        cp16(s0 + 2 * TILE_B + so0, Bh + gb0);
        cp16(s0 + 2 * TILE_B + so1, Bh + gb1);
        if (!two_term) {
            cp16(s0 + 3 * TILE_B + so0, Bl + gb0);
            cp16(s0 + 3 * TILE_B + so1, Bl + gb1);
        }
        CP_COMMIT();
    };

    load_stage(0, 0);
    const int NCH = cD / 32;
    for (int ch = 0; ch < NCH; ch++) {
        if (ch + 1 < NCH) { load_stage(ch + 1, (ch + 1) & 1); CP_WAIT(1); }
        else              { CP_WAIT(0); }
        __syncthreads();
        const uint32_t s0 = sb + (ch & 1) * STAGE_B;

        #pragma unroll
        for (int ks = 0; ks < 2; ks++) {
            const int acol = ks * 16 + ((lane >> 4) << 3);
            const int bcol = ks * 16 + (((lane >> 3) & 1) << 3);
            const int brow0 = wn * 32 + (lane & 7) + ((lane >> 4) << 3);

            // B-hi fragments
            uint32_t bh[4][2];
            #pragma unroll
            for (int np = 0; np < 2; np++) {
                const uint32_t boff = (uint32_t)((brow0 + np * 16) * ROWB + bcol * 2);
                uint32_t r0, r1, r2, r3;
                ldsm4(r0, r1, r2, r3, s0 + 2 * TILE_B + boff);
                bh[2 * np][0] = r0;     bh[2 * np][1] = r1;
                bh[2 * np + 1][0] = r2; bh[2 * np + 1][1] = r3;
            }
            // A-hi fragments
            uint32_t af[4][4];
            #pragma unroll
            for (int mi = 0; mi < 4; mi++) {
                const int row = wm * 64 + mi * 16 + (lane & 15);
                ldsm4(af[mi][0], af[mi][1], af[mi][2], af[mi][3],
                      s0 + (uint32_t)(row * ROWB + acol * 2));
            }
            #pragma unroll
            for (int mi = 0; mi < 4; mi++)
                #pragma unroll
                for (int ni = 0; ni < 4; ni++)
                    mma_f16(acc[mi][ni], af[mi][0], af[mi][1],
                            af[mi][2], af[mi][3], bh[ni][0], bh[ni][1]);

            if (!two_term) {
                // B-lo fragments; A-hi regs still live
                uint32_t bl[4][2];
                #pragma unroll
                for (int np = 0; np < 2; np++) {
                    const uint32_t boff = (uint32_t)((brow0 + np * 16) * ROWB + bcol * 2);
                    uint32_t r0, r1, r2, r3;
                    ldsm4(r0, r1, r2, r3, s0 + 3 * TILE_B + boff);
                    bl[2 * np][0] = r0;     bl[2 * np][1] = r1;
                    bl[2 * np + 1][0] = r2; bl[2 * np + 1][1] = r3;
                }
                #pragma unroll
                for (int mi = 0; mi < 4; mi++)
                    #pragma unroll
                    for (int ni = 0; ni < 4; ni++)
                        mma_f16(acc[mi][ni], af[mi][0], af[mi][1],
                                af[mi][2], af[mi][3], bl[ni][0], bl[ni][1]);
            }

            // A-lo overwrites the same registers; multiply with B-hi
            #pragma unroll
            for (int mi = 0; mi < 4; mi++) {
                const int row = wm * 64 + mi * 16 + (lane & 15);
                ldsm4(af[mi][0], af[mi][1], af[mi][2], af[mi][3],
                      s0 + TILE_B + (uint32_t)(row * ROWB + acol * 2));
            }
            #pragma unroll
            for (int mi = 0; mi < 4; mi++)
                #pragma unroll
                for (int ni = 0; ni < 4; ni++)
                    mma_f16(acc[mi][ni], af[mi][0], af[mi][1],
                            af[mi][2], af[mi][3], bh[ni][0], bh[ni][1]);
        }
        __syncthreads();
    }

    #pragma unroll
    for (int mi = 0; mi < 4; mi++) {
        #pragma unroll
        for (int h = 0; h < 2; h++) {
            const int row = m0 + wm * 64 + mi * 16 + h * 8 + (lane >> 2);
            #pragma unroll
            for (int ni = 0; ni < 4; ni++) {
                const int col = n0 + wn * 32 + ni * 8 + (lane & 3) * 2;
                const float2 bb = *reinterpret_cast<const float2*>(bias + col);
                const float v0 = (acc[mi][ni][h * 2 + 0] + bb.x) * scale;
                const float v1 = (acc[mi][ni][h * 2 + 1] + bb.y) * scale;
                if (F16OUT) {
                    uint32_t hp, lp;
                    hilo2h(v0, v1, hp, lp);
                    const size_t o = (size_t)z * XSZ + (size_t)row * 1024 + col;
                    *reinterpret_cast<uint32_t*>(oh + o) = hp;
                    if (write_lo)
                        *reinterpret_cast<uint32_t*>(ol + (size_t)row * 1024 + col) = lp;
                } else {
                    *reinterpret_cast<float2*>(oF + (size_t)row * 1024 + col) =
                        make_float2(v0, v1);
                }
            }
        }
    }
}

// ---------------------------------------------------------------------------
// fp16 2-term flash attention (round 10, prefetch moved before softmax):
//   S = Qh*Kh + Ql*Kh;  O = Ph*Vh + Pl*Vh
//   4-stage cp.async K/V pipeline, one barrier per tile; Q-lo in smem.
// ---------------------------------------------------------------------------
constexpr int ROW2 = 144;
constexpr int R_KH = 0;
constexpr int R_VH = 64 * ROW2;
constexpr int STG2 = 2 * 64 * ROW2;          // 18432 per stage
constexpr int QLO  = 4 * STG2;               // 73728: persistent Q-lo
constexpr int ATTN_SMEM = QLO + 128 * ROW2;  // 92160

__global__ __launch_bounds__(256, 2) void attn_mma(
    const f16* __restrict__ qh, const f16* __restrict__ ql,
    const f16* __restrict__ kh, const f16* __restrict__ vh,
    f16* __restrict__ oh, f16* __restrict__ ol)
{
    __shared__ __align__(16) unsigned char smb[ATTN_SMEM];
    const uint32_t sb = smem_u32(smb);
    const int tid = threadIdx.x;
    const int wid = tid >> 5;
    const int lane = tid & 31;
    const int t0 = blockIdx.x * 128;
    const int hh = blockIdx.y;
    const int bi = blockIdx.z;

    // ---- Q: hi staged transiently in stage area, lo into persistent QLO
    #pragma unroll
    for (int it = 0; it < 4; it++) {
        const int i = tid + it * 256;
        const int r = i >> 3, c = i & 7;
        const size_t g = ((size_t)(bi * cT + t0 + r) * cH + hh) * cDK + c * 8;
        *reinterpret_cast<uint4*>(smb + r * ROW2 + c * 16) =
            *reinterpret_cast<const uint4*>(qh + g);
        *reinterpret_cast<uint4*>(smb + QLO + r * ROW2 + c * 16) =
            *reinterpret_cast<const uint4*>(ql + g);
    }
    __syncthreads();

    uint32_t qfh[4][4];
    #pragma unroll
    for (int kb = 0; kb < 4; kb++) {
        const int row = wid * 16 + (lane & 15);
        const int col = kb * 16 + ((lane >> 4) << 3);
        ldsm4(qfh[kb][0], qfh[kb][1], qfh[kb][2], qfh[kb][3],
              sb + (uint32_t)(row * ROW2 + col * 2));
    }
    __syncthreads();   // stage area free for K/V

    const int lr = tid >> 3, lc8 = (tid & 7);
    auto load_kv = [&](int s0, int stage) {
        const uint32_t st = sb + stage * STG2;
        #pragma unroll
        for (int it = 0; it < 2; it++) {
            const int r = lr + it * 32;
            const uint32_t so = (uint32_t)(r * ROW2 + lc8 * 16);
            const size_t g = ((size_t)(bi * cS + s0 + r) * cH + hh) * cDK + lc8 * 8;
            cp16(st + R_KH + so, kh + g);
            cp16(st + R_VH + so, vh + g);
        }
        CP_COMMIT();
    };

    float oacc[8][4] = {};
    float mrow0 = -INFINITY, mrow1 = -INFINITY;
    float lrow0 = 0.0f, lrow1 = 0.0f;

    const int quad = lane >> 3, id8 = lane & 7;
    const int qrow = wid * 16 + (lane & 15);
    constexpr int NT = cS / 64;

    load_kv(0, 0);
    load_kv(64, 1);
    load_kv(128, 2);

    for (int ch = 0; ch < NT; ch++) {
        CP_WAIT(2);
        __syncthreads();
        const uint32_t st = sb + (ch & 3) * STG2;

        // ---- S = Qh*Kh + Ql*Kh
        float sacc[8][4] = {};
        #pragma unroll
        for (int kb = 0; kb < 4; kb++) {
            uint32_t ql0, ql1, ql2, ql3;
            {
                const int col = kb * 16 + ((lane >> 4) << 3);
                ldsm4(ql0, ql1, ql2, ql3,
                      sb + (uint32_t)(QLO + qrow * ROW2 + col * 2));
            }
            #pragma unroll
            for (int np = 0; np < 4; np++) {
                const int nrow = np * 16 + (lane & 7) + ((lane >> 4) << 3);
                const int col = kb * 16 + (((lane >> 3) & 1) << 3);
                uint32_t h0, h1, h2, h3;
                ldsm4(h0, h1, h2, h3, st + (uint32_t)(R_KH + nrow * ROW2 + col * 2));
                mma_f16(sacc[2 * np], qfh[kb][0], qfh[kb][1], qfh[kb][2], qfh[kb][3], h0, h1);
                mma_f16(sacc[2 * np], ql0, ql1, ql2, ql3, h0, h1);
                mma_f16(sacc[2 * np + 1], qfh[kb][0], qfh[kb][1], qfh[kb][2], qfh[kb][3], h2, h3);
                mma_f16(sacc[2 * np + 1], ql0, ql1, ql2, ql3, h2, h3);
            }
        }

        // prefetch tile ch+3 now so cp.async overlaps softmax + PV
        // (stage (ch+3)&3 held tile ch-1, finished by all warps before the
        // barrier above; empty commit keeps wait-count invariant)
        if (ch + 3 < NT) load_kv((ch + 3) * 64, (ch + 3) & 3);
        else             CP_COMMIT();

        // ---- Online softmax (exp2 domain; log2e folded into Q scale)
        float mx0 = -INFINITY, mx1 = -INFINITY;
        #pragma unroll
        for (int n = 0; n < 8; n++) {
            mx0 = fmaxf(mx0, fmaxf(sacc[n][0], sacc[n][1]));
            mx1 = fmaxf(mx1, fmaxf(sacc[n][2], sacc[n][3]));
        }
        mx0 = fmaxf(mx0, __shfl_xor_sync(0xffffffffu, mx0, 1));
        mx0 = fmaxf(mx0, __shfl_xor_sync(0xffffffffu, mx0, 2));
        mx1 = fmaxf(mx1, __shfl_xor_sync(0xffffffffu, mx1, 1));
        mx1 = fmaxf(mx1, __shfl_xor_sync(0xffffffffu, mx1, 2));
        const float mn0 = fmaxf(mrow0, mx0);
        const float mn1 = fmaxf(mrow1, mx1);
        const float corr0 = ex2(mrow0 - mn0);
        const float corr1 = ex2(mrow1 - mn1);
        float sum0 = 0.0f, sum1 = 0.0f;
        #pragma unroll
        for (int n = 0; n < 8; n++) {
            sacc[n][0] = ex2(sacc[n][0] - mn0);
            sacc[n][1] = ex2(sacc[n][1] - mn0);
            sacc[n][2] = ex2(sacc[n][2] - mn1);
            sacc[n][3] = ex2(sacc[n][3] - mn1);
            sum0 += sacc[n][0] + sacc[n][1];
            sum1 += sacc[n][2] + sacc[n][3];
        }
        sum0 += __shfl_xor_sync(0xffffffffu, sum0, 1);
        sum0 += __shfl_xor_sync(0xffffffffu, sum0, 2);
        sum1 += __shfl_xor_sync(0xffffffffu, sum1, 1);
        sum1 += __shfl_xor_sync(0xffffffffu, sum1, 2);
        lrow0 = lrow0 * corr0 + sum0;  mrow0 = mn0;
        lrow1 = lrow1 * corr1 + sum1;  mrow1 = mn1;
        #pragma unroll
        for (int n = 0; n < 8; n++) {
            oacc[n][0] *= corr0; oacc[n][1] *= corr0;
            oacc[n][2] *= corr1; oacc[n][3] *= corr1;
        }

        // ---- O += Ph*Vh + Pl*Vh (V natural, trans-ldsm B-fragments)
        #pragma unroll
        for (int kb = 0; kb < 4; kb++) {
            uint32_t pah[4], pal[4];
            hilo2h(sacc[2 * kb][0],     sacc[2 * kb][1],     pah[0], pal[0]);
            hilo2h(sacc[2 * kb][2],     sacc[2 * kb][3],     pah[1], pal[1]);
            hilo2h(sacc[2 * kb + 1][0], sacc[2 * kb + 1][1], pah[2], pal[2]);
            hilo2h(sacc[2 * kb + 1][2], sacc[2 * kb + 1][3], pah[3], pal[3]);
            #pragma unroll
            for (int np = 0; np < 4; np++) {
                const uint32_t av = (uint32_t)(
                    (kb * 16 + (quad & 1) * 8 + id8) * ROW2 +
                    (np * 16 + (quad >> 1) * 8) * 2);
                uint32_t h0, h1, h2, h3;
                ldsm4t(h0, h1, h2, h3, st + R_VH + av);
                mma_f16(oacc[2 * np], pah[0], pah[1], pah[2], pah[3], h0, h1);
                mma_f16(oacc[2 * np], pal[0], pal[1], pal[2], pal[3], h0, h1);
                mma_f16(oacc[2 * np + 1], pah[0], pah[1], pah[2], pah[3], h2, h3);
                mma_f16(oacc[2 * np + 1], pal[0], pal[1], pal[2], pal[3], h2, h3);
            }
        }
    }

    // ---- Normalize + write O as fp16 hi/lo
    const float inv0 = 1.0f / lrow0;
    const float inv1 = 1.0f / lrow1;
    const int row0 = t0 + wid * 16 + (lane >> 2);
    #pragma unroll
    for (int n = 0; n < 8; n++) {
        const int dk = n * 8 + (lane & 3) * 2;
        const size_t g0 = ((size_t)(bi * cT + row0) * cH + hh) * cDK + dk;
        const size_t g1 = ((size_t)(bi * cT + row0 + 8) * cH + hh) * cDK + dk;
        uint32_t hp, lp;
        hilo2h(oacc[n][0] * inv0, oacc[n][1] * inv0, hp, lp);
        *reinterpret_cast<uint32_t*>(oh + g0) = hp;
        *reinterpret_cast<uint32_t*>(ol + g0) = lp;
        hilo2h(oacc[n][2] * inv1, oacc[n][3] * inv1, hp, lp);
        *reinterpret_cast<uint32_t*>(oh + g1) = hp;
        *reinterpret_cast<uint32_t*>(ol + g1) = lp;
    }
}

// ---------------------------------------------------------------------------
extern "C" void kernel_launch(void* const* d_in, const int* in_sizes, int n_in,
                              void* d_out, int out_size)
{
    const float* query = (const float*)d_in[0];
    const float* value = (const float*)d_in[1];
    const float* key   = (const float*)d_in[2];
    const float* Wq    = (const float*)d_in[3];
    const float* bq    = (const float*)d_in[4];
    const float* Wk    = (const float*)d_in[5];
    const float* bk    = (const float*)d_in[6];
    const float* Wv    = (const float*)d_in[7];
    const float* bv    = (const float*)d_in[8];
    const float* Wo    = (const float*)d_in[9];
    const float* bo    = (const float*)d_in[10];
    float* out = (float*)d_out;

    f16 *xh, *xl, *yh, *yl, *wh, *wl;
    cudaGetSymbolAddress((void**)&xh, g_xh);
    cudaGetSymbolAddress((void**)&xl, g_xl);
    cudaGetSymbolAddress((void**)&yh, g_yh);
    cudaGetSymbolAddress((void**)&yl, g_yl);
    cudaGetSymbolAddress((void**)&wh, g_wth);
    cudaGetSymbolAddress((void**)&wl, g_wtl);

    cudaFuncSetAttribute(gemm_mma<true>,
                         cudaFuncAttributeMaxDynamicSharedMemorySize, GEMM_SMEM);
    cudaFuncSetAttribute(gemm_mma<false>,
                         cudaFuncAttributeMaxDynamicSharedMemorySize, GEMM_SMEM);

    const int XB = (int)(XSZ / 4 / 256);

    xconv3<<<dim3(XB, 1, 3), 256>>>(query, key, value, xh, xl);
    wconv<<<dim3(32, 32, 4), dim3(32, 8)>>>(Wq, Wk, Wv, Wo, wh, wl);

    // Q/K/V projections; Q: 3-term + lo plane; K,V: 2-term, hi only
    const float qscale = 0.125f * 1.44269504088896340736f;
    gemm_mma<true><<<dim3(cHD / 128, cMT / 128, 3), 256, GEMM_SMEM>>>(
        xh, xl, wh, wl, bq, bk, bv, nullptr, yh, yl, qscale, 0b001, 0b110);

    // 2-term fp16 attention; out -> x slot 0 hi/lo
    attn_mma<<<dim3(cT / 128, cH, cB), 256>>>(
        yh, yl, yh + XSZ, yh + 2 * XSZ, xh, xl);

    // O projection (fp32 out, 3-term)
    gemm_mma<false><<<dim3(cD / 128, cMT / 128, 1), 256, GEMM_SMEM>>>(
        xh, xl, wh + 3 * WSZ, wl + 3 * WSZ, bo, bo, bo, out, nullptr, nullptr,
        1.0f, 0, 0);
}

// round 13
// speedup vs baseline: 5.5983x; 1.1047x over previous
#include <cuda_runtime.h>
#include <cuda_fp16.h>
#include <math.h>
#include <cstdint>

// Problem constants
constexpr int cB = 2, cT = 2048, cS = 2048, cD = 1024, cH = 16, cDK = 64;
constexpr int cHD = cH * cDK;      // 1024
constexpr int cMT = cB * cT;       // 4096
constexpr size_t XSZ = (size_t)cMT * cD;
constexpr size_t WSZ = (size_t)cD * cHD;

using f16 = __half;

// ---- helpers ----
__device__ __forceinline__ uint32_t smem_u32(const void* p) {
    uint32_t a;
    asm("{ .reg .u64 t; cvta.to.shared.u64 t, %1; cvt.u32.u64 %0, t; }"
        : "=r"(a) : "l"(p));
    return a;
}
__device__ __forceinline__ void ldsm4(uint32_t& r0, uint32_t& r1,
                                      uint32_t& r2, uint32_t& r3, uint32_t a) {
    asm volatile("ldmatrix.sync.aligned.m8n8.x4.shared.b16 {%0,%1,%2,%3}, [%4];"
                 : "=r"(r0), "=r"(r1), "=r"(r2), "=r"(r3) : "r"(a));
}
__device__ __forceinline__ void ldsm4t(uint32_t& r0, uint32_t& r1,
                                       uint32_t& r2, uint32_t& r3, uint32_t a) {
    asm volatile("ldmatrix.sync.aligned.m8n8.x4.trans.shared.b16 {%0,%1,%2,%3}, [%4];"
                 : "=r"(r0), "=r"(r1), "=r"(r2), "=r"(r3) : "r"(a));
}
__device__ __forceinline__ void mma_f16(float c[4],
    uint32_t a0, uint32_t a1, uint32_t a2, uint32_t a3,
    uint32_t b0, uint32_t b1) {
    asm volatile("mma.sync.aligned.m16n8k16.row.col.f32.f16.f16.f32 "
                 "{%0,%1,%2,%3}, {%4,%5,%6,%7}, {%8,%9}, {%0,%1,%2,%3};"
                 : "+f"(c[0]), "+f"(c[1]), "+f"(c[2]), "+f"(c[3])
                 : "r"(a0), "r"(a1), "r"(a2), "r"(a3), "r"(b0), "r"(b1));
}
__device__ __forceinline__ void cp16(uint32_t dst, const void* src) {
    asm volatile("cp.async.cg.shared.global [%0], [%1], 16;"
                 :: "r"(dst), "l"(src));
}
#define CP_COMMIT() asm volatile("cp.async.commit_group;")
#define CP_WAIT(n)  asm volatile("cp.async.wait_group %0;" :: "n"(n))

__device__ __forceinline__ float ex2(float x) {
    float r; asm("ex2.approx.ftz.f32 %0, %1;" : "=f"(r) : "f"(x));
    return r;
}
// packed fp16 exp2 (one MUFU op for two values)
__device__ __forceinline__ uint32_t ex2h2(uint32_t x) {
    uint32_t r; asm("ex2.approx.f16x2 %0, %1;" : "=r"(r) : "r"(x));
    return r;
}
// pack two fp32 -> fp16x2 (lo half = first arg)
__device__ __forceinline__ uint32_t packh2(float lo, float hi) {
    uint32_t r;
    asm("cvt.rn.f16x2.f32 %0, %1, %2;" : "=r"(r) : "f"(hi), "f"(lo));
    return r;
}
// fp32 pair -> fp16 hi/lo packed pairs
__device__ __forceinline__ void hilo2h(float x, float y,
                                       uint32_t& h, uint32_t& l) {
    __half2 hh = __floats2half2_rn(x, y);
    float2 hf = __half22float2(hh);
    __half2 ll = __floats2half2_rn(x - hf.x, y - hf.y);
    h = *reinterpret_cast<uint32_t*>(&hh);
    l = *reinterpret_cast<uint32_t*>(&ll);
}

// ---- Scratch ----
__device__ f16 g_xh[3 * XSZ];
__device__ f16 g_xl[3 * XSZ];
__device__ f16 g_yh[3 * XSZ];
__device__ f16 g_yl[XSZ];          // only Q needs a lo plane
__device__ f16 g_wth[4 * WSZ];
__device__ f16 g_wtl[4 * WSZ];

// ---------------------------------------------------------------------------
// fp32 -> fp16 hi/lo split (3 inputs fused)
// ---------------------------------------------------------------------------
__global__ __launch_bounds__(256) void xconv3(
    const float* __restrict__ X0, const float* __restrict__ X1,
    const float* __restrict__ X2, f16* __restrict__ xh, f16* __restrict__ xl)
{
    const int z = blockIdx.z;
    const float* X = (z == 0) ? X0 : (z == 1) ? X1 : X2;
    const size_t i4 = ((size_t)blockIdx.x * 256 + threadIdx.x) * 4;
    const float4 v = *reinterpret_cast<const float4*>(X + i4);
    uint32_t h0, l0, h1, l1;
    hilo2h(v.x, v.y, h0, l0);
    hilo2h(v.z, v.w, h1, l1);
    const size_t o = (size_t)z * XSZ + i4;
    *reinterpret_cast<uint2*>(xh + o) = make_uint2(h0, h1);
    *reinterpret_cast<uint2*>(xl + o) = make_uint2(l0, l1);
}

// ---------------------------------------------------------------------------
// W[K,N] fp32 -> W^T[N,K] fp16 hi/lo
// ---------------------------------------------------------------------------
__global__ __launch_bounds__(256) void wconv(
    const float* __restrict__ W0, const float* __restrict__ W1,
    const float* __restrict__ W2, const float* __restrict__ W3,
    f16* __restrict__ wh, f16* __restrict__ wl)
{
    __shared__ float t[32][33];
    const int z = blockIdx.z;
    const float* W = (z == 0) ? W0 : (z == 1) ? W1 : (z == 2) ? W2 : W3;
    const int n0 = blockIdx.x * 32, k0 = blockIdx.y * 32;
    const int tx = threadIdx.x, ty = threadIdx.y;
    #pragma unroll
    for (int i = 0; i < 4; i++)
        t[ty + 8 * i][tx] = W[(size_t)(k0 + ty + 8 * i) * cHD + n0 + tx];
    __syncthreads();
    const size_t zb = (size_t)z * WSZ;
    #pragma unroll
    for (int i = 0; i < 4; i++) {
        const float v = t[tx][ty + 8 * i];
        const f16 h = __float2half_rn(v);
        const f16 l = __float2half_rn(v - __half2float(h));
        const size_t o = zb + (size_t)(n0 + ty + 8 * i) * cD + k0 + tx;
        wh[o] = h; wl[o] = l;
    }
}

// ---------------------------------------------------------------------------
// mma.sync split-fp16 GEMM (verified). Per-z: 3-term or 2-term (W-lo dropped).
// ---------------------------------------------------------------------------
constexpr int ROWB = 80;
constexpr int TILE_B = 128 * ROWB;
constexpr int STAGE_B = 4 * TILE_B;
constexpr int GEMM_SMEM = 2 * STAGE_B;   // 81920

template <bool F16OUT>
__global__ __launch_bounds__(256, 2) void gemm_mma(
    const f16* __restrict__ Xh, const f16* __restrict__ Xl,
    const f16* __restrict__ Wh, const f16* __restrict__ Wl,
    const float* b0, const float* b1, const float* b2,
    float* oF, f16* oh, f16* ol, float scale0, int lo_mask, int term2_mask)
{
    extern __shared__ char dynsm[];
    const uint32_t sb = smem_u32(dynsm);
    const int tid = threadIdx.x;
    const int wid = tid >> 5;
    const int lane = tid & 31;
    const int z = blockIdx.z;
    const int m0 = blockIdx.y * 128;
    const int n0 = blockIdx.x * 128;
    const int wm = wid & 1;
    const int wn = wid >> 1;

    const f16* Ah = Xh + (size_t)z * XSZ;
    const f16* Al = Xl + (size_t)z * XSZ;
    const f16* Bh = Wh + (size_t)z * WSZ;
    const f16* Bl = Wl + (size_t)z * WSZ;
    const float* bias = (z == 0) ? b0 : (z == 1) ? b1 : b2;
    const float scale = (z == 0) ? scale0 : 1.0f;
    const bool write_lo = ((lo_mask >> z) & 1) != 0;
    const bool two_term = ((term2_mask >> z) & 1) != 0;

    float acc[4][4][4] = {};

    const int lr0 = tid >> 2, lc = (tid & 3);
    const uint32_t so0 = (uint32_t)(lr0 * ROWB + lc * 16);
    const uint32_t so1 = (uint32_t)((lr0 + 64) * ROWB + lc * 16);

    auto load_stage = [&](int chunk, int stage) {
        const uint32_t s0 = sb + stage * STAGE_B;
        const int k0 = chunk * 32;
        const size_t ga0 = (size_t)(m0 + lr0) * cD + k0 + lc * 8;
        const size_t ga1 = (size_t)(m0 + lr0 + 64) * cD + k0 + lc * 8;
        const size_t gb0 = (size_t)(n0 + lr0) * cD + k0 + lc * 8;
        const size_t gb1 = (size_t)(n0 + lr0 + 64) * cD + k0 + lc * 8;
        cp16(s0 + so0,              Ah + ga0);
        cp16(s0 + so1,              Ah + ga1);
        cp16(s0 + TILE_B + so0,     Al + ga0);
        cp16(s0 + TILE_B + so1,     Al + ga1);
        cp16(s0 + 2 * TILE_B + so0, Bh + gb0);
        cp16(s0 + 2 * TILE_B + so1, Bh + gb1);
        if (!two_term) {
            cp16(s0 + 3 * TILE_B + so0, Bl + gb0);
            cp16(s0 + 3 * TILE_B + so1, Bl + gb1);
        }
        CP_COMMIT();
    };

    load_stage(0, 0);
    const int NCH = cD / 32;
    for (int ch = 0; ch < NCH; ch++) {
        if (ch + 1 < NCH) { load_stage(ch + 1, (ch + 1) & 1); CP_WAIT(1); }
        else              { CP_WAIT(0); }
        __syncthreads();
        const uint32_t s0 = sb + (ch & 1) * STAGE_B;

        #pragma unroll
        for (int ks = 0; ks < 2; ks++) {
            const int acol = ks * 16 + ((lane >> 4) << 3);
            const int bcol = ks * 16 + (((lane >> 3) & 1) << 3);
            const int brow0 = wn * 32 + (lane & 7) + ((lane >> 4) << 3);

            // B-hi fragments
            uint32_t bh[4][2];
            #pragma unroll
            for (int np = 0; np < 2; np++) {
                const uint32_t boff = (uint32_t)((brow0 + np * 16) * ROWB + bcol * 2);
                uint32_t r0, r1, r2, r3;
                ldsm4(r0, r1, r2, r3, s0 + 2 * TILE_B + boff);
                bh[2 * np][0] = r0;     bh[2 * np][1] = r1;
                bh[2 * np + 1][0] = r2; bh[2 * np + 1][1] = r3;
            }
            // A-hi fragments
            uint32_t af[4][4];
            #pragma unroll
            for (int mi = 0; mi < 4; mi++) {
                const int row = wm * 64 + mi * 16 + (lane & 15);
                ldsm4(af[mi][0], af[mi][1], af[mi][2], af[mi][3],
                      s0 + (uint32_t)(row * ROWB + acol * 2));
            }
            #pragma unroll
            for (int mi = 0; mi < 4; mi++)
                #pragma unroll
                for (int ni = 0; ni < 4; ni++)
                    mma_f16(acc[mi][ni], af[mi][0], af[mi][1],
                            af[mi][2], af[mi][3], bh[ni][0], bh[ni][1]);

            if (!two_term) {
                uint32_t bl[4][2];
                #pragma unroll
                for (int np = 0; np < 2; np++) {
                    const uint32_t boff = (uint32_t)((brow0 + np * 16) * ROWB + bcol * 2);
                    uint32_t r0, r1, r2, r3;
                    ldsm4(r0, r1, r2, r3, s0 + 3 * TILE_B + boff);
                    bl[2 * np][0] = r0;     bl[2 * np][1] = r1;
                    bl[2 * np + 1][0] = r2; bl[2 * np + 1][1] = r3;
                }
                #pragma unroll
                for (int mi = 0; mi < 4; mi++)
                    #pragma unroll
                    for (int ni = 0; ni < 4; ni++)
                        mma_f16(acc[mi][ni], af[mi][0], af[mi][1],
                                af[mi][2], af[mi][3], bl[ni][0], bl[ni][1]);
            }

            // A-lo overwrites the same registers; multiply with B-hi
            #pragma unroll
            for (int mi = 0; mi < 4; mi++) {
                const int row = wm * 64 + mi * 16 + (lane & 15);
                ldsm4(af[mi][0], af[mi][1], af[mi][2], af[mi][3],
                      s0 + TILE_B + (uint32_t)(row * ROWB + acol * 2));
            }
            #pragma unroll
            for (int mi = 0; mi < 4; mi++)
                #pragma unroll
                for (int ni = 0; ni < 4; ni++)
                    mma_f16(acc[mi][ni], af[mi][0], af[mi][1],
                            af[mi][2], af[mi][3], bh[ni][0], bh[ni][1]);
        }
        __syncthreads();
    }

    #pragma unroll
    for (int mi = 0; mi < 4; mi++) {
        #pragma unroll
        for (int h = 0; h < 2; h++) {
            const int row = m0 + wm * 64 + mi * 16 + h * 8 + (lane >> 2);
            #pragma unroll
            for (int ni = 0; ni < 4; ni++) {
                const int col = n0 + wn * 32 + ni * 8 + (lane & 3) * 2;
                const float2 bb = *reinterpret_cast<const float2*>(bias + col);
                const float v0 = (acc[mi][ni][h * 2 + 0] + bb.x) * scale;
                const float v1 = (acc[mi][ni][h * 2 + 1] + bb.y) * scale;
                if (F16OUT) {
                    uint32_t hp, lp;
                    hilo2h(v0, v1, hp, lp);
                    const size_t o = (size_t)z * XSZ + (size_t)row * 1024 + col;
                    *reinterpret_cast<uint32_t*>(oh + o) = hp;
                    if (write_lo)
                        *reinterpret_cast<uint32_t*>(ol + (size_t)row * 1024 + col) = lp;
                } else {
                    *reinterpret_cast<float2*>(oF + (size_t)row * 1024 + col) =
                        make_float2(v0, v1);
                }
            }
        }
    }
}

// ---------------------------------------------------------------------------
// fp16 flash attention v4:
//   S = Qh*Kh + Ql*Kh;  P = ex2.f16x2(S - m)  (packed fp16 exp2, half MUFU)
//   O += Ph*Vh  (1-term PV; P is intrinsically fp16 now)
//   row sums via MMA against an all-ones B fragment (no shuffles, fp32 acc,
//   same quantized P in numerator and denominator -> bias cancels)
// ---------------------------------------------------------------------------
constexpr int ROW2 = 144;
constexpr int R_KH = 0;
constexpr int R_VH = 64 * ROW2;
constexpr int STG2 = 2 * 64 * ROW2;          // 18432 per stage
constexpr int QLO  = 4 * STG2;               // 73728: persistent Q-lo
constexpr int ATTN_SMEM = QLO + 128 * ROW2;  // 92160

__global__ __launch_bounds__(256, 2) void attn_mma(
    const f16* __restrict__ qh, const f16* __restrict__ ql,
    const f16* __restrict__ kh, const f16* __restrict__ vh,
    f16* __restrict__ oh, f16* __restrict__ ol)
{
    __shared__ __align__(16) unsigned char smb[ATTN_SMEM];
    const uint32_t sb = smem_u32(smb);
    const int tid = threadIdx.x;
    const int wid = tid >> 5;
    const int lane = tid & 31;
    const int t0 = blockIdx.x * 128;
    const int hh = blockIdx.y;
    const int bi = blockIdx.z;

    // ---- Q: hi staged transiently in stage area, lo into persistent QLO
    #pragma unroll
    for (int it = 0; it < 4; it++) {
        const int i = tid + it * 256;
        const int r = i >> 3, c = i & 7;
        const size_t g = ((size_t)(bi * cT + t0 + r) * cH + hh) * cDK + c * 8;
        *reinterpret_cast<uint4*>(smb + r * ROW2 + c * 16) =
            *reinterpret_cast<const uint4*>(qh + g);
        *reinterpret_cast<uint4*>(smb + QLO + r * ROW2 + c * 16) =
            *reinterpret_cast<const uint4*>(ql + g);
    }
    __syncthreads();

    uint32_t qfh[4][4];
    #pragma unroll
    for (int kb = 0; kb < 4; kb++) {
        const int row = wid * 16 + (lane & 15);
        const int col = kb * 16 + ((lane >> 4) << 3);
        ldsm4(qfh[kb][0], qfh[kb][1], qfh[kb][2], qfh[kb][3],
              sb + (uint32_t)(row * ROW2 + col * 2));
    }
    __syncthreads();   // stage area free for K/V

    const int lr = tid >> 3, lc8 = (tid & 7);
    auto load_kv = [&](int s0, int stage) {
        const uint32_t st = sb + stage * STG2;
        #pragma unroll
        for (int it = 0; it < 2; it++) {
            const int r = lr + it * 32;
            const uint32_t so = (uint32_t)(r * ROW2 + lc8 * 16);
            const size_t g = ((size_t)(bi * cS + s0 + r) * cH + hh) * cDK + lc8 * 8;
            cp16(st + R_KH + so, kh + g);
            cp16(st + R_VH + so, vh + g);
        }
        CP_COMMIT();
    };

    float oacc[8][4] = {};
    float mrow0 = -INFINITY, mrow1 = -INFINITY;
    float lrow0 = 0.0f, lrow1 = 0.0f;

    const int quad = lane >> 3, id8 = lane & 7;
    const int qrow = wid * 16 + (lane & 15);
    constexpr uint32_t ONES2 = 0x3C003C00u;   // half2(1.0, 1.0)
    constexpr int NT = cS / 64;

    load_kv(0, 0);
    load_kv(64, 1);
    load_kv(128, 2);

    for (int ch = 0; ch < NT; ch++) {
        CP_WAIT(2);
        __syncthreads();
        const uint32_t st = sb + (ch & 3) * STG2;

        // ---- S = Qh*Kh + Ql*Kh
        float sacc[8][4] = {};
        #pragma unroll
        for (int kb = 0; kb < 4; kb++) {
            uint32_t ql0, ql1, ql2, ql3;
            {
                const int col = kb * 16 + ((lane >> 4) << 3);
                ldsm4(ql0, ql1, ql2, ql3,
                      sb + (uint32_t)(QLO + qrow * ROW2 + col * 2));
            }
            #pragma unroll
            for (int np = 0; np < 4; np++) {
                const int nrow = np * 16 + (lane & 7) + ((lane >> 4) << 3);
                const int col = kb * 16 + (((lane >> 3) & 1) << 3);
                uint32_t h0, h1, h2, h3;
                ldsm4(h0, h1, h2, h3, st + (uint32_t)(R_KH + nrow * ROW2 + col * 2));
                mma_f16(sacc[2 * np], qfh[kb][0], qfh[kb][1], qfh[kb][2], qfh[kb][3], h0, h1);
                mma_f16(sacc[2 * np], ql0, ql1, ql2, ql3, h0, h1);
                mma_f16(sacc[2 * np + 1], qfh[kb][0], qfh[kb][1], qfh[kb][2], qfh[kb][3], h2, h3);
                mma_f16(sacc[2 * np + 1], ql0, ql1, ql2, ql3, h2, h3);
            }
        }

        // prefetch tile ch+3 now so cp.async overlaps softmax + PV
        if (ch + 3 < NT) load_kv((ch + 3) * 64, (ch + 3) & 3);
        else             CP_COMMIT();

        // ---- max reduction (fp32)
        float mx0 = -INFINITY, mx1 = -INFINITY;
        #pragma unroll
        for (int n = 0; n < 8; n++) {
            mx0 = fmaxf(mx0, fmaxf(sacc[n][0], sacc[n][1]));
            mx1 = fmaxf(mx1, fmaxf(sacc[n][2], sacc[n][3]));
        }
        mx0 = fmaxf(mx0, __shfl_xor_sync(0xffffffffu, mx0, 1));
        mx0 = fmaxf(mx0, __shfl_xor_sync(0xffffffffu, mx0, 2));
        mx1 = fmaxf(mx1, __shfl_xor_sync(0xffffffffu, mx1, 1));
        mx1 = fmaxf(mx1, __shfl_xor_sync(0xffffffffu, mx1, 2));
        const float mn0 = fmaxf(mrow0, mx0);
        const float mn1 = fmaxf(mrow1, mx1);
        const float corr0 = ex2(mrow0 - mn0);
        const float corr1 = ex2(mrow1 - mn1);
        mrow0 = mn0;  mrow1 = mn1;

        // ---- P = ex2((S - m)) in packed fp16; row sums via ones-MMA
        // A-frag mapping (m16n8k16): [kb][0]=rows r    (mn0), [kb][1]=rows r+8 (mn1),
        //                            [kb][2]=rows r k+8(mn0), [kb][3]=rows r+8 k+8 (mn1)
        uint32_t pah[4][4];
        float sumacc[4] = {0.f, 0.f, 0.f, 0.f};
        #pragma unroll
        for (int kb = 0; kb < 4; kb++) {
            pah[kb][0] = ex2h2(packh2(sacc[2 * kb][0] - mn0, sacc[2 * kb][1] - mn0));
            pah[kb][1] = ex2h2(packh2(sacc[2 * kb][2] - mn1, sacc[2 * kb][3] - mn1));
            pah[kb][2] = ex2h2(packh2(sacc[2 * kb + 1][0] - mn0, sacc[2 * kb + 1][1] - mn0));
            pah[kb][3] = ex2h2(packh2(sacc[2 * kb + 1][2] - mn1, sacc[2 * kb + 1][3] - mn1));
            mma_f16(sumacc, pah[kb][0], pah[kb][1], pah[kb][2], pah[kb][3],
                    ONES2, ONES2);
        }
        // every lane holds the full row sums (all D columns equal)
        lrow0 = lrow0 * corr0 + sumacc[0];
        lrow1 = lrow1 * corr1 + sumacc[2];

        #pragma unroll
        for (int n = 0; n < 8; n++) {
            oacc[n][0] *= corr0; oacc[n][1] *= corr0;
            oacc[n][2] *= corr1; oacc[n][3] *= corr1;
        }

        // ---- O += Ph*Vh (V natural, trans-ldsm B-fragments)
        #pragma unroll
        for (int kb = 0; kb < 4; kb++) {
            #pragma unroll
            for (int np = 0; np < 4; np++) {
                const uint32_t av = (uint32_t)(
                    (kb * 16 + (quad & 1) * 8 + id8) * ROW2 +
                    (np * 16 + (quad >> 1) * 8) * 2);
                uint32_t h0, h1, h2, h3;
                ldsm4t(h0, h1, h2, h3, st + R_VH + av);
                mma_f16(oacc[2 * np], pah[kb][0], pah[kb][1], pah[kb][2], pah[kb][3], h0, h1);
                mma_f16(oacc[2 * np + 1], pah[kb][0], pah[kb][1], pah[kb][2], pah[kb][3], h2, h3);
            }
        }
    }

    // ---- Normalize + write O as fp16 hi/lo
    const float inv0 = 1.0f / lrow0;
    const float inv1 = 1.0f / lrow1;
    const int row0 = t0 + wid * 16 + (lane >> 2);
    #pragma unroll
    for (int n = 0; n < 8; n++) {
        const int dk = n * 8 + (lane & 3) * 2;
        const size_t g0 = ((size_t)(bi * cT + row0) * cH + hh) * cDK + dk;
        const size_t g1 = ((size_t)(bi * cT + row0 + 8) * cH + hh) * cDK + dk;
        uint32_t hp, lp;
        hilo2h(oacc[n][0] * inv0, oacc[n][1] * inv0, hp, lp);
        *reinterpret_cast<uint32_t*>(oh + g0) = hp;
        *reinterpret_cast<uint32_t*>(ol + g0) = lp;
        hilo2h(oacc[n][2] * inv1, oacc[n][3] * inv1, hp, lp);
        *reinterpret_cast<uint32_t*>(oh + g1) = hp;
        *reinterpret_cast<uint32_t*>(ol + g1) = lp;
    }
}

// ---------------------------------------------------------------------------
extern "C" void kernel_launch(void* const* d_in, const int* in_sizes, int n_in,
                              void* d_out, int out_size)
{
    const float* query = (const float*)d_in[0];
    const float* value = (const float*)d_in[1];
    const float* key   = (const float*)d_in[2];
    const float* Wq    = (const float*)d_in[3];
    const float* bq    = (const float*)d_in[4];
    const float* Wk    = (const float*)d_in[5];
    const float* bk    = (const float*)d_in[6];
    const float* Wv    = (const float*)d_in[7];
    const float* bv    = (const float*)d_in[8];
    const float* Wo    = (const float*)d_in[9];
    const float* bo    = (const float*)d_in[10];
    float* out = (float*)d_out;

    f16 *xh, *xl, *yh, *yl, *wh, *wl;
    cudaGetSymbolAddress((void**)&xh, g_xh);
    cudaGetSymbolAddress((void**)&xl, g_xl);
    cudaGetSymbolAddress((void**)&yh, g_yh);
    cudaGetSymbolAddress((void**)&yl, g_yl);
    cudaGetSymbolAddress((void**)&wh, g_wth);
    cudaGetSymbolAddress((void**)&wl, g_wtl);

    cudaFuncSetAttribute(gemm_mma<true>,
                         cudaFuncAttributeMaxDynamicSharedMemorySize, GEMM_SMEM);
    cudaFuncSetAttribute(gemm_mma<false>,
                         cudaFuncAttributeMaxDynamicSharedMemorySize, GEMM_SMEM);

    const int XB = (int)(XSZ / 4 / 256);

    xconv3<<<dim3(XB, 1, 3), 256>>>(query, key, value, xh, xl);
    wconv<<<dim3(32, 32, 4), dim3(32, 8)>>>(Wq, Wk, Wv, Wo, wh, wl);

    // Q/K/V projections; Q: 3-term + lo plane; K,V: 2-term, hi only
    const float qscale = 0.125f * 1.44269504088896340736f;
    gemm_mma<true><<<dim3(cHD / 128, cMT / 128, 3), 256, GEMM_SMEM>>>(
        xh, xl, wh, wl, bq, bk, bv, nullptr, yh, yl, qscale, 0b001, 0b110);

    // fp16 attention; out -> x slot 0 hi/lo
    attn_mma<<<dim3(cT / 128, cH, cB), 256>>>(
        yh, yl, yh + XSZ, yh + 2 * XSZ, xh, xl);

    // O projection (fp32 out, 3-term)
    gemm_mma<false><<<dim3(cD / 128, cMT / 128, 1), 256, GEMM_SMEM>>>(
        xh, xl, wh + 3 * WSZ, wl + 3 * WSZ, bo, bo, bo, out, nullptr, nullptr,
        1.0f, 0, 0);
}

// round 14
// speedup vs baseline: 6.0831x; 1.0866x over previous
#include <cuda_runtime.h>
#include <cuda_fp16.h>
#include <math.h>
#include <cstdint>

// Problem constants
constexpr int cB = 2, cT = 2048, cS = 2048, cD = 1024, cH = 16, cDK = 64;
constexpr int cHD = cH * cDK;      // 1024
constexpr int cMT = cB * cT;       // 4096
constexpr size_t XSZ = (size_t)cMT * cD;
constexpr size_t WSZ = (size_t)cD * cHD;

using f16 = __half;

// ---- helpers ----
__device__ __forceinline__ uint32_t smem_u32(const void* p) {
    uint32_t a;
    asm("{ .reg .u64 t; cvta.to.shared.u64 t, %1; cvt.u32.u64 %0, t; }"
        : "=r"(a) : "l"(p));
    return a;
}
__device__ __forceinline__ void ldsm4(uint32_t& r0, uint32_t& r1,
                                      uint32_t& r2, uint32_t& r3, uint32_t a) {
    asm volatile("ldmatrix.sync.aligned.m8n8.x4.shared.b16 {%0,%1,%2,%3}, [%4];"
                 : "=r"(r0), "=r"(r1), "=r"(r2), "=r"(r3) : "r"(a));
}
__device__ __forceinline__ void ldsm4t(uint32_t& r0, uint32_t& r1,
                                       uint32_t& r2, uint32_t& r3, uint32_t a) {
    asm volatile("ldmatrix.sync.aligned.m8n8.x4.trans.shared.b16 {%0,%1,%2,%3}, [%4];"
                 : "=r"(r0), "=r"(r1), "=r"(r2), "=r"(r3) : "r"(a));
}
__device__ __forceinline__ void mma_f16(float c[4],
    uint32_t a0, uint32_t a1, uint32_t a2, uint32_t a3,
    uint32_t b0, uint32_t b1) {
    asm volatile("mma.sync.aligned.m16n8k16.row.col.f32.f16.f16.f32 "
                 "{%0,%1,%2,%3}, {%4,%5,%6,%7}, {%8,%9}, {%0,%1,%2,%3};"
                 : "+f"(c[0]), "+f"(c[1]), "+f"(c[2]), "+f"(c[3])
                 : "r"(a0), "r"(a1), "r"(a2), "r"(a3), "r"(b0), "r"(b1));
}
__device__ __forceinline__ void cp16(uint32_t dst, const void* src) {
    asm volatile("cp.async.cg.shared.global [%0], [%1], 16;"
                 :: "r"(dst), "l"(src));
}
#define CP_COMMIT() asm volatile("cp.async.commit_group;")
#define CP_WAIT(n)  asm volatile("cp.async.wait_group %0;" :: "n"(n))

__device__ __forceinline__ float ex2(float x) {
    float r; asm("ex2.approx.ftz.f32 %0, %1;" : "=f"(r) : "f"(x));
    return r;
}
// packed fp16 exp2 (one MUFU op for two values)
__device__ __forceinline__ uint32_t ex2h2(uint32_t x) {
    uint32_t r; asm("ex2.approx.f16x2 %0, %1;" : "=r"(r) : "r"(x));
    return r;
}
// pack two fp32 -> fp16x2 (lo half = first arg)
__device__ __forceinline__ uint32_t packh2(float lo, float hi) {
    uint32_t r;
    asm("cvt.rn.f16x2.f32 %0, %1, %2;" : "=r"(r) : "f"(hi), "f"(lo));
    return r;
}
// fp32 pair -> fp16 hi/lo packed pairs
__device__ __forceinline__ void hilo2h(float x, float y,
                                       uint32_t& h, uint32_t& l) {
    __half2 hh = __floats2half2_rn(x, y);
    float2 hf = __half22float2(hh);
    __half2 ll = __floats2half2_rn(x - hf.x, y - hf.y);
    h = *reinterpret_cast<uint32_t*>(&hh);
    l = *reinterpret_cast<uint32_t*>(&ll);
}

// ---- Scratch ----
__device__ f16 g_xh[3 * XSZ];
__device__ f16 g_xl[3 * XSZ];
__device__ f16 g_yh[3 * XSZ];      // Q/K/V projections, fp16-hi only
__device__ f16 g_wth[4 * WSZ];
__device__ f16 g_wtl[4 * WSZ];

// ---------------------------------------------------------------------------
// fp32 -> fp16 hi/lo split (3 inputs fused)
// ---------------------------------------------------------------------------
__global__ __launch_bounds__(256) void xconv3(
    const float* __restrict__ X0, const float* __restrict__ X1,
    const float* __restrict__ X2, f16* __restrict__ xh, f16* __restrict__ xl)
{
    const int z = blockIdx.z;
    const float* X = (z == 0) ? X0 : (z == 1) ? X1 : X2;
    const size_t i4 = ((size_t)blockIdx.x * 256 + threadIdx.x) * 4;
    const float4 v = *reinterpret_cast<const float4*>(X + i4);
    uint32_t h0, l0, h1, l1;
    hilo2h(v.x, v.y, h0, l0);
    hilo2h(v.z, v.w, h1, l1);
    const size_t o = (size_t)z * XSZ + i4;
    *reinterpret_cast<uint2*>(xh + o) = make_uint2(h0, h1);
    *reinterpret_cast<uint2*>(xl + o) = make_uint2(l0, l1);
}

// ---------------------------------------------------------------------------
// W[K,N] fp32 -> W^T[N,K] fp16 hi/lo
// ---------------------------------------------------------------------------
__global__ __launch_bounds__(256) void wconv(
    const float* __restrict__ W0, const float* __restrict__ W1,
    const float* __restrict__ W2, const float* __restrict__ W3,
    f16* __restrict__ wh, f16* __restrict__ wl)
{
    __shared__ float t[32][33];
    const int z = blockIdx.z;
    const float* W = (z == 0) ? W0 : (z == 1) ? W1 : (z == 2) ? W2 : W3;
    const int n0 = blockIdx.x * 32, k0 = blockIdx.y * 32;
    const int tx = threadIdx.x, ty = threadIdx.y;
    #pragma unroll
    for (int i = 0; i < 4; i++)
        t[ty + 8 * i][tx] = W[(size_t)(k0 + ty + 8 * i) * cHD + n0 + tx];
    __syncthreads();
    const size_t zb = (size_t)z * WSZ;
    #pragma unroll
    for (int i = 0; i < 4; i++) {
        const float v = t[tx][ty + 8 * i];
        const f16 h = __float2half_rn(v);
        const f16 l = __float2half_rn(v - __half2float(h));
        const size_t o = zb + (size_t)(n0 + ty + 8 * i) * cD + k0 + tx;
        wh[o] = h; wl[o] = l;
    }
}

// ---------------------------------------------------------------------------
// mma.sync split-fp16 GEMM (verified). Per-z: 3-term or 2-term (W-lo dropped).
// ---------------------------------------------------------------------------
constexpr int ROWB = 80;
constexpr int TILE_B = 128 * ROWB;
constexpr int STAGE_B = 4 * TILE_B;
constexpr int GEMM_SMEM = 2 * STAGE_B;   // 81920

template <bool F16OUT>
__global__ __launch_bounds__(256, 2) void gemm_mma(
    const f16* __restrict__ Xh, const f16* __restrict__ Xl,
    const f16* __restrict__ Wh, const f16* __restrict__ Wl,
    const float* b0, const float* b1, const float* b2,
    float* oF, f16* oh, float scale0, int term2_mask)
{
    extern __shared__ char dynsm[];
    const uint32_t sb = smem_u32(dynsm);
    const int tid = threadIdx.x;
    const int wid = tid >> 5;
    const int lane = tid & 31;
    const int z = blockIdx.z;
    const int m0 = blockIdx.y * 128;
    const int n0 = blockIdx.x * 128;
    const int wm = wid & 1;
    const int wn = wid >> 1;

    const f16* Ah = Xh + (size_t)z * XSZ;
    const f16* Al = Xl + (size_t)z * XSZ;
    const f16* Bh = Wh + (size_t)z * WSZ;
    const f16* Bl = Wl + (size_t)z * WSZ;
    const float* bias = (z == 0) ? b0 : (z == 1) ? b1 : b2;
    const float scale = (z == 0) ? scale0 : 1.0f;
    const bool two_term = ((term2_mask >> z) & 1) != 0;

    float acc[4][4][4] = {};

    const int lr0 = tid >> 2, lc = (tid & 3);
    const uint32_t so0 = (uint32_t)(lr0 * ROWB + lc * 16);
    const uint32_t so1 = (uint32_t)((lr0 + 64) * ROWB + lc * 16);

    auto load_stage = [&](int chunk, int stage) {
        const uint32_t s0 = sb + stage * STAGE_B;
        const int k0 = chunk * 32;
        const size_t ga0 = (size_t)(m0 + lr0) * cD + k0 + lc * 8;
        const size_t ga1 = (size_t)(m0 + lr0 + 64) * cD + k0 + lc * 8;
        const size_t gb0 = (size_t)(n0 + lr0) * cD + k0 + lc * 8;
        const size_t gb1 = (size_t)(n0 + lr0 + 64) * cD + k0 + lc * 8;
        cp16(s0 + so0,              Ah + ga0);
        cp16(s0 + so1,              Ah + ga1);
        cp16(s0 + TILE_B + so0,     Al + ga0);
        cp16(s0 + TILE_B + so1,     Al + ga1);
        cp16(s0 + 2 * TILE_B + so0, Bh + gb0);
        cp16(s0 + 2 * TILE_B + so1, Bh + gb1);
        if (!two_term) {
            cp16(s0 + 3 * TILE_B + so0, Bl + gb0);
            cp16(s0 + 3 * TILE_B + so1, Bl + gb1);
        }
        CP_COMMIT();
    };

    load_stage(0, 0);
    const int NCH = cD / 32;
    for (int ch = 0; ch < NCH; ch++) {
        if (ch + 1 < NCH) { load_stage(ch + 1, (ch + 1) & 1); CP_WAIT(1); }
        else              { CP_WAIT(0); }
        __syncthreads();
        const uint32_t s0 = sb + (ch & 1) * STAGE_B;

        #pragma unroll
        for (int ks = 0; ks < 2; ks++) {
            const int acol = ks * 16 + ((lane >> 4) << 3);
            const int bcol = ks * 16 + (((lane >> 3) & 1) << 3);
            const int brow0 = wn * 32 + (lane & 7) + ((lane >> 4) << 3);

            // B-hi fragments
            uint32_t bh[4][2];
            #pragma unroll
            for (int np = 0; np < 2; np++) {
                const uint32_t boff = (uint32_t)((brow0 + np * 16) * ROWB + bcol * 2);
                uint32_t r0, r1, r2, r3;
                ldsm4(r0, r1, r2, r3, s0 + 2 * TILE_B + boff);
                bh[2 * np][0] = r0;     bh[2 * np][1] = r1;
                bh[2 * np + 1][0] = r2; bh[2 * np + 1][1] = r3;
            }
            // A-hi fragments
            uint32_t af[4][4];
            #pragma unroll
            for (int mi = 0; mi < 4; mi++) {
                const int row = wm * 64 + mi * 16 + (lane & 15);
                ldsm4(af[mi][0], af[mi][1], af[mi][2], af[mi][3],
                      s0 + (uint32_t)(row * ROWB + acol * 2));
            }
            #pragma unroll
            for (int mi = 0; mi < 4; mi++)
                #pragma unroll
                for (int ni = 0; ni < 4; ni++)
                    mma_f16(acc[mi][ni], af[mi][0], af[mi][1],
                            af[mi][2], af[mi][3], bh[ni][0], bh[ni][1]);

            if (!two_term) {
                uint32_t bl[4][2];
                #pragma unroll
                for (int np = 0; np < 2; np++) {
                    const uint32_t boff = (uint32_t)((brow0 + np * 16) * ROWB + bcol * 2);
                    uint32_t r0, r1, r2, r3;
                    ldsm4(r0, r1, r2, r3, s0 + 3 * TILE_B + boff);
                    bl[2 * np][0] = r0;     bl[2 * np][1] = r1;
                    bl[2 * np + 1][0] = r2; bl[2 * np + 1][1] = r3;
                }
                #pragma unroll
                for (int mi = 0; mi < 4; mi++)
                    #pragma unroll
                    for (int ni = 0; ni < 4; ni++)
                        mma_f16(acc[mi][ni], af[mi][0], af[mi][1],
                                af[mi][2], af[mi][3], bl[ni][0], bl[ni][1]);
            }

            // A-lo overwrites the same registers; multiply with B-hi
            #pragma unroll
            for (int mi = 0; mi < 4; mi++) {
                const int row = wm * 64 + mi * 16 + (lane & 15);
                ldsm4(af[mi][0], af[mi][1], af[mi][2], af[mi][3],
                      s0 + TILE_B + (uint32_t)(row * ROWB + acol * 2));
            }
            #pragma unroll
            for (int mi = 0; mi < 4; mi++)
                #pragma unroll
                for (int ni = 0; ni < 4; ni++)
                    mma_f16(acc[mi][ni], af[mi][0], af[mi][1],
                            af[mi][2], af[mi][3], bh[ni][0], bh[ni][1]);
        }
        __syncthreads();
    }

    #pragma unroll
    for (int mi = 0; mi < 4; mi++) {
        #pragma unroll
        for (int h = 0; h < 2; h++) {
            const int row = m0 + wm * 64 + mi * 16 + h * 8 + (lane >> 2);
            #pragma unroll
            for (int ni = 0; ni < 4; ni++) {
                const int col = n0 + wn * 32 + ni * 8 + (lane & 3) * 2;
                const float2 bb = *reinterpret_cast<const float2*>(bias + col);
                const float v0 = (acc[mi][ni][h * 2 + 0] + bb.x) * scale;
                const float v1 = (acc[mi][ni][h * 2 + 1] + bb.y) * scale;
                if (F16OUT) {
                    const size_t o = (size_t)z * XSZ + (size_t)row * 1024 + col;
                    *reinterpret_cast<uint32_t*>(oh + o) = packh2(v0, v1);
                } else {
                    *reinterpret_cast<float2*>(oF + (size_t)row * 1024 + col) =
                        make_float2(v0, v1);
                }
            }
        }
    }
}

// ---------------------------------------------------------------------------
// fp16 flash attention v5 (pure-hi Q path):
//   S = Qh*Kh (1-term);  P = ex2.f16x2(S - m);  O += Ph*Vh
//   row sums via ones-MMA; 4-stage cp.async K/V pipeline.
// ---------------------------------------------------------------------------
constexpr int ROW2 = 144;
constexpr int R_KH = 0;
constexpr int R_VH = 64 * ROW2;
constexpr int STG2 = 2 * 64 * ROW2;          // 18432 per stage
constexpr int ATTN_SMEM = 4 * STG2;          // 73728

__global__ __launch_bounds__(256, 2) void attn_mma(
    const f16* __restrict__ qh, const f16* __restrict__ kh,
    const f16* __restrict__ vh, f16* __restrict__ oh, f16* __restrict__ ol)
{
    __shared__ __align__(16) unsigned char smb[ATTN_SMEM];
    const uint32_t sb = smem_u32(smb);
    const int tid = threadIdx.x;
    const int wid = tid >> 5;
    const int lane = tid & 31;
    const int t0 = blockIdx.x * 128;
    const int hh = blockIdx.y;
    const int bi = blockIdx.z;

    // ---- Q-hi staged transiently in the stage area, then to registers
    #pragma unroll
    for (int it = 0; it < 4; it++) {
        const int i = tid + it * 256;
        const int r = i >> 3, c = i & 7;
        const size_t g = ((size_t)(bi * cT + t0 + r) * cH + hh) * cDK + c * 8;
        *reinterpret_cast<uint4*>(smb + r * ROW2 + c * 16) =
            *reinterpret_cast<const uint4*>(qh + g);
    }
    __syncthreads();

    uint32_t qfh[4][4];
    #pragma unroll
    for (int kb = 0; kb < 4; kb++) {
        const int row = wid * 16 + (lane & 15);
        const int col = kb * 16 + ((lane >> 4) << 3);
        ldsm4(qfh[kb][0], qfh[kb][1], qfh[kb][2], qfh[kb][3],
              sb + (uint32_t)(row * ROW2 + col * 2));
    }
    __syncthreads();   // stage area free for K/V

    const int lr = tid >> 3, lc8 = (tid & 7);
    auto load_kv = [&](int s0, int stage) {
        const uint32_t st = sb + stage * STG2;
        #pragma unroll
        for (int it = 0; it < 2; it++) {
            const int r = lr + it * 32;
            const uint32_t so = (uint32_t)(r * ROW2 + lc8 * 16);
            const size_t g = ((size_t)(bi * cS + s0 + r) * cH + hh) * cDK + lc8 * 8;
            cp16(st + R_KH + so, kh + g);
            cp16(st + R_VH + so, vh + g);
        }
        CP_COMMIT();
    };

    float oacc[8][4] = {};
    float mrow0 = -INFINITY, mrow1 = -INFINITY;
    float lrow0 = 0.0f, lrow1 = 0.0f;

    const int quad = lane >> 3, id8 = lane & 7;
    constexpr uint32_t ONES2 = 0x3C003C00u;   // half2(1.0, 1.0)
    constexpr int NT = cS / 64;

    load_kv(0, 0);
    load_kv(64, 1);
    load_kv(128, 2);

    for (int ch = 0; ch < NT; ch++) {
        CP_WAIT(2);
        __syncthreads();
        const uint32_t st = sb + (ch & 3) * STG2;

        // ---- S = Qh*Kh (1-term)
        float sacc[8][4] = {};
        #pragma unroll
        for (int kb = 0; kb < 4; kb++) {
            #pragma unroll
            for (int np = 0; np < 4; np++) {
                const int nrow = np * 16 + (lane & 7) + ((lane >> 4) << 3);
                const int col = kb * 16 + (((lane >> 3) & 1) << 3);
                uint32_t h0, h1, h2, h3;
                ldsm4(h0, h1, h2, h3, st + (uint32_t)(R_KH + nrow * ROW2 + col * 2));
                mma_f16(sacc[2 * np], qfh[kb][0], qfh[kb][1], qfh[kb][2], qfh[kb][3], h0, h1);
                mma_f16(sacc[2 * np + 1], qfh[kb][0], qfh[kb][1], qfh[kb][2], qfh[kb][3], h2, h3);
            }
        }

        // prefetch tile ch+3 now so cp.async overlaps softmax + PV
        if (ch + 3 < NT) load_kv((ch + 3) * 64, (ch + 3) & 3);
        else             CP_COMMIT();

        // ---- max reduction (fp32)
        float mx0 = -INFINITY, mx1 = -INFINITY;
        #pragma unroll
        for (int n = 0; n < 8; n++) {
            mx0 = fmaxf(mx0, fmaxf(sacc[n][0], sacc[n][1]));
            mx1 = fmaxf(mx1, fmaxf(sacc[n][2], sacc[n][3]));
        }
        mx0 = fmaxf(mx0, __shfl_xor_sync(0xffffffffu, mx0, 1));
        mx0 = fmaxf(mx0, __shfl_xor_sync(0xffffffffu, mx0, 2));
        mx1 = fmaxf(mx1, __shfl_xor_sync(0xffffffffu, mx1, 1));
        mx1 = fmaxf(mx1, __shfl_xor_sync(0xffffffffu, mx1, 2));
        const float mn0 = fmaxf(mrow0, mx0);
        const float mn1 = fmaxf(mrow1, mx1);
        const float corr0 = ex2(mrow0 - mn0);
        const float corr1 = ex2(mrow1 - mn1);
        mrow0 = mn0;  mrow1 = mn1;

        // ---- P = ex2(S - m) in packed fp16; row sums via ones-MMA
        uint32_t pah[4][4];
        float sumacc[4] = {0.f, 0.f, 0.f, 0.f};
        #pragma unroll
        for (int kb = 0; kb < 4; kb++) {
            pah[kb][0] = ex2h2(packh2(sacc[2 * kb][0] - mn0, sacc[2 * kb][1] - mn0));
            pah[kb][1] = ex2h2(packh2(sacc[2 * kb][2] - mn1, sacc[2 * kb][3] - mn1));
            pah[kb][2] = ex2h2(packh2(sacc[2 * kb + 1][0] - mn0, sacc[2 * kb + 1][1] - mn0));
            pah[kb][3] = ex2h2(packh2(sacc[2 * kb + 1][2] - mn1, sacc[2 * kb + 1][3] - mn1));
            mma_f16(sumacc, pah[kb][0], pah[kb][1], pah[kb][2], pah[kb][3],
                    ONES2, ONES2);
        }
        lrow0 = lrow0 * corr0 + sumacc[0];
        lrow1 = lrow1 * corr1 + sumacc[2];

        #pragma unroll
        for (int n = 0; n < 8; n++) {
            oacc[n][0] *= corr0; oacc[n][1] *= corr0;
            oacc[n][2] *= corr1; oacc[n][3] *= corr1;
        }

        // ---- O += Ph*Vh (V natural, trans-ldsm B-fragments)
        #pragma unroll
        for (int kb = 0; kb < 4; kb++) {
            #pragma unroll
            for (int np = 0; np < 4; np++) {
                const uint32_t av = (uint32_t)(
                    (kb * 16 + (quad & 1) * 8 + id8) * ROW2 +
                    (np * 16 + (quad >> 1) * 8) * 2);
                uint32_t h0, h1, h2, h3;
                ldsm4t(h0, h1, h2, h3, st + R_VH + av);
                mma_f16(oacc[2 * np], pah[kb][0], pah[kb][1], pah[kb][2], pah[kb][3], h0, h1);
                mma_f16(oacc[2 * np + 1], pah[kb][0], pah[kb][1], pah[kb][2], pah[kb][3], h2, h3);
            }
        }
    }

    // ---- Normalize + write O as fp16 hi/lo
    const float inv0 = 1.0f / lrow0;
    const float inv1 = 1.0f / lrow1;
    const int row0 = t0 + wid * 16 + (lane >> 2);
    #pragma unroll
    for (int n = 0; n < 8; n++) {
        const int dk = n * 8 + (lane & 3) * 2;
        const size_t g0 = ((size_t)(bi * cT + row0) * cH + hh) * cDK + dk;
        const size_t g1 = ((size_t)(bi * cT + row0 + 8) * cH + hh) * cDK + dk;
        uint32_t hp, lp;
        hilo2h(oacc[n][0] * inv0, oacc[n][1] * inv0, hp, lp);
        *reinterpret_cast<uint32_t*>(oh + g0) = hp;
        *reinterpret_cast<uint32_t*>(ol + g0) = lp;
        hilo2h(oacc[n][2] * inv1, oacc[n][3] * inv1, hp, lp);
        *reinterpret_cast<uint32_t*>(oh + g1) = hp;
        *reinterpret_cast<uint32_t*>(ol + g1) = lp;
    }
}

// ---------------------------------------------------------------------------
extern "C" void kernel_launch(void* const* d_in, const int* in_sizes, int n_in,
                              void* d_out, int out_size)
{
    const float* query = (const float*)d_in[0];
    const float* value = (const float*)d_in[1];
    const float* key   = (const float*)d_in[2];
    const float* Wq    = (const float*)d_in[3];
    const float* bq    = (const float*)d_in[4];
    const float* Wk    = (const float*)d_in[5];
    const float* bk    = (const float*)d_in[6];
    const float* Wv    = (const float*)d_in[7];
    const float* bv    = (const float*)d_in[8];
    const float* Wo    = (const float*)d_in[9];
    const float* bo    = (const float*)d_in[10];
    float* out = (float*)d_out;

    f16 *xh, *xl, *yh, *wh, *wl;
    cudaGetSymbolAddress((void**)&xh, g_xh);
    cudaGetSymbolAddress((void**)&xl, g_xl);
    cudaGetSymbolAddress((void**)&yh, g_yh);
    cudaGetSymbolAddress((void**)&wh, g_wth);
    cudaGetSymbolAddress((void**)&wl, g_wtl);

    cudaFuncSetAttribute(gemm_mma<true>,
                         cudaFuncAttributeMaxDynamicSharedMemorySize, GEMM_SMEM);
    cudaFuncSetAttribute(gemm_mma<false>,
                         cudaFuncAttributeMaxDynamicSharedMemorySize, GEMM_SMEM);

    const int XB = (int)(XSZ / 4 / 256);

    xconv3<<<dim3(XB, 1, 3), 256>>>(query, key, value, xh, xl);
    wconv<<<dim3(32, 32, 4), dim3(32, 8)>>>(Wq, Wk, Wv, Wo, wh, wl);

    // Q/K/V projections, all 2-term (Xh*Wh + Xl*Wh), fp16-hi outputs only;
    // Q scaled by 1/sqrt(DK)*log2(e)
    const float qscale = 0.125f * 1.44269504088896340736f;
    gemm_mma<true><<<dim3(cHD / 128, cMT / 128, 3), 256, GEMM_SMEM>>>(
        xh, xl, wh, wl, bq, bk, bv, nullptr, yh, qscale, 0b111);

    // 1-term fp16 attention; out -> x slot 0 hi/lo
    attn_mma<<<dim3(cT / 128, cH, cB), 256>>>(
        yh, yh + XSZ, yh + 2 * XSZ, xh, xl);

    // O projection (fp32 out, 3-term)
    gemm_mma<false><<<dim3(cD / 128, cMT / 128, 1), 256, GEMM_SMEM>>>(
        xh, xl, wh + 3 * WSZ, wl + 3 * WSZ, bo, bo, bo, out, nullptr,
        1.0f, 0);
}